// round 1
// baseline (speedup 1.0000x reference)
#include <cuda_runtime.h>

#define Bsz 32
#define Ssz 2048
#define Dsz 256
#define BS (Bsz*Ssz)   // 65536 rows
#define WIN 44         // attention smem window rows (32 + 2*6 halo)

// ---------------- scratch (device globals; no allocation) ----------------
__device__ float g_qk[(size_t)BS*Dsz];
__device__ float g_v [(size_t)BS*Dsz];
__device__ float g_at[(size_t)BS*Dsz];
__device__ float g_hq[(size_t)BS*Dsz];
__device__ float g_hs[(size_t)BS*Dsz];

// ---------------- packed fp32x2 FMA helpers ----------------
__device__ __forceinline__ unsigned long long dup_f32(float a) {
    unsigned long long r; unsigned ai = __float_as_uint(a);
    asm("mov.b64 %0, {%1, %2};" : "=l"(r) : "r"(ai), "r"(ai));
    return r;
}
__device__ __forceinline__ void ffma2(unsigned long long &d,
                                      unsigned long long a,
                                      unsigned long long b) {
    asm("fma.rn.f32x2 %0, %1, %2, %0;" : "+l"(d) : "l"(a), "l"(b));
}
__device__ __forceinline__ float2 unpack2(unsigned long long u) {
    float2 f;
    f.x = __uint_as_float((unsigned)u);
    f.y = __uint_as_float((unsigned)(u >> 32));
    return f;
}

// ---------------- projection GEMM: y = x_slice @ W^T + b, channel-permuted ----------------
// tile 128 rows x 128 cols, 256 threads, 8x8 micro-tile (as 8x4 f32x2 pairs).
// Output column j of the math GEMM is stored at permuted channel m=(j&31)*4+(j>>5),
// so attention reads each effective head's 32 dims contiguously.
__global__ __launch_bounds__(256) void proj_kernel(
    const float* __restrict__ x,     // (BS,256)
    const float* __restrict__ W,     // (2,128,128) row-major (j,c)
    const float* __restrict__ bias,  // (2,128)
    float* __restrict__ out)         // (BS,256), permuted within each 128-split
{
    const int branch = blockIdx.y;
    const int r0 = blockIdx.x * 128;
    const int tid = threadIdx.x;
    const int ty = tid >> 4;   // 16 row groups x 8 rows
    const int tx = tid & 15;   // 16 col groups x 8 cols

    __shared__ float Wt[32][132];  // [c][permuted j]
    __shared__ float Xt[32][132];  // [c][row]
    __shared__ float sb[128];

    const float* Wb = W + (size_t)branch * (128*128);
    if (tid < 128) {
        int j = tid;
        sb[(j & 31) * 4 + (j >> 5)] = bias[branch*128 + j];
    }

    unsigned long long acc[8][4];
    #pragma unroll
    for (int i = 0; i < 8; i++)
        #pragma unroll
        for (int j = 0; j < 4; j++) acc[i][j] = 0ull;

    for (int kc = 0; kc < 128; kc += 32) {
        #pragma unroll
        for (int it = 0; it < 16; it++) {
            int idx = tid + it*256;
            int c = idx & 31, j = idx >> 5;
            Wt[c][(j & 31)*4 + (j >> 5)] = Wb[j*128 + kc + c];
        }
        #pragma unroll
        for (int it = 0; it < 16; it++) {
            int idx = tid + it*256;
            int c = idx & 31, r = idx >> 5;
            Xt[c][r] = x[(size_t)(r0 + r)*256 + branch*128 + kc + c];
        }
        __syncthreads();
        #pragma unroll
        for (int c = 0; c < 32; c++) {
            const float* xr = &Xt[c][ty*8];
            const unsigned long long* wr = (const unsigned long long*)&Wt[c][tx*8];
            unsigned long long w0 = wr[0], w1 = wr[1], w2 = wr[2], w3 = wr[3];
            #pragma unroll
            for (int i = 0; i < 8; i++) {
                unsigned long long ad = dup_f32(xr[i]);
                ffma2(acc[i][0], ad, w0);
                ffma2(acc[i][1], ad, w1);
                ffma2(acc[i][2], ad, w2);
                ffma2(acc[i][3], ad, w3);
            }
        }
        __syncthreads();
    }

    #pragma unroll
    for (int i = 0; i < 8; i++) {
        size_t row = (size_t)r0 + ty*8 + i;
        float* o = out + row*256 + branch*128 + tx*8;
        #pragma unroll
        for (int j2 = 0; j2 < 4; j2++) {
            float2 v = unpack2(acc[i][j2]);
            o[j2*2+0] = v.x + sb[tx*8 + j2*2 + 0];
            o[j2*2+1] = v.y + sb[tx*8 + j2*2 + 1];
        }
    }
}

// ---------------- dilated local attention ----------------
// One CTA = (b, 32 s-positions). smem window of 44 rows x 256 ch for QK and V.
// Warp handles one (s_local, effective-head) task; lane = d' (contiguous channel).
__global__ __launch_bounds__(256) void attn_kernel(
    const float* __restrict__ QK,   // projected q(=k), permuted channels
    const float* __restrict__ V,    // projected v, permuted channels
    float* __restrict__ aout,       // (BS,256) natural concat order
    float* __restrict__ scores)     // (B,8,S,5) or nullptr
{
    extern __shared__ float sm[];
    float* sQK = sm;
    float* sV  = sm + WIN*256;
    const int b  = blockIdx.y;
    const int s0 = blockIdx.x * 32;
    const int tid = threadIdx.x;

    for (int idx = tid; idx < WIN*64; idx += 256) {   // float4 granularity
        int w = idx >> 6, c4 = idx & 63;
        int s = s0 + w - 6;
        float4 vq = make_float4(0.f,0.f,0.f,0.f);
        float4 vv = vq;
        if (s >= 0 && s < Ssz) {
            size_t off = ((size_t)b*Ssz + s)*64 + c4;
            vq = ((const float4*)QK)[off];
            vv = ((const float4*)V)[off];
        }
        ((float4*)sQK)[idx] = vq;
        ((float4*)sV)[idx]  = vv;
    }
    __syncthreads();

    const int warp = tid >> 5, lane = tid & 31;
    const float scale = 0.1767766952966369f;  // 32^-0.5

    for (int t = warp; t < 256; t += 8) {
        int sl = t >> 3, e = t & 7;
        int i  = e >> 2, hp = e & 3;
        int dil = i ? 1 : 3;
        int ch = i*128 + hp*32 + lane;

        float q = sQK[(sl+6)*256 + ch];
        float sc[5];
        #pragma unroll
        for (int k = 0; k < 5; k++) {
            int wk = sl + 6 + (k-2)*dil;
            float p = q * sQK[wk*256 + ch];
            #pragma unroll
            for (int m = 16; m; m >>= 1) p += __shfl_xor_sync(0xffffffffu, p, m);
            sc[k] = p * scale;
        }
        float mx = sc[0];
        #pragma unroll
        for (int k = 1; k < 5; k++) mx = fmaxf(mx, sc[k]);
        float ex[5], sum = 0.f;
        #pragma unroll
        for (int k = 0; k < 5; k++) { ex[k] = __expf(sc[k] - mx); sum += ex[k]; }
        float inv = 1.f / sum;
        float o = 0.f;
        #pragma unroll
        for (int k = 0; k < 5; k++) {
            int wk = sl + 6 + (k-2)*dil;
            o += ex[k] * sV[wk*256 + ch];
        }
        aout[((size_t)b*Ssz + s0 + sl)*256 + ch] = o * inv;

        if (scores != nullptr && lane < 5) {
            float pv = (lane==0?ex[0]:lane==1?ex[1]:lane==2?ex[2]:lane==3?ex[3]:ex[4]) * inv;
            scores[(((size_t)b*8 + i*4 + hp)*Ssz + s0 + sl)*5 + lane] = pv;
        }
    }
}

// ---------------- out-proj + bias + residual + LayerNorm, fused ----------------
// tile 64 rows x 256 cols (full N), 256 threads; warp = 8 rows x full 256 cols
// so LayerNorm is a pure warp-shuffle reduction.
__global__ __launch_bounds__(256) void outln_kernel(
    const float* __restrict__ A,    // attn (BS,256)
    const float* __restrict__ W,    // (256,256) row-major (j,c)
    const float* __restrict__ bo,   // (256)
    const float* __restrict__ xres, // (BS,256)
    const float* __restrict__ g,
    const float* __restrict__ bb,
    float* __restrict__ out)
{
    const int r0 = blockIdx.x * 64;
    const int tid = threadIdx.x;
    const int ty = tid >> 5;    // 8 row groups x 8 rows
    const int lane = tid & 31;  // 32 col groups x 8 cols

    __shared__ float Wt[32][260];
    __shared__ float At[32][68];
    __shared__ float sBo[256], sG[256], sB[256];

    sBo[tid] = bo[tid]; sG[tid] = g[tid]; sB[tid] = bb[tid];

    unsigned long long acc[8][4];
    #pragma unroll
    for (int i = 0; i < 8; i++)
        #pragma unroll
        for (int j = 0; j < 4; j++) acc[i][j] = 0ull;

    for (int kc = 0; kc < 256; kc += 32) {
        #pragma unroll
        for (int it = 0; it < 32; it++) {
            int idx = tid + it*256;
            int c = idx & 31, j = idx >> 5;
            Wt[c][j] = W[j*256 + kc + c];
        }
        #pragma unroll
        for (int it = 0; it < 8; it++) {
            int idx = tid + it*256;
            int c = idx & 31, r = idx >> 5;
            At[c][r] = A[(size_t)(r0 + r)*256 + kc + c];
        }
        __syncthreads();
        #pragma unroll
        for (int c = 0; c < 32; c++) {
            const float* ar = &At[c][ty*8];
            const unsigned long long* wr = (const unsigned long long*)&Wt[c][lane*8];
            unsigned long long w0 = wr[0], w1 = wr[1], w2 = wr[2], w3 = wr[3];
            #pragma unroll
            for (int i = 0; i < 8; i++) {
                unsigned long long ad = dup_f32(ar[i]);
                ffma2(acc[i][0], ad, w0);
                ffma2(acc[i][1], ad, w1);
                ffma2(acc[i][2], ad, w2);
                ffma2(acc[i][3], ad, w3);
            }
        }
        __syncthreads();
    }

    float bov[8], gv[8], bbv[8];
    #pragma unroll
    for (int j = 0; j < 8; j++) {
        bov[j] = sBo[lane*8+j]; gv[j] = sG[lane*8+j]; bbv[j] = sB[lane*8+j];
    }

    #pragma unroll
    for (int r = 0; r < 8; r++) {
        size_t row = (size_t)r0 + ty*8 + r;
        const float* xr = xres + row*256 + lane*8;
        float v[8];
        #pragma unroll
        for (int j2 = 0; j2 < 4; j2++) {
            float2 p = unpack2(acc[r][j2]);
            v[j2*2+0] = p.x + bov[j2*2+0] + xr[j2*2+0];
            v[j2*2+1] = p.y + bov[j2*2+1] + xr[j2*2+1];
        }
        float s = 0.f;
        #pragma unroll
        for (int j = 0; j < 8; j++) s += v[j];
        #pragma unroll
        for (int m = 16; m; m >>= 1) s += __shfl_xor_sync(0xffffffffu, s, m);
        float mu = s * (1.f/256.f);
        float qv = 0.f;
        #pragma unroll
        for (int j = 0; j < 8; j++) { float d = v[j] - mu; qv += d*d; }
        #pragma unroll
        for (int m = 16; m; m >>= 1) qv += __shfl_xor_sync(0xffffffffu, qv, m);
        float rstd = rsqrtf(qv * (1.f/256.f) + 1e-5f);
        float* o = out + row*256 + lane*8;
        #pragma unroll
        for (int j = 0; j < 8; j++) o[j] = (v[j] - mu)*rstd*gv[j] + bbv[j];
    }
}

// ---------------- launch ----------------
extern "C" void kernel_launch(void* const* d_in, const int* in_sizes, int n_in,
                              void* d_out, int out_size)
{
    (void)in_sizes; (void)n_in; (void)out_size;
    const float* q_emb = (const float*)d_in[0];
    const float* s_emb = (const float*)d_in[1];
    // d_in[2] = lens (unused in eval path)
    const float* W_lin = (const float*)d_in[3];  // (3,2,128,128)
    const float* b_lin = (const float*)d_in[4];  // (3,2,128)
    const float* W_out = (const float*)d_in[5];  // (3,256,256)
    const float* b_out = (const float*)d_in[6];  // (3,256)
    const float* ln_g  = (const float*)d_in[7];  // (3,256)
    const float* ln_b  = (const float*)d_in[8];  // (3,256)

    float* outp = (float*)d_out;
    float* z  = outp;                           // (32,2048,256)
    float* qs = outp + (size_t)BS*Dsz;          // (32,8,2048,5)

    float *p_qk, *p_v, *p_at, *p_hq, *p_hs;
    cudaGetSymbolAddress((void**)&p_qk, g_qk);
    cudaGetSymbolAddress((void**)&p_v,  g_v);
    cudaGetSymbolAddress((void**)&p_at, g_at);
    cudaGetSymbolAddress((void**)&p_hq, g_hq);
    cudaGetSymbolAddress((void**)&p_hs, g_hs);

    const int smemA = WIN*256*4*2;  // 90112 B
    cudaFuncSetAttribute(attn_kernel, cudaFuncAttributeMaxDynamicSharedMemorySize, smemA);

    dim3 pg(BS/128, 2);
    dim3 ag(Ssz/32, Bsz);
    const int og = BS/64;

    // ---- block 1: a1 = MHA(q_emb,q_emb,q_emb); hq = LN(q_emb + a1) ----
    proj_kernel<<<pg, 256>>>(q_emb, W_lin, b_lin, p_qk);
    attn_kernel<<<ag, 256, smemA>>>(p_qk, p_qk, p_at, nullptr);
    outln_kernel<<<og, 256>>>(p_at, W_out, b_out, q_emb, ln_g, ln_b, p_hq);

    // ---- block 2: a2,q_scores = MHA(s_emb,...); hs = LN(s_emb + a2) ----
    proj_kernel<<<pg, 256>>>(s_emb, W_lin + 2*128*128, b_lin + 2*128, p_qk);
    attn_kernel<<<ag, 256, smemA>>>(p_qk, p_qk, p_at, qs);
    outln_kernel<<<og, 256>>>(p_at, W_out + 256*256, b_out + 256,
                              s_emb, ln_g + 256, ln_b + 256, p_hs);

    // ---- block 3: a3 = MHA(hq, hq, hs); z = LN(hq + a3) ----
    proj_kernel<<<pg, 256>>>(p_hq, W_lin + 4*128*128, b_lin + 4*128, p_qk);
    proj_kernel<<<pg, 256>>>(p_hs, W_lin + 4*128*128, b_lin + 4*128, p_v);
    attn_kernel<<<ag, 256, smemA>>>(p_qk, p_v, p_at, nullptr);
    outln_kernel<<<og, 256>>>(p_at, W_out + 2*256*256, b_out + 2*256,
                              p_hq, ln_g + 2*256, ln_b + 2*256, z);
}

// round 3
// speedup vs baseline: 1.5297x; 1.5297x over previous
#include <cuda_runtime.h>
#include <cuda_bf16.h>
#include <cstdint>

#define Bsz 32
#define Ssz 2048
#define BS (Bsz*Ssz)   // 65536 rows
#define WIN 44         // attention smem window rows (32 + 2*6 halo)

// ---------------- scratch (device globals; no allocation) ----------------
__device__ float g_qk[(size_t)BS*256];
__device__ float g_v [(size_t)BS*256];
__device__ float g_at[(size_t)BS*256];
__device__ float g_hq[(size_t)BS*256];
__device__ float g_hs[(size_t)BS*256];

// ================= helpers =================
__device__ __forceinline__ uint32_t smem_u32(const void* p) {
    uint32_t a;
    asm("{ .reg .u64 t; cvta.to.shared.u64 t, %1; cvt.u32.u64 %0, t; }"
        : "=r"(a) : "l"(p));
    return a;
}
__device__ __forceinline__ void ldsm4(uint32_t r[4], uint32_t addr) {
    asm volatile("ldmatrix.sync.aligned.m8n8.x4.shared.b16 {%0,%1,%2,%3}, [%4];"
                 : "=r"(r[0]), "=r"(r[1]), "=r"(r[2]), "=r"(r[3]) : "r"(addr));
}
__device__ __forceinline__ void mma_bf16(float4& c, const uint32_t a[4],
                                         uint32_t b0, uint32_t b1) {
    asm volatile(
        "mma.sync.aligned.m16n8k16.row.col.f32.bf16.bf16.f32 "
        "{%0,%1,%2,%3}, {%4,%5,%6,%7}, {%8,%9}, {%0,%1,%2,%3};"
        : "+f"(c.x), "+f"(c.y), "+f"(c.z), "+f"(c.w)
        : "r"(a[0]), "r"(a[1]), "r"(a[2]), "r"(a[3]), "r"(b0), "r"(b1));
}
// fp32 pair -> bf16x2 hi + bf16x2 lo (3-term split source)
__device__ __forceinline__ void split2(float x0, float x1, uint32_t& hi, uint32_t& lo) {
    __nv_bfloat162 h = __floats2bfloat162_rn(x0, x1);
    hi = *reinterpret_cast<uint32_t*>(&h);
    __nv_bfloat162 l = __floats2bfloat162_rn(x0 - __bfloat162float(h.x),
                                             x1 - __bfloat162float(h.y));
    lo = *reinterpret_cast<uint32_t*>(&l);
}

// Fill a 128-row x 64-col chunk (fp32 src) into hi/lo bf16 smem, row stride 72 halves.
__device__ __forceinline__ void fill128(const float* __restrict__ src, int stride,
                                        uint32_t* __restrict__ hi,
                                        uint32_t* __restrict__ lo, int tid) {
    #pragma unroll
    for (int it = 0; it < 8; it++) {
        int idx = tid + it * 512;
        int row = idx >> 5, c2 = idx & 31;
        float2 v = *(const float2*)(src + (size_t)row * stride + c2 * 2);
        uint32_t h, l;
        split2(v.x, v.y, h, l);
        hi[row * 36 + c2] = h;
        lo[row * 36 + c2] = l;
    }
}

// ================= projection GEMM (mma.sync bf16 3-term) =================
// out[row, branch*128 + perm(j)] = sum_c x[row, branch*128+c]*W[j,c] + bias[j]
// perm(j) = (j&31)*4 + (j>>5). tile 128x128, 512 threads, warp tile 32x32.
#define PR_BIAS 73728u
#define PR_SMEM 74240u

__global__ __launch_bounds__(512) void proj_mma(
    const float* __restrict__ x, const float* __restrict__ W,
    const float* __restrict__ bias, float* __restrict__ out)
{
    extern __shared__ __align__(16) char sm[];
    uint32_t* Ahi = (uint32_t*)(sm);
    uint32_t* Alo = (uint32_t*)(sm + 18432);
    uint32_t* Bhi = (uint32_t*)(sm + 36864);
    uint32_t* Blo = (uint32_t*)(sm + 55296);
    float* sbias  = (float*)(sm + PR_BIAS);
    float* stg    = (float*)sm;            // 128x132 fp32, overlaps operands post-GEMM

    const int branch = blockIdx.y;
    const int r0 = blockIdx.x * 128;
    const int tid = threadIdx.x, lane = tid & 31, wid = tid >> 5;
    const int m0 = (wid >> 2) * 32, n0 = (wid & 3) * 32;

    if (tid < 128) sbias[tid] = bias[branch * 128 + tid];

    const uint32_t sA = smem_u32(Ahi), sB = smem_u32(Bhi);
    const int a_row = lane & 15, a_kh = (lane >> 4) << 3;
    const int b_n = (lane & 7) + ((lane >> 4) << 3);
    const int b_kh = ((lane >> 3) & 1) << 3;

    float4 acc[2][4];
    #pragma unroll
    for (int i = 0; i < 2; i++)
        #pragma unroll
        for (int j = 0; j < 4; j++) acc[i][j] = make_float4(0.f, 0.f, 0.f, 0.f);

    const float* xp = x + (size_t)r0 * 256 + branch * 128;
    const float* Wp = W + (size_t)branch * 128 * 128;

    uint32_t aAddr[2], bAddr[2];
    aAddr[0] = sA + ((m0 + a_row) * 72 + a_kh) * 2;
    aAddr[1] = sA + ((m0 + 16 + a_row) * 72 + a_kh) * 2;
    bAddr[0] = sB + ((n0 + b_n) * 72 + b_kh) * 2;
    bAddr[1] = sB + ((n0 + 16 + b_n) * 72 + b_kh) * 2;

    for (int kc = 0; kc < 128; kc += 64) {
        fill128(xp + kc, 256, Ahi, Alo, tid);
        fill128(Wp + kc, 128, Bhi, Blo, tid);
        __syncthreads();
        #pragma unroll
        for (int ks = 0; ks < 4; ks++) {
            uint32_t ah[2][4], al[2][4], bh[2][4], bl[2][4];
            #pragma unroll
            for (int mt = 0; mt < 2; mt++) {
                ldsm4(ah[mt], aAddr[mt] + ks * 32);
                ldsm4(al[mt], aAddr[mt] + 18432 + ks * 32);
            }
            #pragma unroll
            for (int bt = 0; bt < 2; bt++) {
                ldsm4(bh[bt], bAddr[bt] + ks * 32);
                ldsm4(bl[bt], bAddr[bt] + 18432 + ks * 32);
            }
            #pragma unroll
            for (int mt = 0; mt < 2; mt++)
                #pragma unroll
                for (int bt = 0; bt < 2; bt++)
                    #pragma unroll
                    for (int sub = 0; sub < 2; sub++) {
                        int nt = bt * 2 + sub;
                        mma_bf16(acc[mt][nt], ah[mt], bh[bt][sub*2], bh[bt][sub*2+1]);
                        mma_bf16(acc[mt][nt], al[mt], bh[bt][sub*2], bh[bt][sub*2+1]);
                        mma_bf16(acc[mt][nt], ah[mt], bl[bt][sub*2], bl[bt][sub*2+1]);
                    }
        }
        __syncthreads();
    }

    // epilogue: bias + permuted store to staging, then coalesced gmem write
    #pragma unroll
    for (int mt = 0; mt < 2; mt++) {
        int rb = m0 + mt * 16 + (lane >> 2);
        #pragma unroll
        for (int nt = 0; nt < 4; nt++) {
            int j = n0 + nt * 8 + (lane & 3) * 2;
            int p0 = ((j & 31) << 2) + (j >> 5);
            int p1 = (((j + 1) & 31) << 2) + ((j + 1) >> 5);
            float4 a = acc[mt][nt];
            stg[rb * 132 + p0]       = a.x + sbias[j];
            stg[rb * 132 + p1]       = a.y + sbias[j + 1];
            stg[(rb + 8) * 132 + p0] = a.z + sbias[j];
            stg[(rb + 8) * 132 + p1] = a.w + sbias[j + 1];
        }
    }
    __syncthreads();
    #pragma unroll
    for (int it = 0; it < 8; it++) {
        int idx = tid + it * 512;
        int row = idx >> 5, q = idx & 31;
        float4 v = *(const float4*)(stg + row * 132 + q * 4);
        *(float4*)(out + (size_t)(r0 + row) * 256 + branch * 128 + q * 4) = v;
    }
}

// ================= out-proj + bias + residual + LayerNorm (mma.sync) =================
// tile 128 rows x 256 cols (two 128-col halves), K=256 in 4 chunks of 64.
#define OL_STG  73728u
#define OL_BO   208896u
#define OL_G    209920u
#define OL_B    210944u
#define OL_MU   211968u
#define OL_RS   212480u
#define OL_SMEM 212992u

__global__ __launch_bounds__(512) void outln_mma(
    const float* __restrict__ A, const float* __restrict__ W,
    const float* __restrict__ bo, const float* __restrict__ xres,
    const float* __restrict__ g, const float* __restrict__ bb,
    float* __restrict__ out)
{
    extern __shared__ __align__(16) char sm[];
    uint32_t* Ahi = (uint32_t*)(sm);
    uint32_t* Alo = (uint32_t*)(sm + 18432);
    uint32_t* Bhi = (uint32_t*)(sm + 36864);
    uint32_t* Blo = (uint32_t*)(sm + 55296);
    float* stg = (float*)(sm + OL_STG);    // 128 x 264 fp32
    float* sbo = (float*)(sm + OL_BO);
    float* sg  = (float*)(sm + OL_G);
    float* sb2 = (float*)(sm + OL_B);
    float* smu = (float*)(sm + OL_MU);
    float* srs = (float*)(sm + OL_RS);

    const int r0 = blockIdx.x * 128;
    const int tid = threadIdx.x, lane = tid & 31, wid = tid >> 5;
    const int m0 = (wid >> 2) * 32, n0 = (wid & 3) * 32;

    if (tid < 256) { sbo[tid] = bo[tid]; sg[tid] = g[tid]; sb2[tid] = bb[tid]; }

    const uint32_t sA = smem_u32(Ahi), sB = smem_u32(Bhi);
    const int a_row = lane & 15, a_kh = (lane >> 4) << 3;
    const int b_n = (lane & 7) + ((lane >> 4) << 3);
    const int b_kh = ((lane >> 3) & 1) << 3;

    float4 acc[2][2][4];
    #pragma unroll
    for (int n = 0; n < 2; n++)
        #pragma unroll
        for (int i = 0; i < 2; i++)
            #pragma unroll
            for (int j = 0; j < 4; j++) acc[n][i][j] = make_float4(0.f, 0.f, 0.f, 0.f);

    uint32_t aAddr[2], bAddr[2];
    aAddr[0] = sA + ((m0 + a_row) * 72 + a_kh) * 2;
    aAddr[1] = sA + ((m0 + 16 + a_row) * 72 + a_kh) * 2;
    bAddr[0] = sB + ((n0 + b_n) * 72 + b_kh) * 2;
    bAddr[1] = sB + ((n0 + 16 + b_n) * 72 + b_kh) * 2;

    #pragma unroll 1
    for (int nh = 0; nh < 2; nh++) {
        #pragma unroll 1
        for (int kc = 0; kc < 4; kc++) {
            fill128(A + (size_t)r0 * 256 + kc * 64, 256, Ahi, Alo, tid);
            fill128(W + (size_t)nh * 128 * 256 + kc * 64, 256, Bhi, Blo, tid);
            __syncthreads();
            #pragma unroll
            for (int ks = 0; ks < 4; ks++) {
                uint32_t ah[2][4], al[2][4], bh[2][4], bl[2][4];
                #pragma unroll
                for (int mt = 0; mt < 2; mt++) {
                    ldsm4(ah[mt], aAddr[mt] + ks * 32);
                    ldsm4(al[mt], aAddr[mt] + 18432 + ks * 32);
                }
                #pragma unroll
                for (int bt = 0; bt < 2; bt++) {
                    ldsm4(bh[bt], bAddr[bt] + ks * 32);
                    ldsm4(bl[bt], bAddr[bt] + 18432 + ks * 32);
                }
                #pragma unroll
                for (int mt = 0; mt < 2; mt++)
                    #pragma unroll
                    for (int bt = 0; bt < 2; bt++)
                        #pragma unroll
                        for (int sub = 0; sub < 2; sub++) {
                            int nt = bt * 2 + sub;
                            mma_bf16(acc[nh][mt][nt], ah[mt], bh[bt][sub*2], bh[bt][sub*2+1]);
                            mma_bf16(acc[nh][mt][nt], al[mt], bh[bt][sub*2], bh[bt][sub*2+1]);
                            mma_bf16(acc[nh][mt][nt], ah[mt], bl[bt][sub*2], bl[bt][sub*2+1]);
                        }
            }
            __syncthreads();
        }
    }

    // stage acc + output-bias
    #pragma unroll
    for (int nh = 0; nh < 2; nh++)
        #pragma unroll
        for (int mt = 0; mt < 2; mt++) {
            int rb = m0 + mt * 16 + (lane >> 2);
            #pragma unroll
            for (int nt = 0; nt < 4; nt++) {
                int col = nh * 128 + n0 + nt * 8 + (lane & 3) * 2;
                float4 a = acc[nh][mt][nt];
                stg[rb * 264 + col]           = a.x + sbo[col];
                stg[rb * 264 + col + 1]       = a.y + sbo[col + 1];
                stg[(rb + 8) * 264 + col]     = a.z + sbo[col];
                stg[(rb + 8) * 264 + col + 1] = a.w + sbo[col + 1];
            }
        }
    __syncthreads();

    // residual add + LN stats (4 threads per row)
    {
        int row = tid >> 2, q = tid & 3;
        const float* xr = xres + (size_t)(r0 + row) * 256 + q * 64;
        float* sr = stg + row * 264 + q * 64;
        float sum = 0.f, sq = 0.f;
        #pragma unroll
        for (int i = 0; i < 16; i++) {
            float4 v = *(float4*)(sr + i * 4);
            float4 xv = *(const float4*)(xr + i * 4);
            v.x += xv.x; v.y += xv.y; v.z += xv.z; v.w += xv.w;
            sum += v.x + v.y + v.z + v.w;
            sq  += v.x*v.x + v.y*v.y + v.z*v.z + v.w*v.w;
            *(float4*)(sr + i * 4) = v;
        }
        sum += __shfl_xor_sync(0xffffffffu, sum, 1);
        sum += __shfl_xor_sync(0xffffffffu, sum, 2);
        sq  += __shfl_xor_sync(0xffffffffu, sq, 1);
        sq  += __shfl_xor_sync(0xffffffffu, sq, 2);
        if (q == 0) {
            float mu = sum * (1.f / 256.f);
            smu[row] = mu;
            srs[row] = rsqrtf(sq * (1.f / 256.f) - mu * mu + 1e-5f);
        }
    }
    __syncthreads();

    #pragma unroll
    for (int it = 0; it < 16; it++) {
        int idx = tid + it * 512;
        int row = idx >> 6, c4 = idx & 63, c = c4 * 4;
        float4 v = *(const float4*)(stg + row * 264 + c);
        float mu = smu[row], rs = srs[row];
        v.x = (v.x - mu) * rs * sg[c+0] + sb2[c+0];
        v.y = (v.y - mu) * rs * sg[c+1] + sb2[c+1];
        v.z = (v.z - mu) * rs * sg[c+2] + sb2[c+2];
        v.w = (v.w - mu) * rs * sg[c+3] + sb2[c+3];
        *(float4*)(out + (size_t)(r0 + row) * 256 + c) = v;
    }
}

// ================= dilated local attention (unchanged, passing) =================
__global__ __launch_bounds__(256) void attn_kernel(
    const float* __restrict__ QK, const float* __restrict__ V,
    float* __restrict__ aout, float* __restrict__ scores)
{
    extern __shared__ float smf[];
    float* sQK = smf;
    float* sV  = smf + WIN * 256;
    const int b  = blockIdx.y;
    const int s0 = blockIdx.x * 32;
    const int tid = threadIdx.x;

    for (int idx = tid; idx < WIN * 64; idx += 256) {
        int w = idx >> 6, c4 = idx & 63;
        int s = s0 + w - 6;
        float4 vq = make_float4(0.f, 0.f, 0.f, 0.f);
        float4 vv = vq;
        if (s >= 0 && s < Ssz) {
            size_t off = ((size_t)b * Ssz + s) * 64 + c4;
            vq = ((const float4*)QK)[off];
            vv = ((const float4*)V)[off];
        }
        ((float4*)sQK)[idx] = vq;
        ((float4*)sV)[idx]  = vv;
    }
    __syncthreads();

    const int warp = tid >> 5, lane = tid & 31;
    const float scale = 0.1767766952966369f;

    for (int t = warp; t < 256; t += 8) {
        int sl = t >> 3, e = t & 7;
        int i = e >> 2, hp = e & 3;
        int dil = i ? 1 : 3;
        int ch = i * 128 + hp * 32 + lane;

        float q = sQK[(sl + 6) * 256 + ch];
        float sc[5];
        #pragma unroll
        for (int k = 0; k < 5; k++) {
            int wk = sl + 6 + (k - 2) * dil;
            float p = q * sQK[wk * 256 + ch];
            #pragma unroll
            for (int m = 16; m; m >>= 1) p += __shfl_xor_sync(0xffffffffu, p, m);
            sc[k] = p * scale;
        }
        float mx = sc[0];
        #pragma unroll
        for (int k = 1; k < 5; k++) mx = fmaxf(mx, sc[k]);
        float ex[5], sum = 0.f;
        #pragma unroll
        for (int k = 0; k < 5; k++) { ex[k] = __expf(sc[k] - mx); sum += ex[k]; }
        float inv = 1.f / sum;
        float o = 0.f;
        #pragma unroll
        for (int k = 0; k < 5; k++) {
            int wk = sl + 6 + (k - 2) * dil;
            o += ex[k] * sV[wk * 256 + ch];
        }
        aout[((size_t)b * Ssz + s0 + sl) * 256 + ch] = o * inv;

        if (scores != nullptr && lane < 5) {
            float pv = (lane==0?ex[0]:lane==1?ex[1]:lane==2?ex[2]:lane==3?ex[3]:ex[4]) * inv;
            scores[(((size_t)b * 8 + i * 4 + hp) * Ssz + s0 + sl) * 5 + lane] = pv;
        }
    }
}

// ================= launch =================
extern "C" void kernel_launch(void* const* d_in, const int* in_sizes, int n_in,
                              void* d_out, int out_size)
{
    (void)in_sizes; (void)n_in; (void)out_size;
    const float* q_emb = (const float*)d_in[0];
    const float* s_emb = (const float*)d_in[1];
    const float* W_lin = (const float*)d_in[3];  // (3,2,128,128)
    const float* b_lin = (const float*)d_in[4];  // (3,2,128)
    const float* W_out = (const float*)d_in[5];  // (3,256,256)
    const float* b_out = (const float*)d_in[6];  // (3,256)
    const float* ln_g  = (const float*)d_in[7];  // (3,256)
    const float* ln_b  = (const float*)d_in[8];  // (3,256)

    float* outp = (float*)d_out;
    float* z  = outp;
    float* qs = outp + (size_t)BS * 256;

    float *p_qk, *p_v, *p_at, *p_hq, *p_hs;
    cudaGetSymbolAddress((void**)&p_qk, g_qk);
    cudaGetSymbolAddress((void**)&p_v,  g_v);
    cudaGetSymbolAddress((void**)&p_at, g_at);
    cudaGetSymbolAddress((void**)&p_hq, g_hq);
    cudaGetSymbolAddress((void**)&p_hs, g_hs);

    const int smemP = (int)PR_SMEM;    // 74240
    const int smemO = (int)OL_SMEM;    // 212992
    const int smemA = WIN * 256 * 4 * 2;
    cudaFuncSetAttribute(proj_mma,  cudaFuncAttributeMaxDynamicSharedMemorySize, smemP);
    cudaFuncSetAttribute(outln_mma, cudaFuncAttributeMaxDynamicSharedMemorySize, smemO);
    cudaFuncSetAttribute(attn_kernel, cudaFuncAttributeMaxDynamicSharedMemorySize, smemA);

    dim3 pg(BS / 128, 2);
    dim3 ag(Ssz / 32, Bsz);
    const int og = BS / 128;

    // block 1
    proj_mma<<<pg, 512, smemP>>>(q_emb, W_lin, b_lin, p_qk);
    attn_kernel<<<ag, 256, smemA>>>(p_qk, p_qk, p_at, nullptr);
    outln_mma<<<og, 512, smemO>>>(p_at, W_out, b_out, q_emb, ln_g, ln_b, p_hq);

    // block 2
    proj_mma<<<pg, 512, smemP>>>(s_emb, W_lin + 2*128*128, b_lin + 2*128, p_qk);
    attn_kernel<<<ag, 256, smemA>>>(p_qk, p_qk, p_at, qs);
    outln_mma<<<og, 512, smemO>>>(p_at, W_out + 256*256, b_out + 256,
                                  s_emb, ln_g + 256, ln_b + 256, p_hs);

    // block 3
    proj_mma<<<pg, 512, smemP>>>(p_hq, W_lin + 4*128*128, b_lin + 4*128, p_qk);
    proj_mma<<<pg, 512, smemP>>>(p_hs, W_lin + 4*128*128, b_lin + 4*128, p_v);
    attn_kernel<<<ag, 256, smemA>>>(p_qk, p_v, p_at, nullptr);
    outln_mma<<<og, 512, smemO>>>(p_at, W_out + 2*256*256, b_out + 2*256,
                                  p_hq, ln_g + 2*256, ln_b + 2*256, z);
}

// round 4
// speedup vs baseline: 1.7549x; 1.1473x over previous
#include <cuda_runtime.h>
#include <cuda_bf16.h>
#include <cstdint>

#define Bsz 32
#define Ssz 2048
#define BS (Bsz*Ssz)   // 65536 rows
#define WIN 44         // attention smem window rows (32 + 2*6 halo)

// ---------------- scratch (device globals; no allocation) ----------------
__device__ float g_qk[(size_t)BS*256];
__device__ float g_v [(size_t)BS*256];
__device__ float g_at[(size_t)BS*256];
__device__ float g_hq[(size_t)BS*256];
__device__ float g_hs[(size_t)BS*256];

// ================= helpers =================
__device__ __forceinline__ uint32_t smem_u32(const void* p) {
    uint32_t a;
    asm("{ .reg .u64 t; cvta.to.shared.u64 t, %1; cvt.u32.u64 %0, t; }"
        : "=r"(a) : "l"(p));
    return a;
}
__device__ __forceinline__ void ldsm4(uint32_t r[4], uint32_t addr) {
    asm volatile("ldmatrix.sync.aligned.m8n8.x4.shared.b16 {%0,%1,%2,%3}, [%4];"
                 : "=r"(r[0]), "=r"(r[1]), "=r"(r[2]), "=r"(r[3]) : "r"(addr));
}
__device__ __forceinline__ void mma_bf16(float4& c, const uint32_t a[4],
                                         uint32_t b0, uint32_t b1) {
    asm volatile(
        "mma.sync.aligned.m16n8k16.row.col.f32.bf16.bf16.f32 "
        "{%0,%1,%2,%3}, {%4,%5,%6,%7}, {%8,%9}, {%0,%1,%2,%3};"
        : "+f"(c.x), "+f"(c.y), "+f"(c.z), "+f"(c.w)
        : "r"(a[0]), "r"(a[1]), "r"(a[2]), "r"(a[3]), "r"(b0), "r"(b1));
}
// fp32 pair -> bf16x2 hi + bf16x2 lo (3-term split source)
__device__ __forceinline__ void split2(float x0, float x1, uint32_t& hi, uint32_t& lo) {
    __nv_bfloat162 h = __floats2bfloat162_rn(x0, x1);
    hi = *reinterpret_cast<uint32_t*>(&h);
    __nv_bfloat162 l = __floats2bfloat162_rn(x0 - __bfloat162float(h.x),
                                             x1 - __bfloat162float(h.y));
    lo = *reinterpret_cast<uint32_t*>(&l);
}

// Fill a 128-row x 64-col chunk (fp32 src) into hi/lo bf16 smem, row stride 72 halves.
__device__ __forceinline__ void fill128(const float* __restrict__ src, int stride,
                                        uint32_t* __restrict__ hi,
                                        uint32_t* __restrict__ lo, int tid) {
    #pragma unroll
    for (int it = 0; it < 8; it++) {
        int idx = tid + it * 512;
        int row = idx >> 5, c2 = idx & 31;
        float2 v = *(const float2*)(src + (size_t)row * stride + c2 * 2);
        uint32_t h, l;
        split2(v.x, v.y, h, l);
        hi[row * 36 + c2] = h;
        lo[row * 36 + c2] = l;
    }
}

// ================= projection GEMM (mma.sync bf16 3-term) =================
#define PR_BIAS 73728u
#define PR_SMEM 74240u

__global__ __launch_bounds__(512) void proj_mma(
    const float* __restrict__ x, const float* __restrict__ W,
    const float* __restrict__ bias, float* __restrict__ out)
{
    extern __shared__ __align__(16) char sm[];
    uint32_t* Ahi = (uint32_t*)(sm);
    uint32_t* Alo = (uint32_t*)(sm + 18432);
    uint32_t* Bhi = (uint32_t*)(sm + 36864);
    uint32_t* Blo = (uint32_t*)(sm + 55296);
    float* sbias  = (float*)(sm + PR_BIAS);
    float* stg    = (float*)sm;            // 128x132 fp32, overlaps operands post-GEMM

    const int branch = blockIdx.y;
    const int r0 = blockIdx.x * 128;
    const int tid = threadIdx.x, lane = tid & 31, wid = tid >> 5;
    const int m0 = (wid >> 2) * 32, n0 = (wid & 3) * 32;

    if (tid < 128) sbias[tid] = bias[branch * 128 + tid];

    const uint32_t sA = smem_u32(Ahi), sB = smem_u32(Bhi);
    const int a_row = lane & 15, a_kh = (lane >> 4) << 3;
    const int b_n = (lane & 7) + ((lane >> 4) << 3);
    const int b_kh = ((lane >> 3) & 1) << 3;

    float4 acc[2][4];
    #pragma unroll
    for (int i = 0; i < 2; i++)
        #pragma unroll
        for (int j = 0; j < 4; j++) acc[i][j] = make_float4(0.f, 0.f, 0.f, 0.f);

    const float* xp = x + (size_t)r0 * 256 + branch * 128;
    const float* Wp = W + (size_t)branch * 128 * 128;

    uint32_t aAddr[2], bAddr[2];
    aAddr[0] = sA + ((m0 + a_row) * 72 + a_kh) * 2;
    aAddr[1] = sA + ((m0 + 16 + a_row) * 72 + a_kh) * 2;
    bAddr[0] = sB + ((n0 + b_n) * 72 + b_kh) * 2;
    bAddr[1] = sB + ((n0 + 16 + b_n) * 72 + b_kh) * 2;

    for (int kc = 0; kc < 128; kc += 64) {
        fill128(xp + kc, 256, Ahi, Alo, tid);
        fill128(Wp + kc, 128, Bhi, Blo, tid);
        __syncthreads();
        #pragma unroll
        for (int ks = 0; ks < 4; ks++) {
            uint32_t ah[2][4], al[2][4], bh[2][4], bl[2][4];
            #pragma unroll
            for (int mt = 0; mt < 2; mt++) {
                ldsm4(ah[mt], aAddr[mt] + ks * 32);
                ldsm4(al[mt], aAddr[mt] + 18432 + ks * 32);
            }
            #pragma unroll
            for (int bt = 0; bt < 2; bt++) {
                ldsm4(bh[bt], bAddr[bt] + ks * 32);
                ldsm4(bl[bt], bAddr[bt] + 18432 + ks * 32);
            }
            #pragma unroll
            for (int mt = 0; mt < 2; mt++)
                #pragma unroll
                for (int bt = 0; bt < 2; bt++)
                    #pragma unroll
                    for (int sub = 0; sub < 2; sub++) {
                        int nt = bt * 2 + sub;
                        mma_bf16(acc[mt][nt], ah[mt], bh[bt][sub*2], bh[bt][sub*2+1]);
                        mma_bf16(acc[mt][nt], al[mt], bh[bt][sub*2], bh[bt][sub*2+1]);
                        mma_bf16(acc[mt][nt], ah[mt], bl[bt][sub*2], bl[bt][sub*2+1]);
                    }
        }
        __syncthreads();
    }

    // epilogue: bias + permuted store to staging, then coalesced gmem write
    #pragma unroll
    for (int mt = 0; mt < 2; mt++) {
        int rb = m0 + mt * 16 + (lane >> 2);
        #pragma unroll
        for (int nt = 0; nt < 4; nt++) {
            int j = n0 + nt * 8 + (lane & 3) * 2;
            int p0 = ((j & 31) << 2) + (j >> 5);
            int p1 = (((j + 1) & 31) << 2) + ((j + 1) >> 5);
            float4 a = acc[mt][nt];
            stg[rb * 132 + p0]       = a.x + sbias[j];
            stg[rb * 132 + p1]       = a.y + sbias[j + 1];
            stg[(rb + 8) * 132 + p0] = a.z + sbias[j];
            stg[(rb + 8) * 132 + p1] = a.w + sbias[j + 1];
        }
    }
    __syncthreads();
    #pragma unroll
    for (int it = 0; it < 8; it++) {
        int idx = tid + it * 512;
        int row = idx >> 5, q = idx & 31;
        float4 v = *(const float4*)(stg + row * 132 + q * 4);
        *(float4*)(out + (size_t)(r0 + row) * 256 + branch * 128 + q * 4) = v;
    }
}

// ================= out-proj + bias + residual + LayerNorm (mma.sync) =================
#define OL_STG  73728u
#define OL_BO   208896u
#define OL_G    209920u
#define OL_B    210944u
#define OL_MU   211968u
#define OL_RS   212480u
#define OL_SMEM 212992u

__global__ __launch_bounds__(512) void outln_mma(
    const float* __restrict__ A, const float* __restrict__ W,
    const float* __restrict__ bo, const float* __restrict__ xres,
    const float* __restrict__ g, const float* __restrict__ bb,
    float* __restrict__ out)
{
    extern __shared__ __align__(16) char sm[];
    uint32_t* Ahi = (uint32_t*)(sm);
    uint32_t* Alo = (uint32_t*)(sm + 18432);
    uint32_t* Bhi = (uint32_t*)(sm + 36864);
    uint32_t* Blo = (uint32_t*)(sm + 55296);
    float* stg = (float*)(sm + OL_STG);    // 128 x 264 fp32
    float* sbo = (float*)(sm + OL_BO);
    float* sg  = (float*)(sm + OL_G);
    float* sb2 = (float*)(sm + OL_B);
    float* smu = (float*)(sm + OL_MU);
    float* srs = (float*)(sm + OL_RS);

    const int r0 = blockIdx.x * 128;
    const int tid = threadIdx.x, lane = tid & 31, wid = tid >> 5;
    const int m0 = (wid >> 2) * 32, n0 = (wid & 3) * 32;

    if (tid < 256) { sbo[tid] = bo[tid]; sg[tid] = g[tid]; sb2[tid] = bb[tid]; }

    const uint32_t sA = smem_u32(Ahi), sB = smem_u32(Bhi);
    const int a_row = lane & 15, a_kh = (lane >> 4) << 3;
    const int b_n = (lane & 7) + ((lane >> 4) << 3);
    const int b_kh = ((lane >> 3) & 1) << 3;

    float4 acc[2][2][4];
    #pragma unroll
    for (int n = 0; n < 2; n++)
        #pragma unroll
        for (int i = 0; i < 2; i++)
            #pragma unroll
            for (int j = 0; j < 4; j++) acc[n][i][j] = make_float4(0.f, 0.f, 0.f, 0.f);

    uint32_t aAddr[2], bAddr[2];
    aAddr[0] = sA + ((m0 + a_row) * 72 + a_kh) * 2;
    aAddr[1] = sA + ((m0 + 16 + a_row) * 72 + a_kh) * 2;
    bAddr[0] = sB + ((n0 + b_n) * 72 + b_kh) * 2;
    bAddr[1] = sB + ((n0 + 16 + b_n) * 72 + b_kh) * 2;

    #pragma unroll 1
    for (int nh = 0; nh < 2; nh++) {
        #pragma unroll 1
        for (int kc = 0; kc < 4; kc++) {
            fill128(A + (size_t)r0 * 256 + kc * 64, 256, Ahi, Alo, tid);
            fill128(W + (size_t)nh * 128 * 256 + kc * 64, 256, Bhi, Blo, tid);
            __syncthreads();
            #pragma unroll
            for (int ks = 0; ks < 4; ks++) {
                uint32_t ah[2][4], al[2][4], bh[2][4], bl[2][4];
                #pragma unroll
                for (int mt = 0; mt < 2; mt++) {
                    ldsm4(ah[mt], aAddr[mt] + ks * 32);
                    ldsm4(al[mt], aAddr[mt] + 18432 + ks * 32);
                }
                #pragma unroll
                for (int bt = 0; bt < 2; bt++) {
                    ldsm4(bh[bt], bAddr[bt] + ks * 32);
                    ldsm4(bl[bt], bAddr[bt] + 18432 + ks * 32);
                }
                #pragma unroll
                for (int mt = 0; mt < 2; mt++)
                    #pragma unroll
                    for (int bt = 0; bt < 2; bt++)
                        #pragma unroll
                        for (int sub = 0; sub < 2; sub++) {
                            int nt = bt * 2 + sub;
                            mma_bf16(acc[nh][mt][nt], ah[mt], bh[bt][sub*2], bh[bt][sub*2+1]);
                            mma_bf16(acc[nh][mt][nt], al[mt], bh[bt][sub*2], bh[bt][sub*2+1]);
                            mma_bf16(acc[nh][mt][nt], ah[mt], bl[bt][sub*2], bl[bt][sub*2+1]);
                        }
            }
            __syncthreads();
        }
    }

    // stage acc + output-bias
    #pragma unroll
    for (int nh = 0; nh < 2; nh++)
        #pragma unroll
        for (int mt = 0; mt < 2; mt++) {
            int rb = m0 + mt * 16 + (lane >> 2);
            #pragma unroll
            for (int nt = 0; nt < 4; nt++) {
                int col = nh * 128 + n0 + nt * 8 + (lane & 3) * 2;
                float4 a = acc[nh][mt][nt];
                stg[rb * 264 + col]           = a.x + sbo[col];
                stg[rb * 264 + col + 1]       = a.y + sbo[col + 1];
                stg[(rb + 8) * 264 + col]     = a.z + sbo[col];
                stg[(rb + 8) * 264 + col + 1] = a.w + sbo[col + 1];
            }
        }
    __syncthreads();

    // residual add + LN stats (4 threads per row)
    {
        int row = tid >> 2, q = tid & 3;
        const float* xr = xres + (size_t)(r0 + row) * 256 + q * 64;
        float* sr = stg + row * 264 + q * 64;
        float sum = 0.f, sq = 0.f;
        #pragma unroll
        for (int i = 0; i < 16; i++) {
            float4 v = *(float4*)(sr + i * 4);
            float4 xv = *(const float4*)(xr + i * 4);
            v.x += xv.x; v.y += xv.y; v.z += xv.z; v.w += xv.w;
            sum += v.x + v.y + v.z + v.w;
            sq  += v.x*v.x + v.y*v.y + v.z*v.z + v.w*v.w;
            *(float4*)(sr + i * 4) = v;
        }
        sum += __shfl_xor_sync(0xffffffffu, sum, 1);
        sum += __shfl_xor_sync(0xffffffffu, sum, 2);
        sq  += __shfl_xor_sync(0xffffffffu, sq, 1);
        sq  += __shfl_xor_sync(0xffffffffu, sq, 2);
        if (q == 0) {
            float mu = sum * (1.f / 256.f);
            smu[row] = mu;
            srs[row] = rsqrtf(sq * (1.f / 256.f) - mu * mu + 1e-5f);
        }
    }
    __syncthreads();

    #pragma unroll
    for (int it = 0; it < 16; it++) {
        int idx = tid + it * 512;
        int row = idx >> 6, c4 = idx & 63, c = c4 * 4;
        float4 v = *(const float4*)(stg + row * 264 + c);
        float mu = smu[row], rs = srs[row];
        v.x = (v.x - mu) * rs * sg[c+0] + sb2[c+0];
        v.y = (v.y - mu) * rs * sg[c+1] + sb2[c+1];
        v.z = (v.z - mu) * rs * sg[c+2] + sb2[c+2];
        v.w = (v.w - mu) * rs * sg[c+3] + sb2[c+3];
        *(float4*)(out + (size_t)(r0 + row) * 256 + c) = v;
    }
}

// ================= dilated local attention (thread-per-task, no shuffles) =================
// 256 threads = 32 s-positions x 8 effective heads. Skewed smem layout:
// element (row, ch) at row*288 + (ch>>5)*36 + (ch&31)  -> conflict-free for
// both the tile fill and the per-head reads (banks 4*(h+k) mod 32).
#define ATT_STRIDE 288
#define ATT_SMEM (2 * WIN * ATT_STRIDE * 4)   // 101376 B

__global__ __launch_bounds__(256) void attn_kernel(
    const float* __restrict__ QK, const float* __restrict__ V,
    float* __restrict__ aout, float* __restrict__ scores)
{
    extern __shared__ float smf[];
    float* sQK = smf;
    float* sV  = smf + WIN * ATT_STRIDE;
    const int b  = blockIdx.y;
    const int s0 = blockIdx.x * 32;
    const int tid = threadIdx.x;

    // fill tile (zero halo outside sequence)
    for (int idx = tid; idx < WIN * 64; idx += 256) {
        int w = idx >> 6, c4 = idx & 63;
        int s = s0 + w - 6;
        float4 vq = make_float4(0.f, 0.f, 0.f, 0.f);
        float4 vv = vq;
        if (s >= 0 && s < Ssz) {
            size_t off = ((size_t)b * Ssz + s) * 64 + c4;
            vq = ((const float4*)QK)[off];
            vv = ((const float4*)V)[off];
        }
        int sc = w * ATT_STRIDE + (c4 >> 3) * 36 + (c4 & 7) * 4;
        *(float4*)(sQK + sc) = vq;
        *(float4*)(sV + sc)  = vv;
    }
    __syncthreads();

    const int sl = tid >> 3, h = tid & 7;
    const int dil = (h < 4) ? 3 : 1;
    const float scale = 0.1767766952966369f;  // 32^-0.5
    const int colb = h * 36;                  // skewed head base

    // q in registers (32 channels = 8 float4)
    float4 q[8];
    {
        const float* qr = sQK + (sl + 6) * ATT_STRIDE + colb;
        #pragma unroll
        for (int j = 0; j < 8; j++) q[j] = *(const float4*)(qr + j * 4);
    }

    // scores
    float sc[5];
    #pragma unroll
    for (int k = 0; k < 5; k++) {
        const float* kr = sQK + (sl + 6 + (k - 2) * dil) * ATT_STRIDE + colb;
        float d = 0.f;
        #pragma unroll
        for (int j = 0; j < 8; j++) {
            float4 kv = *(const float4*)(kr + j * 4);
            d += q[j].x * kv.x + q[j].y * kv.y + q[j].z * kv.z + q[j].w * kv.w;
        }
        sc[k] = d * scale;
    }
    float mx = sc[0];
    #pragma unroll
    for (int k = 1; k < 5; k++) mx = fmaxf(mx, sc[k]);
    float ex[5], sum = 0.f;
    #pragma unroll
    for (int k = 0; k < 5; k++) { ex[k] = __expf(sc[k] - mx); sum += ex[k]; }
    float inv = 1.f / sum;
    #pragma unroll
    for (int k = 0; k < 5; k++) ex[k] *= inv;

    // output: o[ch] = sum_k p[k] * v[k][ch]; contiguous 32-float span per thread
    float* op = aout + ((size_t)b * Ssz + s0 + sl) * 256 + h * 32;
    const float* v0 = sV + (sl + 6 - 2 * dil) * ATT_STRIDE + colb;
    const int vstep = dil * ATT_STRIDE;
    #pragma unroll
    for (int j = 0; j < 8; j++) {
        float4 o = make_float4(0.f, 0.f, 0.f, 0.f);
        #pragma unroll
        for (int k = 0; k < 5; k++) {
            float4 vv = *(const float4*)(v0 + k * vstep + j * 4);
            o.x += ex[k] * vv.x; o.y += ex[k] * vv.y;
            o.z += ex[k] * vv.z; o.w += ex[k] * vv.w;
        }
        *(float4*)(op + j * 4) = o;
    }

    if (scores != nullptr) {
        float* sp = scores + (((size_t)b * 8 + h) * Ssz + s0 + sl) * 5;
        #pragma unroll
        for (int k = 0; k < 5; k++) sp[k] = ex[k];
    }
}

// ================= launch =================
extern "C" void kernel_launch(void* const* d_in, const int* in_sizes, int n_in,
                              void* d_out, int out_size)
{
    (void)in_sizes; (void)n_in; (void)out_size;
    const float* q_emb = (const float*)d_in[0];
    const float* s_emb = (const float*)d_in[1];
    const float* W_lin = (const float*)d_in[3];  // (3,2,128,128)
    const float* b_lin = (const float*)d_in[4];  // (3,2,128)
    const float* W_out = (const float*)d_in[5];  // (3,256,256)
    const float* b_out = (const float*)d_in[6];  // (3,256)
    const float* ln_g  = (const float*)d_in[7];  // (3,256)
    const float* ln_b  = (const float*)d_in[8];  // (3,256)

    float* outp = (float*)d_out;
    float* z  = outp;
    float* qs = outp + (size_t)BS * 256;

    float *p_qk, *p_v, *p_at, *p_hq, *p_hs;
    cudaGetSymbolAddress((void**)&p_qk, g_qk);
    cudaGetSymbolAddress((void**)&p_v,  g_v);
    cudaGetSymbolAddress((void**)&p_at, g_at);
    cudaGetSymbolAddress((void**)&p_hq, g_hq);
    cudaGetSymbolAddress((void**)&p_hs, g_hs);

    const int smemP = (int)PR_SMEM;    // 74240
    const int smemO = (int)OL_SMEM;    // 212992
    const int smemA = ATT_SMEM;        // 101376
    cudaFuncSetAttribute(proj_mma,  cudaFuncAttributeMaxDynamicSharedMemorySize, smemP);
    cudaFuncSetAttribute(outln_mma, cudaFuncAttributeMaxDynamicSharedMemorySize, smemO);
    cudaFuncSetAttribute(attn_kernel, cudaFuncAttributeMaxDynamicSharedMemorySize, smemA);

    dim3 pg(BS / 128, 2);
    dim3 ag(Ssz / 32, Bsz);
    const int og = BS / 128;

    // block 1
    proj_mma<<<pg, 512, smemP>>>(q_emb, W_lin, b_lin, p_qk);
    attn_kernel<<<ag, 256, smemA>>>(p_qk, p_qk, p_at, nullptr);
    outln_mma<<<og, 512, smemO>>>(p_at, W_out, b_out, q_emb, ln_g, ln_b, p_hq);

    // block 2
    proj_mma<<<pg, 512, smemP>>>(s_emb, W_lin + 2*128*128, b_lin + 2*128, p_qk);
    attn_kernel<<<ag, 256, smemA>>>(p_qk, p_qk, p_at, qs);
    outln_mma<<<og, 512, smemO>>>(p_at, W_out + 256*256, b_out + 256,
                                  s_emb, ln_g + 256, ln_b + 256, p_hs);

    // block 3
    proj_mma<<<pg, 512, smemP>>>(p_hq, W_lin + 4*128*128, b_lin + 4*128, p_qk);
    proj_mma<<<pg, 512, smemP>>>(p_hs, W_lin + 4*128*128, b_lin + 4*128, p_v);
    attn_kernel<<<ag, 256, smemA>>>(p_qk, p_v, p_at, nullptr);
    outln_mma<<<og, 512, smemO>>>(p_at, W_out + 2*256*256, b_out + 2*256,
                                  p_hq, ln_g + 2*256, ln_b + 2*256, z);
}

// round 5
// speedup vs baseline: 2.4374x; 1.3889x over previous
#include <cuda_runtime.h>
#include <cuda_bf16.h>
#include <cstdint>

#define Bsz 32
#define Ssz 2048
#define BS (Bsz*Ssz)   // 65536 rows
#define WIN 44         // attention smem window rows (32 + 2*6 halo)

// ---------------- scratch (device globals; no allocation) ----------------
__device__ float g_qk[(size_t)BS*256];
__device__ float g_v [(size_t)BS*256];
__device__ float g_hq[(size_t)BS*256];
__device__ float g_hs[(size_t)BS*256];
__device__ __nv_bfloat16 g_ath[(size_t)BS*256];
__device__ __nv_bfloat16 g_atl[(size_t)BS*256];
__device__ __nv_bfloat16 g_wlh[3*2*128*128];
__device__ __nv_bfloat16 g_wll[3*2*128*128];
__device__ __nv_bfloat16 g_woh[3*256*256];
__device__ __nv_bfloat16 g_wol[3*256*256];

// ================= helpers =================
__device__ __forceinline__ uint32_t smem_u32(const void* p) {
    uint32_t a;
    asm("{ .reg .u64 t; cvta.to.shared.u64 t, %1; cvt.u32.u64 %0, t; }"
        : "=r"(a) : "l"(p));
    return a;
}
__device__ __forceinline__ void ldsm4(uint32_t r[4], uint32_t addr) {
    asm volatile("ldmatrix.sync.aligned.m8n8.x4.shared.b16 {%0,%1,%2,%3}, [%4];"
                 : "=r"(r[0]), "=r"(r[1]), "=r"(r[2]), "=r"(r[3]) : "r"(addr));
}
__device__ __forceinline__ void mma_bf16(float4& c, const uint32_t a[4],
                                         uint32_t b0, uint32_t b1) {
    asm volatile(
        "mma.sync.aligned.m16n8k16.row.col.f32.bf16.bf16.f32 "
        "{%0,%1,%2,%3}, {%4,%5,%6,%7}, {%8,%9}, {%0,%1,%2,%3};"
        : "+f"(c.x), "+f"(c.y), "+f"(c.z), "+f"(c.w)
        : "r"(a[0]), "r"(a[1]), "r"(a[2]), "r"(a[3]), "r"(b0), "r"(b1));
}
__device__ __forceinline__ void cp16(uint32_t dst, const void* src) {
    asm volatile("cp.async.cg.shared.global [%0], [%1], 16;"
                 :: "r"(dst), "l"(src) : "memory");
}
// fp32 pair -> bf16x2 hi + bf16x2 lo (3-term split source)
__device__ __forceinline__ void split2(float x0, float x1, uint32_t& hi, uint32_t& lo) {
    __nv_bfloat162 h = __floats2bfloat162_rn(x0, x1);
    hi = *reinterpret_cast<uint32_t*>(&h);
    __nv_bfloat162 l = __floats2bfloat162_rn(x0 - __bfloat162float(h.x),
                                             x1 - __bfloat162float(h.y));
    lo = *reinterpret_cast<uint32_t*>(&l);
}

// Fill a 128-row x 64-col chunk (fp32 src) into hi/lo bf16 smem, row stride 72 halves.
__device__ __forceinline__ void fill128(const float* __restrict__ src, int stride,
                                        uint32_t* __restrict__ hi,
                                        uint32_t* __restrict__ lo, int tid) {
    #pragma unroll
    for (int it = 0; it < 8; it++) {
        int idx = tid + it * 512;
        int row = idx >> 5, c2 = idx & 31;
        float2 v = *(const float2*)(src + (size_t)row * stride + c2 * 2);
        uint32_t h, l;
        split2(v.x, v.y, h, l);
        hi[row * 36 + c2] = h;
        lo[row * 36 + c2] = l;
    }
}

// ================= weight split prep (runs every call; ~5us) =================
__global__ void split_w(const float* __restrict__ Wl, const float* __restrict__ Wo,
                        __nv_bfloat16* __restrict__ wlh, __nv_bfloat16* __restrict__ wll,
                        __nv_bfloat16* __restrict__ woh, __nv_bfloat16* __restrict__ wol)
{
    int i = blockIdx.x * 256 + threadIdx.x;
    if (i < 3*2*128*128) {
        float v = Wl[i];
        __nv_bfloat16 h = __float2bfloat16_rn(v);
        wlh[i] = h;
        wll[i] = __float2bfloat16_rn(v - __bfloat162float(h));
    }
    if (i < 3*256*256) {
        float v = Wo[i];
        __nv_bfloat16 h = __float2bfloat16_rn(v);
        woh[i] = h;
        wol[i] = __float2bfloat16_rn(v - __bfloat162float(h));
    }
}

// ================= projection GEMM (mma.sync bf16 3-term, pre-split W) =================
#define PR_BIAS 73728u
#define PR_SMEM 74240u

__global__ __launch_bounds__(512) void proj_mma(
    const float* __restrict__ x,
    const __nv_bfloat16* __restrict__ whi, const __nv_bfloat16* __restrict__ wlo,
    const float* __restrict__ bias, float* __restrict__ out)
{
    extern __shared__ __align__(16) char sm[];
    uint32_t* Ahi = (uint32_t*)(sm);
    uint32_t* Alo = (uint32_t*)(sm + 18432);
    char* Bhi = sm + 36864;
    char* Blo = sm + 55296;
    float* sbias  = (float*)(sm + PR_BIAS);
    float* stg    = (float*)sm;            // 128x132 fp32, overlaps operands post-GEMM

    const int branch = blockIdx.y;
    const int r0 = blockIdx.x * 128;
    const int tid = threadIdx.x, lane = tid & 31, wid = tid >> 5;
    const int m0 = (wid >> 2) * 32, n0 = (wid & 3) * 32;

    if (tid < 128) sbias[tid] = bias[branch * 128 + tid];

    const uint32_t sA = smem_u32(Ahi), sB = smem_u32(Bhi);
    const int a_row = lane & 15, a_kh = (lane >> 4) << 3;
    const int b_n = (lane & 7) + ((lane >> 4) << 3);
    const int b_kh = ((lane >> 3) & 1) << 3;

    float4 acc[2][4];
    #pragma unroll
    for (int i = 0; i < 2; i++)
        #pragma unroll
        for (int j = 0; j < 4; j++) acc[i][j] = make_float4(0.f, 0.f, 0.f, 0.f);

    const float* xp = x + (size_t)r0 * 256 + branch * 128;
    const __nv_bfloat16* whb = whi + (size_t)branch * 128 * 128;
    const __nv_bfloat16* wlb = wlo + (size_t)branch * 128 * 128;

    uint32_t aAddr[2], bAddr[2];
    aAddr[0] = sA + ((m0 + a_row) * 72 + a_kh) * 2;
    aAddr[1] = sA + ((m0 + 16 + a_row) * 72 + a_kh) * 2;
    bAddr[0] = sB + ((n0 + b_n) * 72 + b_kh) * 2;
    bAddr[1] = sB + ((n0 + 16 + b_n) * 72 + b_kh) * 2;

    for (int kc = 0; kc < 128; kc += 64) {
        fill128(xp + kc, 256, Ahi, Alo, tid);
        // direct bf16 copies for W (no conversion)
        #pragma unroll
        for (int it = 0; it < 2; it++) {
            int idx = tid + it * 512;
            int row = idx >> 3, u = idx & 7;
            *(uint4*)(Bhi + row * 144 + u * 16) =
                *(const uint4*)(whb + row * 128 + kc + u * 8);
            *(uint4*)(Blo + row * 144 + u * 16) =
                *(const uint4*)(wlb + row * 128 + kc + u * 8);
        }
        __syncthreads();
        #pragma unroll
        for (int ks = 0; ks < 4; ks++) {
            uint32_t ah[2][4], al[2][4], bh[2][4], bl[2][4];
            #pragma unroll
            for (int mt = 0; mt < 2; mt++) {
                ldsm4(ah[mt], aAddr[mt] + ks * 32);
                ldsm4(al[mt], aAddr[mt] + 18432 + ks * 32);
            }
            #pragma unroll
            for (int bt = 0; bt < 2; bt++) {
                ldsm4(bh[bt], bAddr[bt] + ks * 32);
                ldsm4(bl[bt], bAddr[bt] + 18432 + ks * 32);
            }
            #pragma unroll
            for (int mt = 0; mt < 2; mt++)
                #pragma unroll
                for (int bt = 0; bt < 2; bt++)
                    #pragma unroll
                    for (int sub = 0; sub < 2; sub++) {
                        int nt = bt * 2 + sub;
                        mma_bf16(acc[mt][nt], ah[mt], bh[bt][sub*2], bh[bt][sub*2+1]);
                        mma_bf16(acc[mt][nt], al[mt], bh[bt][sub*2], bh[bt][sub*2+1]);
                        mma_bf16(acc[mt][nt], ah[mt], bl[bt][sub*2], bl[bt][sub*2+1]);
                    }
        }
        __syncthreads();
    }

    // epilogue: bias + permuted store to staging, then coalesced gmem write
    #pragma unroll
    for (int mt = 0; mt < 2; mt++) {
        int rb = m0 + mt * 16 + (lane >> 2);
        #pragma unroll
        for (int nt = 0; nt < 4; nt++) {
            int j = n0 + nt * 8 + (lane & 3) * 2;
            int p0 = ((j & 31) << 2) + (j >> 5);
            int p1 = (((j + 1) & 31) << 2) + ((j + 1) >> 5);
            float4 a = acc[mt][nt];
            stg[rb * 132 + p0]       = a.x + sbias[j];
            stg[rb * 132 + p1]       = a.y + sbias[j + 1];
            stg[(rb + 8) * 132 + p0] = a.z + sbias[j];
            stg[(rb + 8) * 132 + p1] = a.w + sbias[j + 1];
        }
    }
    __syncthreads();
    #pragma unroll
    for (int it = 0; it < 8; it++) {
        int idx = tid + it * 512;
        int row = idx >> 5, q = idx & 31;
        float4 v = *(const float4*)(stg + row * 132 + q * 4);
        *(float4*)(out + (size_t)(r0 + row) * 256 + branch * 128 + q * 4) = v;
    }
}

// ================= out-proj + bias + residual + LayerNorm =================
// Pre-split bf16 operands, cp.async double-buffered K-chunks, register epilogue.
// tile 128 rows x 256 cols, 16 warps, warp tile 32x64.
#define OLS_STAGE 110592u
#define OLS_SUM   221184u
#define OLS_SQ    223232u
#define OLS_SMEM  225280u

__global__ __launch_bounds__(512) void outln_mma(
    const __nv_bfloat16* __restrict__ Ahi, const __nv_bfloat16* __restrict__ Alo,
    const __nv_bfloat16* __restrict__ Whi, const __nv_bfloat16* __restrict__ Wlo,
    const float* __restrict__ bo, const float* __restrict__ xres,
    const float* __restrict__ g, const float* __restrict__ bb,
    float* __restrict__ out)
{
    extern __shared__ __align__(16) char sm[];
    const int r0 = blockIdx.x * 128;
    const int tid = threadIdx.x, lane = tid & 31, wid = tid >> 5;
    const int m0 = (wid >> 2) * 32, n0 = (wid & 3) * 64;
    const uint32_t sb = smem_u32(sm);

    auto load_chunk = [&](int kc) {
        uint32_t st = sb + (uint32_t)(kc & 1) * OLS_STAGE;
        const __nv_bfloat16* ah = Ahi + (size_t)r0 * 256 + kc * 64;
        const __nv_bfloat16* al = Alo + (size_t)r0 * 256 + kc * 64;
        const __nv_bfloat16* wh = Whi + kc * 64;
        const __nv_bfloat16* wl = Wlo + kc * 64;
        #pragma unroll
        for (int it = 0; it < 2; it++) {
            int idx = tid + it * 512;
            int row = idx >> 3, u = idx & 7;
            uint32_t d = st + row * 144 + u * 16;
            cp16(d, ah + (size_t)row * 256 + u * 8);
            cp16(d + 18432, al + (size_t)row * 256 + u * 8);
        }
        #pragma unroll
        for (int it = 0; it < 4; it++) {
            int idx = tid + it * 512;
            int row = idx >> 3, u = idx & 7;
            uint32_t d = st + 36864u + row * 144 + u * 16;
            cp16(d, wh + (size_t)row * 256 + u * 8);
            cp16(d + 36864, wl + (size_t)row * 256 + u * 8);
        }
        asm volatile("cp.async.commit_group;" ::: "memory");
    };

    const int a_row = lane & 15, a_kh = (lane >> 4) << 3;
    const int b_n = (lane & 7) + ((lane >> 4) << 3);
    const int b_kh = ((lane >> 3) & 1) << 3;
    const uint32_t aOff = ((m0 + a_row) * 72 + a_kh) * 2;
    const uint32_t bOff = 36864u + ((n0 + b_n) * 72 + b_kh) * 2;

    float4 acc[2][8];
    #pragma unroll
    for (int i = 0; i < 2; i++)
        #pragma unroll
        for (int j = 0; j < 8; j++) acc[i][j] = make_float4(0.f, 0.f, 0.f, 0.f);

    load_chunk(0);
    #pragma unroll 1
    for (int kc = 0; kc < 4; kc++) {
        if (kc < 3) {
            load_chunk(kc + 1);
            asm volatile("cp.async.wait_group 1;" ::: "memory");
        } else {
            asm volatile("cp.async.wait_group 0;" ::: "memory");
        }
        __syncthreads();
        uint32_t st = sb + (uint32_t)(kc & 1) * OLS_STAGE;
        uint32_t aB = st + aOff, bB = st + bOff;
        #pragma unroll
        for (int ks = 0; ks < 4; ks++) {
            uint32_t ah[2][4], al[2][4];
            ldsm4(ah[0], aB + ks * 32);
            ldsm4(ah[1], aB + 2304 + ks * 32);
            ldsm4(al[0], aB + 18432 + ks * 32);
            ldsm4(al[1], aB + 18432 + 2304 + ks * 32);
            #pragma unroll
            for (int nb = 0; nb < 4; nb++) {
                uint32_t bh[4], bl[4];
                ldsm4(bh, bB + nb * 2304 + ks * 32);
                ldsm4(bl, bB + 36864 + nb * 2304 + ks * 32);
                #pragma unroll
                for (int mt = 0; mt < 2; mt++)
                    #pragma unroll
                    for (int sub = 0; sub < 2; sub++) {
                        int nt = nb * 2 + sub;
                        mma_bf16(acc[mt][nt], ah[mt], bh[sub*2], bh[sub*2+1]);
                        mma_bf16(acc[mt][nt], al[mt], bh[sub*2], bh[sub*2+1]);
                        mma_bf16(acc[mt][nt], ah[mt], bl[sub*2], bl[sub*2+1]);
                    }
            }
        }
        __syncthreads();
    }

    // ---- register epilogue: bias + residual + LN ----
    float sums[2][2] = {{0.f,0.f},{0.f,0.f}}, sqs[2][2] = {{0.f,0.f},{0.f,0.f}};
    #pragma unroll
    for (int mt = 0; mt < 2; mt++) {
        int rl = r0 + m0 + mt * 16 + (lane >> 2);
        #pragma unroll
        for (int nt = 0; nt < 8; nt++) {
            int c = n0 + nt * 8 + (lane & 3) * 2;
            float2 bo2 = *(const float2*)(bo + c);
            float2 xl = *(const float2*)(xres + (size_t)rl * 256 + c);
            float2 xh = *(const float2*)(xres + (size_t)(rl + 8) * 256 + c);
            float4& a = acc[mt][nt];
            a.x += bo2.x + xl.x; a.y += bo2.y + xl.y;
            a.z += bo2.x + xh.x; a.w += bo2.y + xh.y;
            sums[mt][0] += a.x + a.y; sqs[mt][0] += a.x*a.x + a.y*a.y;
            sums[mt][1] += a.z + a.w; sqs[mt][1] += a.z*a.z + a.w*a.w;
        }
    }
    #pragma unroll
    for (int mt = 0; mt < 2; mt++)
        #pragma unroll
        for (int hf = 0; hf < 2; hf++) {
            sums[mt][hf] += __shfl_xor_sync(0xffffffffu, sums[mt][hf], 1);
            sums[mt][hf] += __shfl_xor_sync(0xffffffffu, sums[mt][hf], 2);
            sqs[mt][hf]  += __shfl_xor_sync(0xffffffffu, sqs[mt][hf], 1);
            sqs[mt][hf]  += __shfl_xor_sync(0xffffffffu, sqs[mt][hf], 2);
        }
    float* ssum = (float*)(sm + OLS_SUM);
    float* ssq  = (float*)(sm + OLS_SQ);
    if ((lane & 3) == 0) {
        #pragma unroll
        for (int mt = 0; mt < 2; mt++)
            #pragma unroll
            for (int hf = 0; hf < 2; hf++) {
                int row = m0 + mt * 16 + hf * 8 + (lane >> 2);
                ssum[(wid & 3) * 128 + row] = sums[mt][hf];
                ssq [(wid & 3) * 128 + row] = sqs[mt][hf];
            }
    }
    __syncthreads();
    float mu[2][2], rs[2][2];
    #pragma unroll
    for (int mt = 0; mt < 2; mt++)
        #pragma unroll
        for (int hf = 0; hf < 2; hf++) {
            int row = m0 + mt * 16 + hf * 8 + (lane >> 2);
            float s = ssum[row] + ssum[128 + row] + ssum[256 + row] + ssum[384 + row];
            float q = ssq[row] + ssq[128 + row] + ssq[256 + row] + ssq[384 + row];
            float m = s * (1.f / 256.f);
            mu[mt][hf] = m;
            rs[mt][hf] = rsqrtf(q * (1.f / 256.f) - m * m + 1e-5f);
        }
    #pragma unroll
    for (int mt = 0; mt < 2; mt++) {
        int rl = r0 + m0 + mt * 16 + (lane >> 2);
        #pragma unroll
        for (int nt = 0; nt < 8; nt++) {
            int c = n0 + nt * 8 + (lane & 3) * 2;
            float2 g2 = *(const float2*)(g + c);
            float2 b2 = *(const float2*)(bb + c);
            float4 a = acc[mt][nt];
            float2 o1, o2;
            o1.x = (a.x - mu[mt][0]) * rs[mt][0] * g2.x + b2.x;
            o1.y = (a.y - mu[mt][0]) * rs[mt][0] * g2.y + b2.y;
            o2.x = (a.z - mu[mt][1]) * rs[mt][1] * g2.x + b2.x;
            o2.y = (a.w - mu[mt][1]) * rs[mt][1] * g2.y + b2.y;
            *(float2*)(out + (size_t)rl * 256 + c) = o1;
            *(float2*)(out + (size_t)(rl + 8) * 256 + c) = o2;
        }
    }
}

// ================= dilated local attention (bf16 hi/lo output) =================
#define ATT_STRIDE 288
#define ATT_SMEM (2 * WIN * ATT_STRIDE * 4)   // 101376 B

__global__ __launch_bounds__(256) void attn_kernel(
    const float* __restrict__ QK, const float* __restrict__ V,
    __nv_bfloat16* __restrict__ ath, __nv_bfloat16* __restrict__ atl,
    float* __restrict__ scores)
{
    extern __shared__ float smf[];
    float* sQK = smf;
    float* sV  = smf + WIN * ATT_STRIDE;
    const int b  = blockIdx.y;
    const int s0 = blockIdx.x * 32;
    const int tid = threadIdx.x;

    for (int idx = tid; idx < WIN * 64; idx += 256) {
        int w = idx >> 6, c4 = idx & 63;
        int s = s0 + w - 6;
        float4 vq = make_float4(0.f, 0.f, 0.f, 0.f);
        float4 vv = vq;
        if (s >= 0 && s < Ssz) {
            size_t off = ((size_t)b * Ssz + s) * 64 + c4;
            vq = ((const float4*)QK)[off];
            vv = ((const float4*)V)[off];
        }
        int sc = w * ATT_STRIDE + (c4 >> 3) * 36 + (c4 & 7) * 4;
        *(float4*)(sQK + sc) = vq;
        *(float4*)(sV + sc)  = vv;
    }
    __syncthreads();

    const int sl = tid >> 3, h = tid & 7;
    const int dil = (h < 4) ? 3 : 1;
    const float scale = 0.1767766952966369f;  // 32^-0.5
    const int colb = h * 36;

    float4 q[8];
    {
        const float* qr = sQK + (sl + 6) * ATT_STRIDE + colb;
        #pragma unroll
        for (int j = 0; j < 8; j++) q[j] = *(const float4*)(qr + j * 4);
    }

    float sc[5];
    #pragma unroll
    for (int k = 0; k < 5; k++) {
        const float* kr = sQK + (sl + 6 + (k - 2) * dil) * ATT_STRIDE + colb;
        float d = 0.f;
        #pragma unroll
        for (int j = 0; j < 8; j++) {
            float4 kv = *(const float4*)(kr + j * 4);
            d += q[j].x * kv.x + q[j].y * kv.y + q[j].z * kv.z + q[j].w * kv.w;
        }
        sc[k] = d * scale;
    }
    float mx = sc[0];
    #pragma unroll
    for (int k = 1; k < 5; k++) mx = fmaxf(mx, sc[k]);
    float ex[5], sum = 0.f;
    #pragma unroll
    for (int k = 0; k < 5; k++) { ex[k] = __expf(sc[k] - mx); sum += ex[k]; }
    float inv = 1.f / sum;
    #pragma unroll
    for (int k = 0; k < 5; k++) ex[k] *= inv;

    size_t base = ((size_t)b * Ssz + s0 + sl) * 256 + h * 32;
    const float* v0 = sV + (sl + 6 - 2 * dil) * ATT_STRIDE + colb;
    const int vstep = dil * ATT_STRIDE;
    uint32_t Hw[16], Lw[16];
    #pragma unroll
    for (int j = 0; j < 8; j++) {
        float4 o = make_float4(0.f, 0.f, 0.f, 0.f);
        #pragma unroll
        for (int k = 0; k < 5; k++) {
            float4 vv = *(const float4*)(v0 + k * vstep + j * 4);
            o.x += ex[k] * vv.x; o.y += ex[k] * vv.y;
            o.z += ex[k] * vv.z; o.w += ex[k] * vv.w;
        }
        split2(o.x, o.y, Hw[2*j],   Lw[2*j]);
        split2(o.z, o.w, Hw[2*j+1], Lw[2*j+1]);
    }
    #pragma unroll
    for (int u = 0; u < 4; u++) {
        uint4 vh = make_uint4(Hw[u*4], Hw[u*4+1], Hw[u*4+2], Hw[u*4+3]);
        uint4 vl = make_uint4(Lw[u*4], Lw[u*4+1], Lw[u*4+2], Lw[u*4+3]);
        *(uint4*)((char*)(ath + base) + u * 16) = vh;
        *(uint4*)((char*)(atl + base) + u * 16) = vl;
    }

    if (scores != nullptr) {
        float* sp = scores + (((size_t)b * 8 + h) * Ssz + s0 + sl) * 5;
        #pragma unroll
        for (int k = 0; k < 5; k++) sp[k] = ex[k];
    }
}

// ================= launch =================
extern "C" void kernel_launch(void* const* d_in, const int* in_sizes, int n_in,
                              void* d_out, int out_size)
{
    (void)in_sizes; (void)n_in; (void)out_size;
    const float* q_emb = (const float*)d_in[0];
    const float* s_emb = (const float*)d_in[1];
    const float* W_lin = (const float*)d_in[3];  // (3,2,128,128)
    const float* b_lin = (const float*)d_in[4];  // (3,2,128)
    const float* W_out = (const float*)d_in[5];  // (3,256,256)
    const float* b_out = (const float*)d_in[6];  // (3,256)
    const float* ln_g  = (const float*)d_in[7];  // (3,256)
    const float* ln_b  = (const float*)d_in[8];  // (3,256)

    float* outp = (float*)d_out;
    float* z  = outp;
    float* qs = outp + (size_t)BS * 256;

    float *p_qk, *p_v, *p_hq, *p_hs;
    __nv_bfloat16 *p_ath, *p_atl, *p_wlh, *p_wll, *p_woh, *p_wol;
    cudaGetSymbolAddress((void**)&p_qk, g_qk);
    cudaGetSymbolAddress((void**)&p_v,  g_v);
    cudaGetSymbolAddress((void**)&p_hq, g_hq);
    cudaGetSymbolAddress((void**)&p_hs, g_hs);
    cudaGetSymbolAddress((void**)&p_ath, g_ath);
    cudaGetSymbolAddress((void**)&p_atl, g_atl);
    cudaGetSymbolAddress((void**)&p_wlh, g_wlh);
    cudaGetSymbolAddress((void**)&p_wll, g_wll);
    cudaGetSymbolAddress((void**)&p_woh, g_woh);
    cudaGetSymbolAddress((void**)&p_wol, g_wol);

    const int smemP = (int)PR_SMEM;    // 74240
    const int smemO = (int)OLS_SMEM;   // 225280
    const int smemA = ATT_SMEM;        // 101376
    cudaFuncSetAttribute(proj_mma,  cudaFuncAttributeMaxDynamicSharedMemorySize, smemP);
    cudaFuncSetAttribute(outln_mma, cudaFuncAttributeMaxDynamicSharedMemorySize, smemO);
    cudaFuncSetAttribute(attn_kernel, cudaFuncAttributeMaxDynamicSharedMemorySize, smemA);

    split_w<<<768, 256>>>(W_lin, W_out, p_wlh, p_wll, p_woh, p_wol);

    dim3 pg(BS / 128, 2);
    dim3 ag(Ssz / 32, Bsz);
    const int og = BS / 128;

    // block 1
    proj_mma<<<pg, 512, smemP>>>(q_emb, p_wlh, p_wll, b_lin, p_qk);
    attn_kernel<<<ag, 256, smemA>>>(p_qk, p_qk, p_ath, p_atl, nullptr);
    outln_mma<<<og, 512, smemO>>>(p_ath, p_atl, p_woh, p_wol,
                                  b_out, q_emb, ln_g, ln_b, p_hq);

    // block 2
    proj_mma<<<pg, 512, smemP>>>(s_emb, p_wlh + 32768, p_wll + 32768, b_lin + 256, p_qk);
    attn_kernel<<<ag, 256, smemA>>>(p_qk, p_qk, p_ath, p_atl, qs);
    outln_mma<<<og, 512, smemO>>>(p_ath, p_atl, p_woh + 65536, p_wol + 65536,
                                  b_out + 256, s_emb, ln_g + 256, ln_b + 256, p_hs);

    // block 3
    proj_mma<<<pg, 512, smemP>>>(p_hq, p_wlh + 65536, p_wll + 65536, b_lin + 512, p_qk);
    proj_mma<<<pg, 512, smemP>>>(p_hs, p_wlh + 65536, p_wll + 65536, b_lin + 512, p_v);
    attn_kernel<<<ag, 256, smemA>>>(p_qk, p_v, p_ath, p_atl, nullptr);
    outln_mma<<<og, 512, smemO>>>(p_ath, p_atl, p_woh + 131072, p_wol + 131072,
                                  b_out + 512, p_hq, ln_g + 512, ln_b + 512, z);
}

// round 6
// speedup vs baseline: 2.9846x; 1.2245x over previous
#include <cuda_runtime.h>
#include <cuda_fp16.h>
#include <cstdint>

#define Bsz 32
#define Ssz 2048
#define BS (Bsz*Ssz)   // 65536 rows
#define WIN 44         // attention smem window rows (32 + 2*6 halo)

// ---------------- scratch (device globals; no allocation) ----------------
__device__ float g_qk[(size_t)BS*256];
__device__ float g_v [(size_t)BS*256];
__device__ float g_hq[(size_t)BS*256];
__device__ float g_hs[(size_t)BS*256];
__device__ __half g_ath[(size_t)BS*256];
__device__ __half g_atl[(size_t)BS*256];
__device__ __half g_wlh[3*2*128*128];
__device__ __half g_woh[3*256*256];

// ================= helpers =================
__device__ __forceinline__ uint32_t smem_u32(const void* p) {
    uint32_t a;
    asm("{ .reg .u64 t; cvta.to.shared.u64 t, %1; cvt.u32.u64 %0, t; }"
        : "=r"(a) : "l"(p));
    return a;
}
__device__ __forceinline__ void ldsm4(uint32_t r[4], uint32_t addr) {
    asm volatile("ldmatrix.sync.aligned.m8n8.x4.shared.b16 {%0,%1,%2,%3}, [%4];"
                 : "=r"(r[0]), "=r"(r[1]), "=r"(r[2]), "=r"(r[3]) : "r"(addr));
}
__device__ __forceinline__ void mma_f16(float4& c, const uint32_t a[4],
                                        uint32_t b0, uint32_t b1) {
    asm volatile(
        "mma.sync.aligned.m16n8k16.row.col.f32.f16.f16.f32 "
        "{%0,%1,%2,%3}, {%4,%5,%6,%7}, {%8,%9}, {%0,%1,%2,%3};"
        : "+f"(c.x), "+f"(c.y), "+f"(c.z), "+f"(c.w)
        : "r"(a[0]), "r"(a[1]), "r"(a[2]), "r"(a[3]), "r"(b0), "r"(b1));
}
__device__ __forceinline__ void cp16(uint32_t dst, const void* src) {
    asm volatile("cp.async.cg.shared.global [%0], [%1], 16;"
                 :: "r"(dst), "l"(src) : "memory");
}
// fp32 pair -> fp16x2 hi + fp16x2 lo (2-term split source; A gets 22 bits)
__device__ __forceinline__ void split2(float x0, float x1, uint32_t& hi, uint32_t& lo) {
    __half2 h = __floats2half2_rn(x0, x1);
    hi = *reinterpret_cast<uint32_t*>(&h);
    __half2 l = __floats2half2_rn(x0 - __low2float(h), x1 - __high2float(h));
    lo = *reinterpret_cast<uint32_t*>(&l);
}

// Fill a 128-row x 64-col chunk (fp32 src) into hi/lo fp16 smem, row stride 72 halves.
__device__ __forceinline__ void fill128(const float* __restrict__ src, int stride,
                                        uint32_t* __restrict__ hi,
                                        uint32_t* __restrict__ lo, int tid) {
    #pragma unroll
    for (int it = 0; it < 8; it++) {
        int idx = tid + it * 512;
        int row = idx >> 5, c2 = idx & 31;
        float2 v = *(const float2*)(src + (size_t)row * stride + c2 * 2);
        uint32_t h, l;
        split2(v.x, v.y, h, l);
        hi[row * 36 + c2] = h;
        lo[row * 36 + c2] = l;
    }
}

// ================= weight fp16 prep (runs every call; ~4us) =================
__global__ void split_w(const float* __restrict__ Wl, const float* __restrict__ Wo,
                        __half* __restrict__ wlh, __half* __restrict__ woh)
{
    int i = blockIdx.x * 256 + threadIdx.x;
    if (i < 3*2*128*128) wlh[i] = __float2half_rn(Wl[i]);
    if (i < 3*256*256)   woh[i] = __float2half_rn(Wo[i]);
}

// ================= projection GEMM (mma.sync fp16 2-term) =================
// out[row, branch*128 + perm(j)] = sum_c x[row,...+c]*W[j,c] + bias[j]
#define PR_BIAS 67584u
#define PR_SMEM 68096u

__global__ __launch_bounds__(512) void proj_mma(
    const float* __restrict__ x,
    const __half* __restrict__ whi,
    const float* __restrict__ bias, float* __restrict__ out)
{
    extern __shared__ __align__(16) char sm[];
    uint32_t* Ahi = (uint32_t*)(sm);
    uint32_t* Alo = (uint32_t*)(sm + 18432);
    char* Bhi = sm + 36864;
    float* sbias  = (float*)(sm + PR_BIAS);
    float* stg    = (float*)sm;            // 128x132 fp32, overlaps operands post-GEMM

    const int branch = blockIdx.y;
    const int r0 = blockIdx.x * 128;
    const int tid = threadIdx.x, lane = tid & 31, wid = tid >> 5;
    const int m0 = (wid >> 2) * 32, n0 = (wid & 3) * 32;

    if (tid < 128) sbias[tid] = bias[branch * 128 + tid];

    const uint32_t sA = smem_u32(Ahi), sB = smem_u32(Bhi);
    const int a_row = lane & 15, a_kh = (lane >> 4) << 3;
    const int b_n = (lane & 7) + ((lane >> 4) << 3);
    const int b_kh = ((lane >> 3) & 1) << 3;

    float4 acc[2][4];
    #pragma unroll
    for (int i = 0; i < 2; i++)
        #pragma unroll
        for (int j = 0; j < 4; j++) acc[i][j] = make_float4(0.f, 0.f, 0.f, 0.f);

    const float* xp = x + (size_t)r0 * 256 + branch * 128;
    const __half* whb = whi + (size_t)branch * 128 * 128;

    uint32_t aAddr[2], bAddr[2];
    aAddr[0] = sA + ((m0 + a_row) * 72 + a_kh) * 2;
    aAddr[1] = sA + ((m0 + 16 + a_row) * 72 + a_kh) * 2;
    bAddr[0] = sB + ((n0 + b_n) * 72 + b_kh) * 2;
    bAddr[1] = sB + ((n0 + 16 + b_n) * 72 + b_kh) * 2;

    for (int kc = 0; kc < 128; kc += 64) {
        fill128(xp + kc, 256, Ahi, Alo, tid);
        #pragma unroll
        for (int it = 0; it < 2; it++) {
            int idx = tid + it * 512;
            int row = idx >> 3, u = idx & 7;
            *(uint4*)(Bhi + row * 144 + u * 16) =
                *(const uint4*)(whb + row * 128 + kc + u * 8);
        }
        __syncthreads();
        #pragma unroll
        for (int ks = 0; ks < 4; ks++) {
            uint32_t ah[2][4], al[2][4], bh[2][4];
            #pragma unroll
            for (int mt = 0; mt < 2; mt++) {
                ldsm4(ah[mt], aAddr[mt] + ks * 32);
                ldsm4(al[mt], aAddr[mt] + 18432 + ks * 32);
            }
            #pragma unroll
            for (int bt = 0; bt < 2; bt++) ldsm4(bh[bt], bAddr[bt] + ks * 32);
            #pragma unroll
            for (int mt = 0; mt < 2; mt++)
                #pragma unroll
                for (int bt = 0; bt < 2; bt++)
                    #pragma unroll
                    for (int sub = 0; sub < 2; sub++) {
                        int nt = bt * 2 + sub;
                        mma_f16(acc[mt][nt], ah[mt], bh[bt][sub*2], bh[bt][sub*2+1]);
                        mma_f16(acc[mt][nt], al[mt], bh[bt][sub*2], bh[bt][sub*2+1]);
                    }
        }
        __syncthreads();
    }

    // epilogue: bias + permuted store to staging, then coalesced gmem write
    #pragma unroll
    for (int mt = 0; mt < 2; mt++) {
        int rb = m0 + mt * 16 + (lane >> 2);
        #pragma unroll
        for (int nt = 0; nt < 4; nt++) {
            int j = n0 + nt * 8 + (lane & 3) * 2;
            int p0 = ((j & 31) << 2) + (j >> 5);
            int p1 = (((j + 1) & 31) << 2) + ((j + 1) >> 5);
            float4 a = acc[mt][nt];
            stg[rb * 132 + p0]       = a.x + sbias[j];
            stg[rb * 132 + p1]       = a.y + sbias[j + 1];
            stg[(rb + 8) * 132 + p0] = a.z + sbias[j];
            stg[(rb + 8) * 132 + p1] = a.w + sbias[j + 1];
        }
    }
    __syncthreads();
    #pragma unroll
    for (int it = 0; it < 8; it++) {
        int idx = tid + it * 512;
        int row = idx >> 5, q = idx & 31;
        float4 v = *(const float4*)(stg + row * 132 + q * 4);
        *(float4*)(out + (size_t)(r0 + row) * 256 + branch * 128 + q * 4) = v;
    }
}

// ================= out-proj + bias + residual + LayerNorm (fp16 2-term) =================
#define OLS_STAGE 73728u
#define OLS_SUM   147456u
#define OLS_SQ    149504u
#define OLS_SMEM  151552u

__global__ __launch_bounds__(512) void outln_mma(
    const __half* __restrict__ Ahi, const __half* __restrict__ Alo,
    const __half* __restrict__ Whi,
    const float* __restrict__ bo, const float* __restrict__ xres,
    const float* __restrict__ g, const float* __restrict__ bb,
    float* __restrict__ out)
{
    extern __shared__ __align__(16) char sm[];
    const int r0 = blockIdx.x * 128;
    const int tid = threadIdx.x, lane = tid & 31, wid = tid >> 5;
    const int m0 = (wid >> 2) * 32, n0 = (wid & 3) * 64;
    const uint32_t sb = smem_u32(sm);

    auto load_chunk = [&](int kc) {
        uint32_t st = sb + (uint32_t)(kc & 1) * OLS_STAGE;
        const __half* ah = Ahi + (size_t)r0 * 256 + kc * 64;
        const __half* al = Alo + (size_t)r0 * 256 + kc * 64;
        const __half* wh = Whi + kc * 64;
        #pragma unroll
        for (int it = 0; it < 2; it++) {
            int idx = tid + it * 512;
            int row = idx >> 3, u = idx & 7;
            uint32_t d = st + row * 144 + u * 16;
            cp16(d, ah + (size_t)row * 256 + u * 8);
            cp16(d + 18432, al + (size_t)row * 256 + u * 8);
        }
        #pragma unroll
        for (int it = 0; it < 4; it++) {
            int idx = tid + it * 512;
            int row = idx >> 3, u = idx & 7;
            cp16(st + 36864u + row * 144 + u * 16, wh + (size_t)row * 256 + u * 8);
        }
        asm volatile("cp.async.commit_group;" ::: "memory");
    };

    const int a_row = lane & 15, a_kh = (lane >> 4) << 3;
    const int b_n = (lane & 7) + ((lane >> 4) << 3);
    const int b_kh = ((lane >> 3) & 1) << 3;
    const uint32_t aOff = ((m0 + a_row) * 72 + a_kh) * 2;
    const uint32_t bOff = 36864u + ((n0 + b_n) * 72 + b_kh) * 2;

    float4 acc[2][8];
    #pragma unroll
    for (int i = 0; i < 2; i++)
        #pragma unroll
        for (int j = 0; j < 8; j++) acc[i][j] = make_float4(0.f, 0.f, 0.f, 0.f);

    load_chunk(0);
    #pragma unroll 1
    for (int kc = 0; kc < 4; kc++) {
        if (kc < 3) {
            load_chunk(kc + 1);
            asm volatile("cp.async.wait_group 1;" ::: "memory");
        } else {
            asm volatile("cp.async.wait_group 0;" ::: "memory");
        }
        __syncthreads();
        uint32_t st = sb + (uint32_t)(kc & 1) * OLS_STAGE;
        uint32_t aB = st + aOff, bB = st + bOff;
        #pragma unroll
        for (int ks = 0; ks < 4; ks++) {
            uint32_t ah[2][4], al[2][4];
            ldsm4(ah[0], aB + ks * 32);
            ldsm4(ah[1], aB + 2304 + ks * 32);
            ldsm4(al[0], aB + 18432 + ks * 32);
            ldsm4(al[1], aB + 18432 + 2304 + ks * 32);
            #pragma unroll
            for (int nb = 0; nb < 4; nb++) {
                uint32_t bh[4];
                ldsm4(bh, bB + nb * 2304 + ks * 32);
                #pragma unroll
                for (int mt = 0; mt < 2; mt++)
                    #pragma unroll
                    for (int sub = 0; sub < 2; sub++) {
                        int nt = nb * 2 + sub;
                        mma_f16(acc[mt][nt], ah[mt], bh[sub*2], bh[sub*2+1]);
                        mma_f16(acc[mt][nt], al[mt], bh[sub*2], bh[sub*2+1]);
                    }
            }
        }
        __syncthreads();
    }

    // ---- register epilogue: bias + residual + LN ----
    float sums[2][2] = {{0.f,0.f},{0.f,0.f}}, sqs[2][2] = {{0.f,0.f},{0.f,0.f}};
    #pragma unroll
    for (int mt = 0; mt < 2; mt++) {
        int rl = r0 + m0 + mt * 16 + (lane >> 2);
        #pragma unroll
        for (int nt = 0; nt < 8; nt++) {
            int c = n0 + nt * 8 + (lane & 3) * 2;
            float2 bo2 = *(const float2*)(bo + c);
            float2 xl = *(const float2*)(xres + (size_t)rl * 256 + c);
            float2 xh = *(const float2*)(xres + (size_t)(rl + 8) * 256 + c);
            float4& a = acc[mt][nt];
            a.x += bo2.x + xl.x; a.y += bo2.y + xl.y;
            a.z += bo2.x + xh.x; a.w += bo2.y + xh.y;
            sums[mt][0] += a.x + a.y; sqs[mt][0] += a.x*a.x + a.y*a.y;
            sums[mt][1] += a.z + a.w; sqs[mt][1] += a.z*a.z + a.w*a.w;
        }
    }
    #pragma unroll
    for (int mt = 0; mt < 2; mt++)
        #pragma unroll
        for (int hf = 0; hf < 2; hf++) {
            sums[mt][hf] += __shfl_xor_sync(0xffffffffu, sums[mt][hf], 1);
            sums[mt][hf] += __shfl_xor_sync(0xffffffffu, sums[mt][hf], 2);
            sqs[mt][hf]  += __shfl_xor_sync(0xffffffffu, sqs[mt][hf], 1);
            sqs[mt][hf]  += __shfl_xor_sync(0xffffffffu, sqs[mt][hf], 2);
        }
    float* ssum = (float*)(sm + OLS_SUM);
    float* ssq  = (float*)(sm + OLS_SQ);
    if ((lane & 3) == 0) {
        #pragma unroll
        for (int mt = 0; mt < 2; mt++)
            #pragma unroll
            for (int hf = 0; hf < 2; hf++) {
                int row = m0 + mt * 16 + hf * 8 + (lane >> 2);
                ssum[(wid & 3) * 128 + row] = sums[mt][hf];
                ssq [(wid & 3) * 128 + row] = sqs[mt][hf];
            }
    }
    __syncthreads();
    float mu[2][2], rs[2][2];
    #pragma unroll
    for (int mt = 0; mt < 2; mt++)
        #pragma unroll
        for (int hf = 0; hf < 2; hf++) {
            int row = m0 + mt * 16 + hf * 8 + (lane >> 2);
            float s = ssum[row] + ssum[128 + row] + ssum[256 + row] + ssum[384 + row];
            float q = ssq[row] + ssq[128 + row] + ssq[256 + row] + ssq[384 + row];
            float m = s * (1.f / 256.f);
            mu[mt][hf] = m;
            rs[mt][hf] = rsqrtf(q * (1.f / 256.f) - m * m + 1e-5f);
        }
    #pragma unroll
    for (int mt = 0; mt < 2; mt++) {
        int rl = r0 + m0 + mt * 16 + (lane >> 2);
        #pragma unroll
        for (int nt = 0; nt < 8; nt++) {
            int c = n0 + nt * 8 + (lane & 3) * 2;
            float2 g2 = *(const float2*)(g + c);
            float2 b2 = *(const float2*)(bb + c);
            float4 a = acc[mt][nt];
            float2 o1, o2;
            o1.x = (a.x - mu[mt][0]) * rs[mt][0] * g2.x + b2.x;
            o1.y = (a.y - mu[mt][0]) * rs[mt][0] * g2.y + b2.y;
            o2.x = (a.z - mu[mt][1]) * rs[mt][1] * g2.x + b2.x;
            o2.y = (a.w - mu[mt][1]) * rs[mt][1] * g2.y + b2.y;
            *(float2*)(out + (size_t)rl * 256 + c) = o1;
            *(float2*)(out + (size_t)(rl + 8) * 256 + c) = o2;
        }
    }
}

// ================= dilated local attention (fp16 hi/lo output) =================
#define ATT_STRIDE 288
#define ATT_SMEM (2 * WIN * ATT_STRIDE * 4)   // 101376 B

__global__ __launch_bounds__(256) void attn_kernel(
    const float* __restrict__ QK, const float* __restrict__ V,
    __half* __restrict__ ath, __half* __restrict__ atl,
    float* __restrict__ scores)
{
    extern __shared__ float smf[];
    float* sQK = smf;
    float* sV  = smf + WIN * ATT_STRIDE;
    const int b  = blockIdx.y;
    const int s0 = blockIdx.x * 32;
    const int tid = threadIdx.x;

    for (int idx = tid; idx < WIN * 64; idx += 256) {
        int w = idx >> 6, c4 = idx & 63;
        int s = s0 + w - 6;
        float4 vq = make_float4(0.f, 0.f, 0.f, 0.f);
        float4 vv = vq;
        if (s >= 0 && s < Ssz) {
            size_t off = ((size_t)b * Ssz + s) * 64 + c4;
            vq = ((const float4*)QK)[off];
            vv = ((const float4*)V)[off];
        }
        int sc = w * ATT_STRIDE + (c4 >> 3) * 36 + (c4 & 7) * 4;
        *(float4*)(sQK + sc) = vq;
        *(float4*)(sV + sc)  = vv;
    }
    __syncthreads();

    const int sl = tid >> 3, h = tid & 7;
    const int dil = (h < 4) ? 3 : 1;
    const float scale = 0.1767766952966369f;  // 32^-0.5
    const int colb = h * 36;

    float4 q[8];
    {
        const float* qr = sQK + (sl + 6) * ATT_STRIDE + colb;
        #pragma unroll
        for (int j = 0; j < 8; j++) q[j] = *(const float4*)(qr + j * 4);
    }

    float sc[5];
    #pragma unroll
    for (int k = 0; k < 5; k++) {
        const float* kr = sQK + (sl + 6 + (k - 2) * dil) * ATT_STRIDE + colb;
        float d = 0.f;
        #pragma unroll
        for (int j = 0; j < 8; j++) {
            float4 kv = *(const float4*)(kr + j * 4);
            d += q[j].x * kv.x + q[j].y * kv.y + q[j].z * kv.z + q[j].w * kv.w;
        }
        sc[k] = d * scale;
    }
    float mx = sc[0];
    #pragma unroll
    for (int k = 1; k < 5; k++) mx = fmaxf(mx, sc[k]);
    float ex[5], sum = 0.f;
    #pragma unroll
    for (int k = 0; k < 5; k++) { ex[k] = __expf(sc[k] - mx); sum += ex[k]; }
    float inv = 1.f / sum;
    #pragma unroll
    for (int k = 0; k < 5; k++) ex[k] *= inv;

    size_t base = ((size_t)b * Ssz + s0 + sl) * 256 + h * 32;
    const float* v0 = sV + (sl + 6 - 2 * dil) * ATT_STRIDE + colb;
    const int vstep = dil * ATT_STRIDE;
    uint32_t Hw[16], Lw[16];
    #pragma unroll
    for (int j = 0; j < 8; j++) {
        float4 o = make_float4(0.f, 0.f, 0.f, 0.f);
        #pragma unroll
        for (int k = 0; k < 5; k++) {
            float4 vv = *(const float4*)(v0 + k * vstep + j * 4);
            o.x += ex[k] * vv.x; o.y += ex[k] * vv.y;
            o.z += ex[k] * vv.z; o.w += ex[k] * vv.w;
        }
        split2(o.x, o.y, Hw[2*j],   Lw[2*j]);
        split2(o.z, o.w, Hw[2*j+1], Lw[2*j+1]);
    }
    #pragma unroll
    for (int u = 0; u < 4; u++) {
        uint4 vh = make_uint4(Hw[u*4], Hw[u*4+1], Hw[u*4+2], Hw[u*4+3]);
        uint4 vl = make_uint4(Lw[u*4], Lw[u*4+1], Lw[u*4+2], Lw[u*4+3]);
        *(uint4*)((char*)(ath + base) + u * 16) = vh;
        *(uint4*)((char*)(atl + base) + u * 16) = vl;
    }

    if (scores != nullptr) {
        float* sp = scores + (((size_t)b * 8 + h) * Ssz + s0 + sl) * 5;
        #pragma unroll
        for (int k = 0; k < 5; k++) sp[k] = ex[k];
    }
}

// ================= launch =================
extern "C" void kernel_launch(void* const* d_in, const int* in_sizes, int n_in,
                              void* d_out, int out_size)
{
    (void)in_sizes; (void)n_in; (void)out_size;
    const float* q_emb = (const float*)d_in[0];
    const float* s_emb = (const float*)d_in[1];
    const float* W_lin = (const float*)d_in[3];  // (3,2,128,128)
    const float* b_lin = (const float*)d_in[4];  // (3,2,128)
    const float* W_out = (const float*)d_in[5];  // (3,256,256)
    const float* b_out = (const float*)d_in[6];  // (3,256)
    const float* ln_g  = (const float*)d_in[7];  // (3,256)
    const float* ln_b  = (const float*)d_in[8];  // (3,256)

    float* outp = (float*)d_out;
    float* z  = outp;
    float* qs = outp + (size_t)BS * 256;

    float *p_qk, *p_v, *p_hq, *p_hs;
    __half *p_ath, *p_atl, *p_wlh, *p_woh;
    cudaGetSymbolAddress((void**)&p_qk, g_qk);
    cudaGetSymbolAddress((void**)&p_v,  g_v);
    cudaGetSymbolAddress((void**)&p_hq, g_hq);
    cudaGetSymbolAddress((void**)&p_hs, g_hs);
    cudaGetSymbolAddress((void**)&p_ath, g_ath);
    cudaGetSymbolAddress((void**)&p_atl, g_atl);
    cudaGetSymbolAddress((void**)&p_wlh, g_wlh);
    cudaGetSymbolAddress((void**)&p_woh, g_woh);

    const int smemP = (int)PR_SMEM;    // 68096
    const int smemO = (int)OLS_SMEM;   // 151552
    const int smemA = ATT_SMEM;        // 101376
    cudaFuncSetAttribute(proj_mma,  cudaFuncAttributeMaxDynamicSharedMemorySize, smemP);
    cudaFuncSetAttribute(outln_mma, cudaFuncAttributeMaxDynamicSharedMemorySize, smemO);
    cudaFuncSetAttribute(attn_kernel, cudaFuncAttributeMaxDynamicSharedMemorySize, smemA);

    split_w<<<768, 256>>>(W_lin, W_out, p_wlh, p_woh);

    dim3 pg(BS / 128, 2);
    dim3 ag(Ssz / 32, Bsz);
    const int og = BS / 128;

    // block 1
    proj_mma<<<pg, 512, smemP>>>(q_emb, p_wlh, b_lin, p_qk);
    attn_kernel<<<ag, 256, smemA>>>(p_qk, p_qk, p_ath, p_atl, nullptr);
    outln_mma<<<og, 512, smemO>>>(p_ath, p_atl, p_woh,
                                  b_out, q_emb, ln_g, ln_b, p_hq);

    // block 2
    proj_mma<<<pg, 512, smemP>>>(s_emb, p_wlh + 32768, b_lin + 256, p_qk);
    attn_kernel<<<ag, 256, smemA>>>(p_qk, p_qk, p_ath, p_atl, qs);
    outln_mma<<<og, 512, smemO>>>(p_ath, p_atl, p_woh + 65536,
                                  b_out + 256, s_emb, ln_g + 256, ln_b + 256, p_hs);

    // block 3
    proj_mma<<<pg, 512, smemP>>>(p_hq, p_wlh + 65536, b_lin + 512, p_qk);
    proj_mma<<<pg, 512, smemP>>>(p_hs, p_wlh + 65536, b_lin + 512, p_v);
    attn_kernel<<<ag, 256, smemA>>>(p_qk, p_v, p_ath, p_atl, nullptr);
    outln_mma<<<og, 512, smemO>>>(p_ath, p_atl, p_woh + 131072,
                                  b_out + 512, p_hq, ln_g + 512, ln_b + 512, z);
}

// round 7
// speedup vs baseline: 3.3417x; 1.1197x over previous
#include <cuda_runtime.h>
#include <cuda_fp16.h>
#include <cstdint>

#define Bsz 32
#define Ssz 2048
#define BS (Bsz*Ssz)   // 65536 rows
#define WIN 44         // attention smem window rows (32 + 2*6 halo)

// ---------------- scratch (device globals; no allocation) ----------------
__device__ float g_qk0[(size_t)BS*256];
__device__ float g_qk1[(size_t)BS*256];
__device__ float g_v  [(size_t)BS*256];
__device__ float g_hq [(size_t)BS*256];
__device__ float g_hs [(size_t)BS*256];
__device__ __half g_ath0[(size_t)BS*256];
__device__ __half g_atl0[(size_t)BS*256];
__device__ __half g_ath1[(size_t)BS*256];
__device__ __half g_atl1[(size_t)BS*256];
__device__ __half g_wlh[3*2*128*128];
__device__ __half g_woh[3*256*256];

// ================= helpers =================
__device__ __forceinline__ uint32_t smem_u32(const void* p) {
    uint32_t a;
    asm("{ .reg .u64 t; cvta.to.shared.u64 t, %1; cvt.u32.u64 %0, t; }"
        : "=r"(a) : "l"(p));
    return a;
}
__device__ __forceinline__ void ldsm4(uint32_t r[4], uint32_t addr) {
    asm volatile("ldmatrix.sync.aligned.m8n8.x4.shared.b16 {%0,%1,%2,%3}, [%4];"
                 : "=r"(r[0]), "=r"(r[1]), "=r"(r[2]), "=r"(r[3]) : "r"(addr));
}
__device__ __forceinline__ void mma_f16(float4& c, const uint32_t a[4],
                                        uint32_t b0, uint32_t b1) {
    asm volatile(
        "mma.sync.aligned.m16n8k16.row.col.f32.f16.f16.f32 "
        "{%0,%1,%2,%3}, {%4,%5,%6,%7}, {%8,%9}, {%0,%1,%2,%3};"
        : "+f"(c.x), "+f"(c.y), "+f"(c.z), "+f"(c.w)
        : "r"(a[0]), "r"(a[1]), "r"(a[2]), "r"(a[3]), "r"(b0), "r"(b1));
}
__device__ __forceinline__ void cp16(uint32_t dst, const void* src) {
    asm volatile("cp.async.cg.shared.global [%0], [%1], 16;"
                 :: "r"(dst), "l"(src) : "memory");
}
// fp32 pair -> fp16x2 hi + fp16x2 lo (2-term split source; A gets 22 bits)
__device__ __forceinline__ void split2(float x0, float x1, uint32_t& hi, uint32_t& lo) {
    __half2 h = __floats2half2_rn(x0, x1);
    hi = *reinterpret_cast<uint32_t*>(&h);
    __half2 l = __floats2half2_rn(x0 - __low2float(h), x1 - __high2float(h));
    lo = *reinterpret_cast<uint32_t*>(&l);
}

// Fill a 128-row x 64-col chunk (fp32 src) into hi/lo fp16 smem, row stride 72 halves.
__device__ __forceinline__ void fill128(const float* __restrict__ src, int stride,
                                        uint32_t* __restrict__ hi,
                                        uint32_t* __restrict__ lo, int tid) {
    #pragma unroll
    for (int it = 0; it < 8; it++) {
        int idx = tid + it * 512;
        int row = idx >> 5, c2 = idx & 31;
        float2 v = *(const float2*)(src + (size_t)row * stride + c2 * 2);
        uint32_t h, l;
        split2(v.x, v.y, h, l);
        hi[row * 36 + c2] = h;
        lo[row * 36 + c2] = l;
    }
}

// ================= weight fp16 prep =================
__global__ void split_w(const float* __restrict__ Wl, const float* __restrict__ Wo,
                        __half* __restrict__ wlh, __half* __restrict__ woh)
{
    int i = blockIdx.x * 256 + threadIdx.x;
    if (i < 3*2*128*128) wlh[i] = __float2half_rn(Wl[i]);
    if (i < 3*256*256)   woh[i] = __float2half_rn(Wo[i]);
}

// ================= projection GEMM (batched over 2 chains via blockIdx.z) =================
#define PR_BIAS 67584u
#define PR_SMEM 68096u

__global__ __launch_bounds__(512) void proj_mma(
    const float* __restrict__ x0, const float* __restrict__ x1,
    const __half* __restrict__ whi, int wstep,
    const float* __restrict__ bias, int bstep,
    float* __restrict__ out0, float* __restrict__ out1)
{
    extern __shared__ __align__(16) char sm[];
    uint32_t* Ahi = (uint32_t*)(sm);
    uint32_t* Alo = (uint32_t*)(sm + 18432);
    char* Bhi = sm + 36864;
    float* sbias  = (float*)(sm + PR_BIAS);
    float* stg    = (float*)sm;

    const int chain = blockIdx.z;
    const float* x = chain ? x1 : x0;
    float* out = chain ? out1 : out0;
    const int branch = blockIdx.y;
    const int r0 = blockIdx.x * 128;
    const int tid = threadIdx.x, lane = tid & 31, wid = tid >> 5;
    const int m0 = (wid >> 2) * 32, n0 = (wid & 3) * 32;

    const float* bp = bias + chain * bstep + branch * 128;
    if (tid < 128) sbias[tid] = bp[tid];

    const uint32_t sA = smem_u32(Ahi), sB = smem_u32(Bhi);
    const int a_row = lane & 15, a_kh = (lane >> 4) << 3;
    const int b_n = (lane & 7) + ((lane >> 4) << 3);
    const int b_kh = ((lane >> 3) & 1) << 3;

    float4 acc[2][4];
    #pragma unroll
    for (int i = 0; i < 2; i++)
        #pragma unroll
        for (int j = 0; j < 4; j++) acc[i][j] = make_float4(0.f, 0.f, 0.f, 0.f);

    const float* xp = x + (size_t)r0 * 256 + branch * 128;
    const __half* whb = whi + (size_t)chain * wstep + (size_t)branch * 128 * 128;

    uint32_t aAddr[2], bAddr[2];
    aAddr[0] = sA + ((m0 + a_row) * 72 + a_kh) * 2;
    aAddr[1] = sA + ((m0 + 16 + a_row) * 72 + a_kh) * 2;
    bAddr[0] = sB + ((n0 + b_n) * 72 + b_kh) * 2;
    bAddr[1] = sB + ((n0 + 16 + b_n) * 72 + b_kh) * 2;

    for (int kc = 0; kc < 128; kc += 64) {
        fill128(xp + kc, 256, Ahi, Alo, tid);
        #pragma unroll
        for (int it = 0; it < 2; it++) {
            int idx = tid + it * 512;
            int row = idx >> 3, u = idx & 7;
            *(uint4*)(Bhi + row * 144 + u * 16) =
                *(const uint4*)(whb + row * 128 + kc + u * 8);
        }
        __syncthreads();
        #pragma unroll
        for (int ks = 0; ks < 4; ks++) {
            uint32_t ah[2][4], al[2][4], bh[2][4];
            #pragma unroll
            for (int mt = 0; mt < 2; mt++) {
                ldsm4(ah[mt], aAddr[mt] + ks * 32);
                ldsm4(al[mt], aAddr[mt] + 18432 + ks * 32);
            }
            #pragma unroll
            for (int bt = 0; bt < 2; bt++) ldsm4(bh[bt], bAddr[bt] + ks * 32);
            #pragma unroll
            for (int mt = 0; mt < 2; mt++)
                #pragma unroll
                for (int bt = 0; bt < 2; bt++)
                    #pragma unroll
                    for (int sub = 0; sub < 2; sub++) {
                        int nt = bt * 2 + sub;
                        mma_f16(acc[mt][nt], ah[mt], bh[bt][sub*2], bh[bt][sub*2+1]);
                        mma_f16(acc[mt][nt], al[mt], bh[bt][sub*2], bh[bt][sub*2+1]);
                    }
        }
        __syncthreads();
    }

    #pragma unroll
    for (int mt = 0; mt < 2; mt++) {
        int rb = m0 + mt * 16 + (lane >> 2);
        #pragma unroll
        for (int nt = 0; nt < 4; nt++) {
            int j = n0 + nt * 8 + (lane & 3) * 2;
            int p0 = ((j & 31) << 2) + (j >> 5);
            int p1 = (((j + 1) & 31) << 2) + ((j + 1) >> 5);
            float4 a = acc[mt][nt];
            stg[rb * 132 + p0]       = a.x + sbias[j];
            stg[rb * 132 + p1]       = a.y + sbias[j + 1];
            stg[(rb + 8) * 132 + p0] = a.z + sbias[j];
            stg[(rb + 8) * 132 + p1] = a.w + sbias[j + 1];
        }
    }
    __syncthreads();
    #pragma unroll
    for (int it = 0; it < 8; it++) {
        int idx = tid + it * 512;
        int row = idx >> 5, q = idx & 31;
        float4 v = *(const float4*)(stg + row * 132 + q * 4);
        *(float4*)(out + (size_t)(r0 + row) * 256 + branch * 128 + q * 4) = v;
    }
}

// ================= out-proj + bias + residual + LayerNorm (batched, blockIdx.y) =================
#define OLS_STAGE 73728u
#define OLS_SUM   147456u
#define OLS_SQ    149504u
#define OLS_SMEM  151552u

__global__ __launch_bounds__(512) void outln_mma(
    const __half* __restrict__ A0h, const __half* __restrict__ A0l,
    const __half* __restrict__ A1h, const __half* __restrict__ A1l,
    const __half* __restrict__ Whi, int wstep,
    const float* __restrict__ bo, const float* __restrict__ xr0,
    const float* __restrict__ xr1,
    const float* __restrict__ g, const float* __restrict__ bb, int pstep,
    float* __restrict__ out0, float* __restrict__ out1)
{
    extern __shared__ __align__(16) char sm[];
    const int chain = blockIdx.y;
    const __half* Ahi = chain ? A1h : A0h;
    const __half* Alo = chain ? A1l : A0l;
    const __half* Wp  = Whi + (size_t)chain * wstep;
    const float* xres = chain ? xr1 : xr0;
    const float* bop = bo + chain * pstep;
    const float* gp  = g  + chain * pstep;
    const float* bbp = bb + chain * pstep;
    float* out = chain ? out1 : out0;

    const int r0 = blockIdx.x * 128;
    const int tid = threadIdx.x, lane = tid & 31, wid = tid >> 5;
    const int m0 = (wid >> 2) * 32, n0 = (wid & 3) * 64;
    const uint32_t sb = smem_u32(sm);

    auto load_chunk = [&](int kc) {
        uint32_t st = sb + (uint32_t)(kc & 1) * OLS_STAGE;
        const __half* ah = Ahi + (size_t)r0 * 256 + kc * 64;
        const __half* al = Alo + (size_t)r0 * 256 + kc * 64;
        const __half* wh = Wp + kc * 64;
        #pragma unroll
        for (int it = 0; it < 2; it++) {
            int idx = tid + it * 512;
            int row = idx >> 3, u = idx & 7;
            uint32_t d = st + row * 144 + u * 16;
            cp16(d, ah + (size_t)row * 256 + u * 8);
            cp16(d + 18432, al + (size_t)row * 256 + u * 8);
        }
        #pragma unroll
        for (int it = 0; it < 4; it++) {
            int idx = tid + it * 512;
            int row = idx >> 3, u = idx & 7;
            cp16(st + 36864u + row * 144 + u * 16, wh + (size_t)row * 256 + u * 8);
        }
        asm volatile("cp.async.commit_group;" ::: "memory");
    };

    const int a_row = lane & 15, a_kh = (lane >> 4) << 3;
    const int b_n = (lane & 7) + ((lane >> 4) << 3);
    const int b_kh = ((lane >> 3) & 1) << 3;
    const uint32_t aOff = ((m0 + a_row) * 72 + a_kh) * 2;
    const uint32_t bOff = 36864u + ((n0 + b_n) * 72 + b_kh) * 2;

    float4 acc[2][8];
    #pragma unroll
    for (int i = 0; i < 2; i++)
        #pragma unroll
        for (int j = 0; j < 8; j++) acc[i][j] = make_float4(0.f, 0.f, 0.f, 0.f);

    load_chunk(0);
    #pragma unroll 1
    for (int kc = 0; kc < 4; kc++) {
        if (kc < 3) {
            load_chunk(kc + 1);
            asm volatile("cp.async.wait_group 1;" ::: "memory");
        } else {
            asm volatile("cp.async.wait_group 0;" ::: "memory");
        }
        __syncthreads();
        uint32_t st = sb + (uint32_t)(kc & 1) * OLS_STAGE;
        uint32_t aB = st + aOff, bB = st + bOff;
        #pragma unroll
        for (int ks = 0; ks < 4; ks++) {
            uint32_t ah[2][4], al[2][4];
            ldsm4(ah[0], aB + ks * 32);
            ldsm4(ah[1], aB + 2304 + ks * 32);
            ldsm4(al[0], aB + 18432 + ks * 32);
            ldsm4(al[1], aB + 18432 + 2304 + ks * 32);
            #pragma unroll
            for (int nb = 0; nb < 4; nb++) {
                uint32_t bh[4];
                ldsm4(bh, bB + nb * 2304 + ks * 32);
                #pragma unroll
                for (int mt = 0; mt < 2; mt++)
                    #pragma unroll
                    for (int sub = 0; sub < 2; sub++) {
                        int nt = nb * 2 + sub;
                        mma_f16(acc[mt][nt], ah[mt], bh[sub*2], bh[sub*2+1]);
                        mma_f16(acc[mt][nt], al[mt], bh[sub*2], bh[sub*2+1]);
                    }
            }
        }
        __syncthreads();
    }

    float sums[2][2] = {{0.f,0.f},{0.f,0.f}}, sqs[2][2] = {{0.f,0.f},{0.f,0.f}};
    #pragma unroll
    for (int mt = 0; mt < 2; mt++) {
        int rl = r0 + m0 + mt * 16 + (lane >> 2);
        #pragma unroll
        for (int nt = 0; nt < 8; nt++) {
            int c = n0 + nt * 8 + (lane & 3) * 2;
            float2 bo2 = *(const float2*)(bop + c);
            float2 xl = *(const float2*)(xres + (size_t)rl * 256 + c);
            float2 xh = *(const float2*)(xres + (size_t)(rl + 8) * 256 + c);
            float4& a = acc[mt][nt];
            a.x += bo2.x + xl.x; a.y += bo2.y + xl.y;
            a.z += bo2.x + xh.x; a.w += bo2.y + xh.y;
            sums[mt][0] += a.x + a.y; sqs[mt][0] += a.x*a.x + a.y*a.y;
            sums[mt][1] += a.z + a.w; sqs[mt][1] += a.z*a.z + a.w*a.w;
        }
    }
    #pragma unroll
    for (int mt = 0; mt < 2; mt++)
        #pragma unroll
        for (int hf = 0; hf < 2; hf++) {
            sums[mt][hf] += __shfl_xor_sync(0xffffffffu, sums[mt][hf], 1);
            sums[mt][hf] += __shfl_xor_sync(0xffffffffu, sums[mt][hf], 2);
            sqs[mt][hf]  += __shfl_xor_sync(0xffffffffu, sqs[mt][hf], 1);
            sqs[mt][hf]  += __shfl_xor_sync(0xffffffffu, sqs[mt][hf], 2);
        }
    float* ssum = (float*)(sm + OLS_SUM);
    float* ssq  = (float*)(sm + OLS_SQ);
    if ((lane & 3) == 0) {
        #pragma unroll
        for (int mt = 0; mt < 2; mt++)
            #pragma unroll
            for (int hf = 0; hf < 2; hf++) {
                int row = m0 + mt * 16 + hf * 8 + (lane >> 2);
                ssum[(wid & 3) * 128 + row] = sums[mt][hf];
                ssq [(wid & 3) * 128 + row] = sqs[mt][hf];
            }
    }
    __syncthreads();
    float mu[2][2], rs[2][2];
    #pragma unroll
    for (int mt = 0; mt < 2; mt++)
        #pragma unroll
        for (int hf = 0; hf < 2; hf++) {
            int row = m0 + mt * 16 + hf * 8 + (lane >> 2);
            float s = ssum[row] + ssum[128 + row] + ssum[256 + row] + ssum[384 + row];
            float q = ssq[row] + ssq[128 + row] + ssq[256 + row] + ssq[384 + row];
            float m = s * (1.f / 256.f);
            mu[mt][hf] = m;
            rs[mt][hf] = rsqrtf(q * (1.f / 256.f) - m * m + 1e-5f);
        }
    #pragma unroll
    for (int mt = 0; mt < 2; mt++) {
        int rl = r0 + m0 + mt * 16 + (lane >> 2);
        #pragma unroll
        for (int nt = 0; nt < 8; nt++) {
            int c = n0 + nt * 8 + (lane & 3) * 2;
            float2 g2 = *(const float2*)(gp + c);
            float2 b2 = *(const float2*)(bbp + c);
            float4 a = acc[mt][nt];
            float2 o1, o2;
            o1.x = (a.x - mu[mt][0]) * rs[mt][0] * g2.x + b2.x;
            o1.y = (a.y - mu[mt][0]) * rs[mt][0] * g2.y + b2.y;
            o2.x = (a.z - mu[mt][1]) * rs[mt][1] * g2.x + b2.x;
            o2.y = (a.w - mu[mt][1]) * rs[mt][1] * g2.y + b2.y;
            *(float2*)(out + (size_t)rl * 256 + c) = o1;
            *(float2*)(out + (size_t)(rl + 8) * 256 + c) = o2;
        }
    }
}

// ================= attention common math =================
#define ATT_STRIDE 288
#define ATT1_SMEM (WIN * ATT_STRIDE * 4)       // 50688 (QK==V)
#define ATT2_SMEM (2 * WIN * ATT_STRIDE * 4)   // 101376

__device__ __forceinline__ void attn_core(
    const float* sQK, const float* sV, int tid, int b, int s0,
    __half* __restrict__ ath, __half* __restrict__ atl,
    float* __restrict__ scores)
{
    const int sl = tid >> 3, h = tid & 7;
    const int dil = (h < 4) ? 3 : 1;
    const float scale = 0.1767766952966369f;  // 32^-0.5
    const int colb = h * 36;

    float4 q[8];
    {
        const float* qr = sQK + (sl + 6) * ATT_STRIDE + colb;
        #pragma unroll
        for (int j = 0; j < 8; j++) q[j] = *(const float4*)(qr + j * 4);
    }

    float sc[5];
    #pragma unroll
    for (int k = 0; k < 5; k++) {
        const float* kr = sQK + (sl + 6 + (k - 2) * dil) * ATT_STRIDE + colb;
        float d = 0.f;
        #pragma unroll
        for (int j = 0; j < 8; j++) {
            float4 kv = *(const float4*)(kr + j * 4);
            d += q[j].x * kv.x + q[j].y * kv.y + q[j].z * kv.z + q[j].w * kv.w;
        }
        sc[k] = d * scale;
    }
    float mx = sc[0];
    #pragma unroll
    for (int k = 1; k < 5; k++) mx = fmaxf(mx, sc[k]);
    float ex[5], sum = 0.f;
    #pragma unroll
    for (int k = 0; k < 5; k++) { ex[k] = __expf(sc[k] - mx); sum += ex[k]; }
    float inv = 1.f / sum;
    #pragma unroll
    for (int k = 0; k < 5; k++) ex[k] *= inv;

    size_t base = ((size_t)b * Ssz + s0 + sl) * 256 + h * 32;
    const float* v0 = sV + (sl + 6 - 2 * dil) * ATT_STRIDE + colb;
    const int vstep = dil * ATT_STRIDE;
    uint32_t Hw[16], Lw[16];
    #pragma unroll
    for (int j = 0; j < 8; j++) {
        float4 o = make_float4(0.f, 0.f, 0.f, 0.f);
        #pragma unroll
        for (int k = 0; k < 5; k++) {
            float4 vv = *(const float4*)(v0 + k * vstep + j * 4);
            o.x += ex[k] * vv.x; o.y += ex[k] * vv.y;
            o.z += ex[k] * vv.z; o.w += ex[k] * vv.w;
        }
        split2(o.x, o.y, Hw[2*j],   Lw[2*j]);
        split2(o.z, o.w, Hw[2*j+1], Lw[2*j+1]);
    }
    #pragma unroll
    for (int u = 0; u < 4; u++) {
        uint4 vh = make_uint4(Hw[u*4], Hw[u*4+1], Hw[u*4+2], Hw[u*4+3]);
        uint4 vl = make_uint4(Lw[u*4], Lw[u*4+1], Lw[u*4+2], Lw[u*4+3]);
        *(uint4*)((char*)(ath + base) + u * 16) = vh;
        *(uint4*)((char*)(atl + base) + u * 16) = vl;
    }

    if (scores != nullptr) {
        float* sp = scores + (((size_t)b * 8 + h) * Ssz + s0 + sl) * 5;
        #pragma unroll
        for (int k = 0; k < 5; k++) sp[k] = ex[k];
    }
}

// attention, QK == V (blocks 1 & 2 batched via blockIdx.z); single smem tile
__global__ __launch_bounds__(256) void attn_same(
    const float* __restrict__ qk0, const float* __restrict__ qk1,
    __half* __restrict__ ath0, __half* __restrict__ atl0,
    __half* __restrict__ ath1, __half* __restrict__ atl1,
    float* __restrict__ qs)
{
    extern __shared__ float smf[];
    const int chain = blockIdx.z;
    const float* QK = chain ? qk1 : qk0;
    const int b  = blockIdx.y;
    const int s0 = blockIdx.x * 32;
    const int tid = threadIdx.x;

    for (int idx = tid; idx < WIN * 64; idx += 256) {
        int w = idx >> 6, c4 = idx & 63;
        int s = s0 + w - 6;
        float4 vq = make_float4(0.f, 0.f, 0.f, 0.f);
        if (s >= 0 && s < Ssz)
            vq = ((const float4*)QK)[((size_t)b * Ssz + s) * 64 + c4];
        *(float4*)(smf + w * ATT_STRIDE + (c4 >> 3) * 36 + (c4 & 7) * 4) = vq;
    }
    __syncthreads();

    attn_core(smf, smf, tid, b, s0,
              chain ? ath1 : ath0, chain ? atl1 : atl0,
              chain ? qs : nullptr);
}

// attention, QK != V (block 3)
__global__ __launch_bounds__(256) void attn_two(
    const float* __restrict__ QK, const float* __restrict__ V,
    __half* __restrict__ ath, __half* __restrict__ atl)
{
    extern __shared__ float smf[];
    float* sQK = smf;
    float* sV  = smf + WIN * ATT_STRIDE;
    const int b  = blockIdx.y;
    const int s0 = blockIdx.x * 32;
    const int tid = threadIdx.x;

    for (int idx = tid; idx < WIN * 64; idx += 256) {
        int w = idx >> 6, c4 = idx & 63;
        int s = s0 + w - 6;
        float4 vq = make_float4(0.f, 0.f, 0.f, 0.f);
        float4 vv = vq;
        if (s >= 0 && s < Ssz) {
            size_t off = ((size_t)b * Ssz + s) * 64 + c4;
            vq = ((const float4*)QK)[off];
            vv = ((const float4*)V)[off];
        }
        int sc = w * ATT_STRIDE + (c4 >> 3) * 36 + (c4 & 7) * 4;
        *(float4*)(sQK + sc) = vq;
        *(float4*)(sV + sc)  = vv;
    }
    __syncthreads();

    attn_core(sQK, sV, tid, b, s0, ath, atl, nullptr);
}

// ================= launch =================
extern "C" void kernel_launch(void* const* d_in, const int* in_sizes, int n_in,
                              void* d_out, int out_size)
{
    (void)in_sizes; (void)n_in; (void)out_size;
    const float* q_emb = (const float*)d_in[0];
    const float* s_emb = (const float*)d_in[1];
    const float* W_lin = (const float*)d_in[3];  // (3,2,128,128)
    const float* b_lin = (const float*)d_in[4];  // (3,2,128)
    const float* W_out = (const float*)d_in[5];  // (3,256,256)
    const float* b_out = (const float*)d_in[6];  // (3,256)
    const float* ln_g  = (const float*)d_in[7];  // (3,256)
    const float* ln_b  = (const float*)d_in[8];  // (3,256)

    float* outp = (float*)d_out;
    float* z  = outp;
    float* qs = outp + (size_t)BS * 256;

    float *p_qk0, *p_qk1, *p_v, *p_hq, *p_hs;
    __half *p_ath0, *p_atl0, *p_ath1, *p_atl1, *p_wlh, *p_woh;
    cudaGetSymbolAddress((void**)&p_qk0, g_qk0);
    cudaGetSymbolAddress((void**)&p_qk1, g_qk1);
    cudaGetSymbolAddress((void**)&p_v,   g_v);
    cudaGetSymbolAddress((void**)&p_hq,  g_hq);
    cudaGetSymbolAddress((void**)&p_hs,  g_hs);
    cudaGetSymbolAddress((void**)&p_ath0, g_ath0);
    cudaGetSymbolAddress((void**)&p_atl0, g_atl0);
    cudaGetSymbolAddress((void**)&p_ath1, g_ath1);
    cudaGetSymbolAddress((void**)&p_atl1, g_atl1);
    cudaGetSymbolAddress((void**)&p_wlh, g_wlh);
    cudaGetSymbolAddress((void**)&p_woh, g_woh);

    const int smemP  = (int)PR_SMEM;
    const int smemO  = (int)OLS_SMEM;
    const int smemA1 = ATT1_SMEM;
    const int smemA2 = ATT2_SMEM;
    cudaFuncSetAttribute(proj_mma,  cudaFuncAttributeMaxDynamicSharedMemorySize, smemP);
    cudaFuncSetAttribute(outln_mma, cudaFuncAttributeMaxDynamicSharedMemorySize, smemO);
    cudaFuncSetAttribute(attn_same, cudaFuncAttributeMaxDynamicSharedMemorySize, smemA1);
    cudaFuncSetAttribute(attn_two,  cudaFuncAttributeMaxDynamicSharedMemorySize, smemA2);

    split_w<<<768, 256>>>(W_lin, W_out, p_wlh, p_woh);

    // ---- blocks 1 & 2, batched ----
    proj_mma<<<dim3(BS/128, 2, 2), 512, smemP>>>(
        q_emb, s_emb, p_wlh, 32768, b_lin, 256, p_qk0, p_qk1);
    attn_same<<<dim3(Ssz/32, Bsz, 2), 256, smemA1>>>(
        p_qk0, p_qk1, p_ath0, p_atl0, p_ath1, p_atl1, qs);
    outln_mma<<<dim3(BS/128, 2), 512, smemO>>>(
        p_ath0, p_atl0, p_ath1, p_atl1, p_woh, 65536,
        b_out, q_emb, s_emb, ln_g, ln_b, 256, p_hq, p_hs);

    // ---- block 3 ----
    proj_mma<<<dim3(BS/128, 2, 2), 512, smemP>>>(
        p_hq, p_hs, p_wlh + 65536, 0, b_lin + 512, 0, p_qk0, p_v);
    attn_two<<<dim3(Ssz/32, Bsz), 256, smemA2>>>(p_qk0, p_v, p_ath0, p_atl0);
    outln_mma<<<dim3(BS/128, 1), 512, smemO>>>(
        p_ath0, p_atl0, p_ath0, p_atl0, p_woh + 131072, 0,
        b_out + 512, p_hq, p_hq, ln_g + 512, ln_b + 512, 0, z, z);
}

// round 8
// speedup vs baseline: 3.9695x; 1.1879x over previous
#include <cuda_runtime.h>
#include <cuda_fp16.h>
#include <cstdint>

#define Bsz 32
#define Ssz 2048
#define BS (Bsz*Ssz)   // 65536 rows
#define WIN 44         // attention smem window rows (32 + 2*6 halo)

// ---------------- scratch (device globals; no allocation) ----------------
__device__ float g_qk0[(size_t)BS*256];
__device__ float g_qk1[(size_t)BS*256];
__device__ float g_v  [(size_t)BS*256];
__device__ float g_hq [(size_t)BS*256];
__device__ float g_hs [(size_t)BS*256];
__device__ __half g_ath0[(size_t)BS*256];
__device__ __half g_ath1[(size_t)BS*256];
__device__ __half g_wlh[3*2*128*128];
__device__ __half g_woh[3*256*256];

// ================= helpers =================
__device__ __forceinline__ uint32_t smem_u32(const void* p) {
    uint32_t a;
    asm("{ .reg .u64 t; cvta.to.shared.u64 t, %1; cvt.u32.u64 %0, t; }"
        : "=r"(a) : "l"(p));
    return a;
}
__device__ __forceinline__ void ldsm4(uint32_t r[4], uint32_t addr) {
    asm volatile("ldmatrix.sync.aligned.m8n8.x4.shared.b16 {%0,%1,%2,%3}, [%4];"
                 : "=r"(r[0]), "=r"(r[1]), "=r"(r[2]), "=r"(r[3]) : "r"(addr));
}
__device__ __forceinline__ void mma_f16(float4& c, const uint32_t a[4],
                                        uint32_t b0, uint32_t b1) {
    asm volatile(
        "mma.sync.aligned.m16n8k16.row.col.f32.f16.f16.f32 "
        "{%0,%1,%2,%3}, {%4,%5,%6,%7}, {%8,%9}, {%0,%1,%2,%3};"
        : "+f"(c.x), "+f"(c.y), "+f"(c.z), "+f"(c.w)
        : "r"(a[0]), "r"(a[1]), "r"(a[2]), "r"(a[3]), "r"(b0), "r"(b1));
}
__device__ __forceinline__ void cp16(uint32_t dst, const void* src) {
    asm volatile("cp.async.cg.shared.global [%0], [%1], 16;"
                 :: "r"(dst), "l"(src) : "memory");
}

// Fill a 128-row x 64-col chunk (fp32 src) into fp16 smem, row stride 72 halves.
__device__ __forceinline__ void fill_hi(const float* __restrict__ src, int stride,
                                        uint32_t* __restrict__ hi, int tid) {
    #pragma unroll
    for (int it = 0; it < 8; it++) {
        int idx = tid + it * 512;
        int row = idx >> 5, c2 = idx & 31;
        float2 v = *(const float2*)(src + (size_t)row * stride + c2 * 2);
        __half2 h = __floats2half2_rn(v.x, v.y);
        hi[row * 36 + c2] = *reinterpret_cast<uint32_t*>(&h);
    }
}

// ================= weight fp16 prep =================
__global__ void split_w(const float* __restrict__ Wl, const float* __restrict__ Wo,
                        __half* __restrict__ wlh, __half* __restrict__ woh)
{
    int i = blockIdx.x * 256 + threadIdx.x;
    if (i < 3*2*128*128) wlh[i] = __float2half_rn(Wl[i]);
    if (i < 3*256*256)   woh[i] = __float2half_rn(Wo[i]);
}

// ================= projection GEMM (single-term fp16, batched 2 chains) =================
#define PR_BIAS 67584u
#define PR_SMEM 68096u

__global__ __launch_bounds__(512) void proj_mma(
    const float* __restrict__ x0, const float* __restrict__ x1,
    const __half* __restrict__ whi, int wstep,
    const float* __restrict__ bias, int bstep,
    float* __restrict__ out0, float* __restrict__ out1)
{
    extern __shared__ __align__(16) char sm[];
    uint32_t* Ahi = (uint32_t*)(sm);
    char* Bhi = sm + 18432;
    float* sbias  = (float*)(sm + PR_BIAS);
    float* stg    = (float*)sm;   // overlaps operands post-GEMM

    const int chain = blockIdx.z;
    const float* x = chain ? x1 : x0;
    float* out = chain ? out1 : out0;
    const int branch = blockIdx.y;
    const int r0 = blockIdx.x * 128;
    const int tid = threadIdx.x, lane = tid & 31, wid = tid >> 5;
    const int m0 = (wid >> 2) * 32, n0 = (wid & 3) * 32;

    const float* bp = bias + chain * bstep + branch * 128;
    if (tid < 128) sbias[tid] = bp[tid];

    const uint32_t sA = smem_u32(Ahi), sB = smem_u32(Bhi);
    const int a_row = lane & 15, a_kh = (lane >> 4) << 3;
    const int b_n = (lane & 7) + ((lane >> 4) << 3);
    const int b_kh = ((lane >> 3) & 1) << 3;

    float4 acc[2][4];
    #pragma unroll
    for (int i = 0; i < 2; i++)
        #pragma unroll
        for (int j = 0; j < 4; j++) acc[i][j] = make_float4(0.f, 0.f, 0.f, 0.f);

    const float* xp = x + (size_t)r0 * 256 + branch * 128;
    const __half* whb = whi + (size_t)chain * wstep + (size_t)branch * 128 * 128;

    uint32_t aAddr[2], bAddr[2];
    aAddr[0] = sA + ((m0 + a_row) * 72 + a_kh) * 2;
    aAddr[1] = sA + ((m0 + 16 + a_row) * 72 + a_kh) * 2;
    bAddr[0] = sB + ((n0 + b_n) * 72 + b_kh) * 2;
    bAddr[1] = sB + ((n0 + 16 + b_n) * 72 + b_kh) * 2;

    for (int kc = 0; kc < 128; kc += 64) {
        fill_hi(xp + kc, 256, Ahi, tid);
        #pragma unroll
        for (int it = 0; it < 2; it++) {
            int idx = tid + it * 512;
            int row = idx >> 3, u = idx & 7;
            *(uint4*)(Bhi + row * 144 + u * 16) =
                *(const uint4*)(whb + row * 128 + kc + u * 8);
        }
        __syncthreads();
        #pragma unroll
        for (int ks = 0; ks < 4; ks++) {
            uint32_t ah[2][4], bh[2][4];
            #pragma unroll
            for (int mt = 0; mt < 2; mt++) ldsm4(ah[mt], aAddr[mt] + ks * 32);
            #pragma unroll
            for (int bt = 0; bt < 2; bt++) ldsm4(bh[bt], bAddr[bt] + ks * 32);
            #pragma unroll
            for (int mt = 0; mt < 2; mt++)
                #pragma unroll
                for (int bt = 0; bt < 2; bt++)
                    #pragma unroll
                    for (int sub = 0; sub < 2; sub++)
                        mma_f16(acc[mt][bt * 2 + sub], ah[mt],
                                bh[bt][sub*2], bh[bt][sub*2+1]);
        }
        __syncthreads();
    }

    #pragma unroll
    for (int mt = 0; mt < 2; mt++) {
        int rb = m0 + mt * 16 + (lane >> 2);
        #pragma unroll
        for (int nt = 0; nt < 4; nt++) {
            int j = n0 + nt * 8 + (lane & 3) * 2;
            int p0 = ((j & 31) << 2) + (j >> 5);
            int p1 = (((j + 1) & 31) << 2) + ((j + 1) >> 5);
            float4 a = acc[mt][nt];
            stg[rb * 132 + p0]       = a.x + sbias[j];
            stg[rb * 132 + p1]       = a.y + sbias[j + 1];
            stg[(rb + 8) * 132 + p0] = a.z + sbias[j];
            stg[(rb + 8) * 132 + p1] = a.w + sbias[j + 1];
        }
    }
    __syncthreads();
    #pragma unroll
    for (int it = 0; it < 8; it++) {
        int idx = tid + it * 512;
        int row = idx >> 5, q = idx & 31;
        float4 v = *(const float4*)(stg + row * 132 + q * 4);
        *(float4*)(out + (size_t)(r0 + row) * 256 + branch * 128 + q * 4) = v;
    }
}

// ================= out-proj + bias + residual + LayerNorm (single-term fp16) =================
#define OLS_STAGE 55296u
#define OLS_SUM   110592u
#define OLS_SQ    112640u
#define OLS_SMEM  114688u

__global__ __launch_bounds__(512) void outln_mma(
    const __half* __restrict__ A0h, const __half* __restrict__ A1h,
    const __half* __restrict__ Whi, int wstep,
    const float* __restrict__ bo, const float* __restrict__ xr0,
    const float* __restrict__ xr1,
    const float* __restrict__ g, const float* __restrict__ bb, int pstep,
    float* __restrict__ out0, float* __restrict__ out1)
{
    extern __shared__ __align__(16) char sm[];
    const int chain = blockIdx.y;
    const __half* Ahi = chain ? A1h : A0h;
    const __half* Wp  = Whi + (size_t)chain * wstep;
    const float* xres = chain ? xr1 : xr0;
    const float* bop = bo + chain * pstep;
    const float* gp  = g  + chain * pstep;
    const float* bbp = bb + chain * pstep;
    float* out = chain ? out1 : out0;

    const int r0 = blockIdx.x * 128;
    const int tid = threadIdx.x, lane = tid & 31, wid = tid >> 5;
    const int m0 = (wid >> 2) * 32, n0 = (wid & 3) * 64;
    const uint32_t sb = smem_u32(sm);

    auto load_chunk = [&](int kc) {
        uint32_t st = sb + (uint32_t)(kc & 1) * OLS_STAGE;
        const __half* ah = Ahi + (size_t)r0 * 256 + kc * 64;
        const __half* wh = Wp + kc * 64;
        #pragma unroll
        for (int it = 0; it < 2; it++) {
            int idx = tid + it * 512;
            int row = idx >> 3, u = idx & 7;
            cp16(st + row * 144 + u * 16, ah + (size_t)row * 256 + u * 8);
        }
        #pragma unroll
        for (int it = 0; it < 4; it++) {
            int idx = tid + it * 512;
            int row = idx >> 3, u = idx & 7;
            cp16(st + 18432u + row * 144 + u * 16, wh + (size_t)row * 256 + u * 8);
        }
        asm volatile("cp.async.commit_group;" ::: "memory");
    };

    const int a_row = lane & 15, a_kh = (lane >> 4) << 3;
    const int b_n = (lane & 7) + ((lane >> 4) << 3);
    const int b_kh = ((lane >> 3) & 1) << 3;
    const uint32_t aOff = ((m0 + a_row) * 72 + a_kh) * 2;
    const uint32_t bOff = 18432u + ((n0 + b_n) * 72 + b_kh) * 2;

    float4 acc[2][8];
    #pragma unroll
    for (int i = 0; i < 2; i++)
        #pragma unroll
        for (int j = 0; j < 8; j++) acc[i][j] = make_float4(0.f, 0.f, 0.f, 0.f);

    load_chunk(0);
    #pragma unroll 1
    for (int kc = 0; kc < 4; kc++) {
        if (kc < 3) {
            load_chunk(kc + 1);
            asm volatile("cp.async.wait_group 1;" ::: "memory");
        } else {
            asm volatile("cp.async.wait_group 0;" ::: "memory");
        }
        __syncthreads();
        uint32_t st = sb + (uint32_t)(kc & 1) * OLS_STAGE;
        uint32_t aB = st + aOff, bB = st + bOff;
        #pragma unroll
        for (int ks = 0; ks < 4; ks++) {
            uint32_t ah[2][4];
            ldsm4(ah[0], aB + ks * 32);
            ldsm4(ah[1], aB + 2304 + ks * 32);
            #pragma unroll
            for (int nb = 0; nb < 4; nb++) {
                uint32_t bh[4];
                ldsm4(bh, bB + nb * 2304 + ks * 32);
                #pragma unroll
                for (int mt = 0; mt < 2; mt++)
                    #pragma unroll
                    for (int sub = 0; sub < 2; sub++)
                        mma_f16(acc[mt][nb * 2 + sub], ah[mt],
                                bh[sub*2], bh[sub*2+1]);
            }
        }
        __syncthreads();
    }

    float sums[2][2] = {{0.f,0.f},{0.f,0.f}}, sqs[2][2] = {{0.f,0.f},{0.f,0.f}};
    #pragma unroll
    for (int mt = 0; mt < 2; mt++) {
        int rl = r0 + m0 + mt * 16 + (lane >> 2);
        #pragma unroll
        for (int nt = 0; nt < 8; nt++) {
            int c = n0 + nt * 8 + (lane & 3) * 2;
            float2 bo2 = *(const float2*)(bop + c);
            float2 xl = *(const float2*)(xres + (size_t)rl * 256 + c);
            float2 xh = *(const float2*)(xres + (size_t)(rl + 8) * 256 + c);
            float4& a = acc[mt][nt];
            a.x += bo2.x + xl.x; a.y += bo2.y + xl.y;
            a.z += bo2.x + xh.x; a.w += bo2.y + xh.y;
            sums[mt][0] += a.x + a.y; sqs[mt][0] += a.x*a.x + a.y*a.y;
            sums[mt][1] += a.z + a.w; sqs[mt][1] += a.z*a.z + a.w*a.w;
        }
    }
    #pragma unroll
    for (int mt = 0; mt < 2; mt++)
        #pragma unroll
        for (int hf = 0; hf < 2; hf++) {
            sums[mt][hf] += __shfl_xor_sync(0xffffffffu, sums[mt][hf], 1);
            sums[mt][hf] += __shfl_xor_sync(0xffffffffu, sums[mt][hf], 2);
            sqs[mt][hf]  += __shfl_xor_sync(0xffffffffu, sqs[mt][hf], 1);
            sqs[mt][hf]  += __shfl_xor_sync(0xffffffffu, sqs[mt][hf], 2);
        }
    float* ssum = (float*)(sm + OLS_SUM);
    float* ssq  = (float*)(sm + OLS_SQ);
    if ((lane & 3) == 0) {
        #pragma unroll
        for (int mt = 0; mt < 2; mt++)
            #pragma unroll
            for (int hf = 0; hf < 2; hf++) {
                int row = m0 + mt * 16 + hf * 8 + (lane >> 2);
                ssum[(wid & 3) * 128 + row] = sums[mt][hf];
                ssq [(wid & 3) * 128 + row] = sqs[mt][hf];
            }
    }
    __syncthreads();
    float mu[2][2], rs[2][2];
    #pragma unroll
    for (int mt = 0; mt < 2; mt++)
        #pragma unroll
        for (int hf = 0; hf < 2; hf++) {
            int row = m0 + mt * 16 + hf * 8 + (lane >> 2);
            float s = ssum[row] + ssum[128 + row] + ssum[256 + row] + ssum[384 + row];
            float q = ssq[row] + ssq[128 + row] + ssq[256 + row] + ssq[384 + row];
            float m = s * (1.f / 256.f);
            mu[mt][hf] = m;
            rs[mt][hf] = rsqrtf(q * (1.f / 256.f) - m * m + 1e-5f);
        }
    #pragma unroll
    for (int mt = 0; mt < 2; mt++) {
        int rl = r0 + m0 + mt * 16 + (lane >> 2);
        #pragma unroll
        for (int nt = 0; nt < 8; nt++) {
            int c = n0 + nt * 8 + (lane & 3) * 2;
            float2 g2 = *(const float2*)(gp + c);
            float2 b2 = *(const float2*)(bbp + c);
            float4 a = acc[mt][nt];
            float2 o1, o2;
            o1.x = (a.x - mu[mt][0]) * rs[mt][0] * g2.x + b2.x;
            o1.y = (a.y - mu[mt][0]) * rs[mt][0] * g2.y + b2.y;
            o2.x = (a.z - mu[mt][1]) * rs[mt][1] * g2.x + b2.x;
            o2.y = (a.w - mu[mt][1]) * rs[mt][1] * g2.y + b2.y;
            *(float2*)(out + (size_t)rl * 256 + c) = o1;
            *(float2*)(out + (size_t)(rl + 8) * 256 + c) = o2;
        }
    }
}

// ================= attention common math =================
#define ATT_STRIDE 288
#define ATT1_SMEM (WIN * ATT_STRIDE * 4)       // 50688 (QK==V)
#define ATT2_SMEM (2 * WIN * ATT_STRIDE * 4)   // 101376

__device__ __forceinline__ void attn_core(
    const float* sQK, const float* sV, int tid, int b, int s0,
    __half* __restrict__ ath, float* __restrict__ scores)
{
    const int sl = tid >> 3, h = tid & 7;
    const int dil = (h < 4) ? 3 : 1;
    const float scale = 0.1767766952966369f;  // 32^-0.5
    const int colb = h * 36;

    float4 q[8];
    {
        const float* qr = sQK + (sl + 6) * ATT_STRIDE + colb;
        #pragma unroll
        for (int j = 0; j < 8; j++) q[j] = *(const float4*)(qr + j * 4);
    }

    float sc[5];
    #pragma unroll
    for (int k = 0; k < 5; k++) {
        const float* kr = sQK + (sl + 6 + (k - 2) * dil) * ATT_STRIDE + colb;
        float d = 0.f;
        #pragma unroll
        for (int j = 0; j < 8; j++) {
            float4 kv = *(const float4*)(kr + j * 4);
            d += q[j].x * kv.x + q[j].y * kv.y + q[j].z * kv.z + q[j].w * kv.w;
        }
        sc[k] = d * scale;
    }
    float mx = sc[0];
    #pragma unroll
    for (int k = 1; k < 5; k++) mx = fmaxf(mx, sc[k]);
    float ex[5], sum = 0.f;
    #pragma unroll
    for (int k = 0; k < 5; k++) { ex[k] = __expf(sc[k] - mx); sum += ex[k]; }
    float inv = 1.f / sum;
    #pragma unroll
    for (int k = 0; k < 5; k++) ex[k] *= inv;

    size_t base = ((size_t)b * Ssz + s0 + sl) * 256 + h * 32;
    const float* v0 = sV + (sl + 6 - 2 * dil) * ATT_STRIDE + colb;
    const int vstep = dil * ATT_STRIDE;
    uint32_t Hw[16];
    #pragma unroll
    for (int j = 0; j < 8; j++) {
        float4 o = make_float4(0.f, 0.f, 0.f, 0.f);
        #pragma unroll
        for (int k = 0; k < 5; k++) {
            float4 vv = *(const float4*)(v0 + k * vstep + j * 4);
            o.x += ex[k] * vv.x; o.y += ex[k] * vv.y;
            o.z += ex[k] * vv.z; o.w += ex[k] * vv.w;
        }
        __half2 h0 = __floats2half2_rn(o.x, o.y);
        __half2 h1 = __floats2half2_rn(o.z, o.w);
        Hw[2*j]   = *reinterpret_cast<uint32_t*>(&h0);
        Hw[2*j+1] = *reinterpret_cast<uint32_t*>(&h1);
    }
    #pragma unroll
    for (int u = 0; u < 4; u++) {
        uint4 vh = make_uint4(Hw[u*4], Hw[u*4+1], Hw[u*4+2], Hw[u*4+3]);
        *(uint4*)((char*)(ath + base) + u * 16) = vh;
    }

    if (scores != nullptr) {
        float* sp = scores + (((size_t)b * 8 + h) * Ssz + s0 + sl) * 5;
        #pragma unroll
        for (int k = 0; k < 5; k++) sp[k] = ex[k];
    }
}

// attention, QK == V (blocks 1 & 2 batched via blockIdx.z); single smem tile
__global__ __launch_bounds__(256) void attn_same(
    const float* __restrict__ qk0, const float* __restrict__ qk1,
    __half* __restrict__ ath0, __half* __restrict__ ath1,
    float* __restrict__ qs)
{
    extern __shared__ float smf[];
    const int chain = blockIdx.z;
    const float* QK = chain ? qk1 : qk0;
    const int b  = blockIdx.y;
    const int s0 = blockIdx.x * 32;
    const int tid = threadIdx.x;

    for (int idx = tid; idx < WIN * 64; idx += 256) {
        int w = idx >> 6, c4 = idx & 63;
        int s = s0 + w - 6;
        float4 vq = make_float4(0.f, 0.f, 0.f, 0.f);
        if (s >= 0 && s < Ssz)
            vq = ((const float4*)QK)[((size_t)b * Ssz + s) * 64 + c4];
        *(float4*)(smf + w * ATT_STRIDE + (c4 >> 3) * 36 + (c4 & 7) * 4) = vq;
    }
    __syncthreads();

    attn_core(smf, smf, tid, b, s0, chain ? ath1 : ath0, chain ? qs : nullptr);
}

// attention, QK != V (block 3)
__global__ __launch_bounds__(256) void attn_two(
    const float* __restrict__ QK, const float* __restrict__ V,
    __half* __restrict__ ath)
{
    extern __shared__ float smf[];
    float* sQK = smf;
    float* sV  = smf + WIN * ATT_STRIDE;
    const int b  = blockIdx.y;
    const int s0 = blockIdx.x * 32;
    const int tid = threadIdx.x;

    for (int idx = tid; idx < WIN * 64; idx += 256) {
        int w = idx >> 6, c4 = idx & 63;
        int s = s0 + w - 6;
        float4 vq = make_float4(0.f, 0.f, 0.f, 0.f);
        float4 vv = vq;
        if (s >= 0 && s < Ssz) {
            size_t off = ((size_t)b * Ssz + s) * 64 + c4;
            vq = ((const float4*)QK)[off];
            vv = ((const float4*)V)[off];
        }
        int sc = w * ATT_STRIDE + (c4 >> 3) * 36 + (c4 & 7) * 4;
        *(float4*)(sQK + sc) = vq;
        *(float4*)(sV + sc)  = vv;
    }
    __syncthreads();

    attn_core(sQK, sV, tid, b, s0, ath, nullptr);
}

// ================= launch =================
extern "C" void kernel_launch(void* const* d_in, const int* in_sizes, int n_in,
                              void* d_out, int out_size)
{
    (void)in_sizes; (void)n_in; (void)out_size;
    const float* q_emb = (const float*)d_in[0];
    const float* s_emb = (const float*)d_in[1];
    const float* W_lin = (const float*)d_in[3];  // (3,2,128,128)
    const float* b_lin = (const float*)d_in[4];  // (3,2,128)
    const float* W_out = (const float*)d_in[5];  // (3,256,256)
    const float* b_out = (const float*)d_in[6];  // (3,256)
    const float* ln_g  = (const float*)d_in[7];  // (3,256)
    const float* ln_b  = (const float*)d_in[8];  // (3,256)

    float* outp = (float*)d_out;
    float* z  = outp;
    float* qs = outp + (size_t)BS * 256;

    float *p_qk0, *p_qk1, *p_v, *p_hq, *p_hs;
    __half *p_ath0, *p_ath1, *p_wlh, *p_woh;
    cudaGetSymbolAddress((void**)&p_qk0, g_qk0);
    cudaGetSymbolAddress((void**)&p_qk1, g_qk1);
    cudaGetSymbolAddress((void**)&p_v,   g_v);
    cudaGetSymbolAddress((void**)&p_hq,  g_hq);
    cudaGetSymbolAddress((void**)&p_hs,  g_hs);
    cudaGetSymbolAddress((void**)&p_ath0, g_ath0);
    cudaGetSymbolAddress((void**)&p_ath1, g_ath1);
    cudaGetSymbolAddress((void**)&p_wlh, g_wlh);
    cudaGetSymbolAddress((void**)&p_woh, g_woh);

    const int smemP  = (int)PR_SMEM;
    const int smemO  = (int)OLS_SMEM;
    const int smemA1 = ATT1_SMEM;
    const int smemA2 = ATT2_SMEM;
    cudaFuncSetAttribute(proj_mma,  cudaFuncAttributeMaxDynamicSharedMemorySize, smemP);
    cudaFuncSetAttribute(outln_mma, cudaFuncAttributeMaxDynamicSharedMemorySize, smemO);
    cudaFuncSetAttribute(attn_same, cudaFuncAttributeMaxDynamicSharedMemorySize, smemA1);
    cudaFuncSetAttribute(attn_two,  cudaFuncAttributeMaxDynamicSharedMemorySize, smemA2);

    split_w<<<768, 256>>>(W_lin, W_out, p_wlh, p_woh);

    // ---- blocks 1 & 2, batched ----
    proj_mma<<<dim3(BS/128, 2, 2), 512, smemP>>>(
        q_emb, s_emb, p_wlh, 32768, b_lin, 256, p_qk0, p_qk1);
    attn_same<<<dim3(Ssz/32, Bsz, 2), 256, smemA1>>>(
        p_qk0, p_qk1, p_ath0, p_ath1, qs);
    outln_mma<<<dim3(BS/128, 2), 512, smemO>>>(
        p_ath0, p_ath1, p_woh, 65536,
        b_out, q_emb, s_emb, ln_g, ln_b, 256, p_hq, p_hs);

    // ---- block 3 ----
    proj_mma<<<dim3(BS/128, 2, 2), 512, smemP>>>(
        p_hq, p_hs, p_wlh + 65536, 0, b_lin + 512, 0, p_qk0, p_v);
    attn_two<<<dim3(Ssz/32, Bsz), 256, smemA2>>>(p_qk0, p_v, p_ath0);
    outln_mma<<<dim3(BS/128, 1), 512, smemO>>>(
        p_ath0, p_ath0, p_woh + 131072, 0,
        b_out + 512, p_hq, p_hq, ln_g + 512, ln_b + 512, 0, z, z);
}

// round 9
// speedup vs baseline: 4.1647x; 1.0492x over previous
#include <cuda_runtime.h>
#include <cuda_fp16.h>
#include <cstdint>

#define Bsz 32
#define Ssz 2048
#define BS (Bsz*Ssz)   // 65536 rows
#define WIN 44         // attention smem window rows (32 + 2*6 halo)

// ---------------- scratch (device globals; no allocation) ----------------
__device__ __half g_qk0[(size_t)BS*256];
__device__ __half g_qk1[(size_t)BS*256];
__device__ __half g_v  [(size_t)BS*256];
__device__ float  g_hq [(size_t)BS*256];
__device__ float  g_hs [(size_t)BS*256];
__device__ __half g_ath0[(size_t)BS*256];
__device__ __half g_ath1[(size_t)BS*256];
__device__ __half g_wlh[3*2*128*128];
__device__ __half g_woh[3*256*256];

// ================= helpers =================
__device__ __forceinline__ uint32_t smem_u32(const void* p) {
    uint32_t a;
    asm("{ .reg .u64 t; cvta.to.shared.u64 t, %1; cvt.u32.u64 %0, t; }"
        : "=r"(a) : "l"(p));
    return a;
}
__device__ __forceinline__ void ldsm4(uint32_t r[4], uint32_t addr) {
    asm volatile("ldmatrix.sync.aligned.m8n8.x4.shared.b16 {%0,%1,%2,%3}, [%4];"
                 : "=r"(r[0]), "=r"(r[1]), "=r"(r[2]), "=r"(r[3]) : "r"(addr));
}
__device__ __forceinline__ void mma_f16(float4& c, const uint32_t a[4],
                                        uint32_t b0, uint32_t b1) {
    asm volatile(
        "mma.sync.aligned.m16n8k16.row.col.f32.f16.f16.f32 "
        "{%0,%1,%2,%3}, {%4,%5,%6,%7}, {%8,%9}, {%0,%1,%2,%3};"
        : "+f"(c.x), "+f"(c.y), "+f"(c.z), "+f"(c.w)
        : "r"(a[0]), "r"(a[1]), "r"(a[2]), "r"(a[3]), "r"(b0), "r"(b1));
}
__device__ __forceinline__ void cp16(uint32_t dst, const void* src) {
    asm volatile("cp.async.cg.shared.global [%0], [%1], 16;"
                 :: "r"(dst), "l"(src) : "memory");
}

// Fill a 128-row x 64-col chunk (fp32 src) into fp16 smem, row stride 72 halves.
__device__ __forceinline__ void fill_hi(const float* __restrict__ src, int stride,
                                        uint32_t* __restrict__ hi, int tid) {
    #pragma unroll
    for (int it = 0; it < 8; it++) {
        int idx = tid + it * 512;
        int row = idx >> 5, c2 = idx & 31;
        float2 v = *(const float2*)(src + (size_t)row * stride + c2 * 2);
        __half2 h = __floats2half2_rn(v.x, v.y);
        hi[row * 36 + c2] = *reinterpret_cast<uint32_t*>(&h);
    }
}

// ================= weight fp16 prep =================
__global__ void split_w(const float* __restrict__ Wl, const float* __restrict__ Wo,
                        __half* __restrict__ wlh, __half* __restrict__ woh)
{
    int i = blockIdx.x * 256 + threadIdx.x;
    if (i < 3*2*128*128) wlh[i] = __float2half_rn(Wl[i]);
    if (i < 3*256*256)   woh[i] = __float2half_rn(Wo[i]);
}

// ================= projection GEMM (fp16 out, batched 2 chains) =================
#define PR_BIAS 67584u
#define PR_SMEM 68096u

__global__ __launch_bounds__(512) void proj_mma(
    const float* __restrict__ x0, const float* __restrict__ x1,
    const __half* __restrict__ whi, int wstep,
    const float* __restrict__ bias, int bstep,
    __half* __restrict__ out0, __half* __restrict__ out1)
{
    extern __shared__ __align__(16) char sm[];
    uint32_t* Ahi = (uint32_t*)(sm);
    char* Bhi = sm + 18432;
    float* sbias  = (float*)(sm + PR_BIAS);
    float* stg    = (float*)sm;   // overlaps operands post-GEMM

    const int chain = blockIdx.z;
    const float* x = chain ? x1 : x0;
    __half* out = chain ? out1 : out0;
    const int branch = blockIdx.y;
    const int r0 = blockIdx.x * 128;
    const int tid = threadIdx.x, lane = tid & 31, wid = tid >> 5;
    const int m0 = (wid >> 2) * 32, n0 = (wid & 3) * 32;

    const float* bp = bias + chain * bstep + branch * 128;
    if (tid < 128) sbias[tid] = bp[tid];

    const uint32_t sA = smem_u32(Ahi), sB = smem_u32(Bhi);
    const int a_row = lane & 15, a_kh = (lane >> 4) << 3;
    const int b_n = (lane & 7) + ((lane >> 4) << 3);
    const int b_kh = ((lane >> 3) & 1) << 3;

    float4 acc[2][4];
    #pragma unroll
    for (int i = 0; i < 2; i++)
        #pragma unroll
        for (int j = 0; j < 4; j++) acc[i][j] = make_float4(0.f, 0.f, 0.f, 0.f);

    const float* xp = x + (size_t)r0 * 256 + branch * 128;
    const __half* whb = whi + (size_t)chain * wstep + (size_t)branch * 128 * 128;

    uint32_t aAddr[2], bAddr[2];
    aAddr[0] = sA + ((m0 + a_row) * 72 + a_kh) * 2;
    aAddr[1] = sA + ((m0 + 16 + a_row) * 72 + a_kh) * 2;
    bAddr[0] = sB + ((n0 + b_n) * 72 + b_kh) * 2;
    bAddr[1] = sB + ((n0 + 16 + b_n) * 72 + b_kh) * 2;

    for (int kc = 0; kc < 128; kc += 64) {
        fill_hi(xp + kc, 256, Ahi, tid);
        #pragma unroll
        for (int it = 0; it < 2; it++) {
            int idx = tid + it * 512;
            int row = idx >> 3, u = idx & 7;
            *(uint4*)(Bhi + row * 144 + u * 16) =
                *(const uint4*)(whb + row * 128 + kc + u * 8);
        }
        __syncthreads();
        #pragma unroll
        for (int ks = 0; ks < 4; ks++) {
            uint32_t ah[2][4], bh[2][4];
            #pragma unroll
            for (int mt = 0; mt < 2; mt++) ldsm4(ah[mt], aAddr[mt] + ks * 32);
            #pragma unroll
            for (int bt = 0; bt < 2; bt++) ldsm4(bh[bt], bAddr[bt] + ks * 32);
            #pragma unroll
            for (int mt = 0; mt < 2; mt++)
                #pragma unroll
                for (int bt = 0; bt < 2; bt++)
                    #pragma unroll
                    for (int sub = 0; sub < 2; sub++)
                        mma_f16(acc[mt][bt * 2 + sub], ah[mt],
                                bh[bt][sub*2], bh[bt][sub*2+1]);
        }
        __syncthreads();
    }

    #pragma unroll
    for (int mt = 0; mt < 2; mt++) {
        int rb = m0 + mt * 16 + (lane >> 2);
        #pragma unroll
        for (int nt = 0; nt < 4; nt++) {
            int j = n0 + nt * 8 + (lane & 3) * 2;
            int p0 = ((j & 31) << 2) + (j >> 5);
            int p1 = (((j + 1) & 31) << 2) + ((j + 1) >> 5);
            float4 a = acc[mt][nt];
            stg[rb * 132 + p0]       = a.x + sbias[j];
            stg[rb * 132 + p1]       = a.y + sbias[j + 1];
            stg[(rb + 8) * 132 + p0] = a.z + sbias[j];
            stg[(rb + 8) * 132 + p1] = a.w + sbias[j + 1];
        }
    }
    __syncthreads();
    #pragma unroll
    for (int it = 0; it < 8; it++) {
        int idx = tid + it * 512;
        int row = idx >> 5, q = idx & 31;
        float4 v = *(const float4*)(stg + row * 132 + q * 4);
        __half2 h0 = __floats2half2_rn(v.x, v.y);
        __half2 h1 = __floats2half2_rn(v.z, v.w);
        uint2 u = make_uint2(*reinterpret_cast<uint32_t*>(&h0),
                             *reinterpret_cast<uint32_t*>(&h1));
        *(uint2*)(out + (size_t)(r0 + row) * 256 + branch * 128 + q * 4) = u;
    }
}

// ================= out-proj + bias + residual + LayerNorm (single-term fp16) =================
#define OLS_STAGE 55296u
#define OLS_SUM   110592u
#define OLS_SQ    112640u
#define OLS_SMEM  114688u

__global__ __launch_bounds__(512) void outln_mma(
    const __half* __restrict__ A0h, const __half* __restrict__ A1h,
    const __half* __restrict__ Whi, int wstep,
    const float* __restrict__ bo, const float* __restrict__ xr0,
    const float* __restrict__ xr1,
    const float* __restrict__ g, const float* __restrict__ bb, int pstep,
    float* __restrict__ out0, float* __restrict__ out1)
{
    extern __shared__ __align__(16) char sm[];
    const int chain = blockIdx.y;
    const __half* Ahi = chain ? A1h : A0h;
    const __half* Wp  = Whi + (size_t)chain * wstep;
    const float* xres = chain ? xr1 : xr0;
    const float* bop = bo + chain * pstep;
    const float* gp  = g  + chain * pstep;
    const float* bbp = bb + chain * pstep;
    float* out = chain ? out1 : out0;

    const int r0 = blockIdx.x * 128;
    const int tid = threadIdx.x, lane = tid & 31, wid = tid >> 5;
    const int m0 = (wid >> 2) * 32, n0 = (wid & 3) * 64;
    const uint32_t sb = smem_u32(sm);

    auto load_chunk = [&](int kc) {
        uint32_t st = sb + (uint32_t)(kc & 1) * OLS_STAGE;
        const __half* ah = Ahi + (size_t)r0 * 256 + kc * 64;
        const __half* wh = Wp + kc * 64;
        #pragma unroll
        for (int it = 0; it < 2; it++) {
            int idx = tid + it * 512;
            int row = idx >> 3, u = idx & 7;
            cp16(st + row * 144 + u * 16, ah + (size_t)row * 256 + u * 8);
        }
        #pragma unroll
        for (int it = 0; it < 4; it++) {
            int idx = tid + it * 512;
            int row = idx >> 3, u = idx & 7;
            cp16(st + 18432u + row * 144 + u * 16, wh + (size_t)row * 256 + u * 8);
        }
        asm volatile("cp.async.commit_group;" ::: "memory");
    };

    const int a_row = lane & 15, a_kh = (lane >> 4) << 3;
    const int b_n = (lane & 7) + ((lane >> 4) << 3);
    const int b_kh = ((lane >> 3) & 1) << 3;
    const uint32_t aOff = ((m0 + a_row) * 72 + a_kh) * 2;
    const uint32_t bOff = 18432u + ((n0 + b_n) * 72 + b_kh) * 2;

    float4 acc[2][8];
    #pragma unroll
    for (int i = 0; i < 2; i++)
        #pragma unroll
        for (int j = 0; j < 8; j++) acc[i][j] = make_float4(0.f, 0.f, 0.f, 0.f);

    load_chunk(0);
    #pragma unroll 1
    for (int kc = 0; kc < 4; kc++) {
        if (kc < 3) {
            load_chunk(kc + 1);
            asm volatile("cp.async.wait_group 1;" ::: "memory");
        } else {
            asm volatile("cp.async.wait_group 0;" ::: "memory");
        }
        __syncthreads();
        uint32_t st = sb + (uint32_t)(kc & 1) * OLS_STAGE;
        uint32_t aB = st + aOff, bB = st + bOff;
        #pragma unroll
        for (int ks = 0; ks < 4; ks++) {
            uint32_t ah[2][4];
            ldsm4(ah[0], aB + ks * 32);
            ldsm4(ah[1], aB + 2304 + ks * 32);
            #pragma unroll
            for (int nb = 0; nb < 4; nb++) {
                uint32_t bh[4];
                ldsm4(bh, bB + nb * 2304 + ks * 32);
                #pragma unroll
                for (int mt = 0; mt < 2; mt++)
                    #pragma unroll
                    for (int sub = 0; sub < 2; sub++)
                        mma_f16(acc[mt][nb * 2 + sub], ah[mt],
                                bh[sub*2], bh[sub*2+1]);
            }
        }
        __syncthreads();
    }

    float sums[2][2] = {{0.f,0.f},{0.f,0.f}}, sqs[2][2] = {{0.f,0.f},{0.f,0.f}};
    #pragma unroll
    for (int mt = 0; mt < 2; mt++) {
        int rl = r0 + m0 + mt * 16 + (lane >> 2);
        #pragma unroll
        for (int nt = 0; nt < 8; nt++) {
            int c = n0 + nt * 8 + (lane & 3) * 2;
            float2 bo2 = *(const float2*)(bop + c);
            float2 xl = *(const float2*)(xres + (size_t)rl * 256 + c);
            float2 xh = *(const float2*)(xres + (size_t)(rl + 8) * 256 + c);
            float4& a = acc[mt][nt];
            a.x += bo2.x + xl.x; a.y += bo2.y + xl.y;
            a.z += bo2.x + xh.x; a.w += bo2.y + xh.y;
            sums[mt][0] += a.x + a.y; sqs[mt][0] += a.x*a.x + a.y*a.y;
            sums[mt][1] += a.z + a.w; sqs[mt][1] += a.z*a.z + a.w*a.w;
        }
    }
    #pragma unroll
    for (int mt = 0; mt < 2; mt++)
        #pragma unroll
        for (int hf = 0; hf < 2; hf++) {
            sums[mt][hf] += __shfl_xor_sync(0xffffffffu, sums[mt][hf], 1);
            sums[mt][hf] += __shfl_xor_sync(0xffffffffu, sums[mt][hf], 2);
            sqs[mt][hf]  += __shfl_xor_sync(0xffffffffu, sqs[mt][hf], 1);
            sqs[mt][hf]  += __shfl_xor_sync(0xffffffffu, sqs[mt][hf], 2);
        }
    float* ssum = (float*)(sm + OLS_SUM);
    float* ssq  = (float*)(sm + OLS_SQ);
    if ((lane & 3) == 0) {
        #pragma unroll
        for (int mt = 0; mt < 2; mt++)
            #pragma unroll
            for (int hf = 0; hf < 2; hf++) {
                int row = m0 + mt * 16 + hf * 8 + (lane >> 2);
                ssum[(wid & 3) * 128 + row] = sums[mt][hf];
                ssq [(wid & 3) * 128 + row] = sqs[mt][hf];
            }
    }
    __syncthreads();
    float mu[2][2], rs[2][2];
    #pragma unroll
    for (int mt = 0; mt < 2; mt++)
        #pragma unroll
        for (int hf = 0; hf < 2; hf++) {
            int row = m0 + mt * 16 + hf * 8 + (lane >> 2);
            float s = ssum[row] + ssum[128 + row] + ssum[256 + row] + ssum[384 + row];
            float q = ssq[row] + ssq[128 + row] + ssq[256 + row] + ssq[384 + row];
            float m = s * (1.f / 256.f);
            mu[mt][hf] = m;
            rs[mt][hf] = rsqrtf(q * (1.f / 256.f) - m * m + 1e-5f);
        }
    #pragma unroll
    for (int mt = 0; mt < 2; mt++) {
        int rl = r0 + m0 + mt * 16 + (lane >> 2);
        #pragma unroll
        for (int nt = 0; nt < 8; nt++) {
            int c = n0 + nt * 8 + (lane & 3) * 2;
            float2 g2 = *(const float2*)(gp + c);
            float2 b2 = *(const float2*)(bbp + c);
            float4 a = acc[mt][nt];
            float2 o1, o2;
            o1.x = (a.x - mu[mt][0]) * rs[mt][0] * g2.x + b2.x;
            o1.y = (a.y - mu[mt][0]) * rs[mt][0] * g2.y + b2.y;
            o2.x = (a.z - mu[mt][1]) * rs[mt][1] * g2.x + b2.x;
            o2.y = (a.w - mu[mt][1]) * rs[mt][1] * g2.y + b2.y;
            *(float2*)(out + (size_t)rl * 256 + c) = o1;
            *(float2*)(out + (size_t)(rl + 8) * 256 + c) = o2;
        }
    }
}

// ================= attention common (fp16 input, fp32 smem/math) =================
#define ATT_STRIDE 288
#define ATT1_SMEM (WIN * ATT_STRIDE * 4)       // 50688 (QK==V)
#define ATT2_SMEM (2 * WIN * ATT_STRIDE * 4)   // 101376

__device__ __forceinline__ float4 h4_to_f4(uint2 raw) {
    __half2 h0 = *reinterpret_cast<__half2*>(&raw.x);
    __half2 h1 = *reinterpret_cast<__half2*>(&raw.y);
    return make_float4(__low2float(h0), __high2float(h0),
                       __low2float(h1), __high2float(h1));
}

__device__ __forceinline__ void attn_core(
    const float* sQK, const float* sV, int tid, int b, int s0,
    __half* __restrict__ ath, float* __restrict__ scores)
{
    const int sl = tid >> 3, h = tid & 7;
    const int dil = (h < 4) ? 3 : 1;
    const float scale = 0.1767766952966369f;  // 32^-0.5
    const int colb = h * 36;

    float4 q[8];
    {
        const float* qr = sQK + (sl + 6) * ATT_STRIDE + colb;
        #pragma unroll
        for (int j = 0; j < 8; j++) q[j] = *(const float4*)(qr + j * 4);
    }

    float sc[5];
    #pragma unroll
    for (int k = 0; k < 5; k++) {
        const float* kr = sQK + (sl + 6 + (k - 2) * dil) * ATT_STRIDE + colb;
        float d = 0.f;
        #pragma unroll
        for (int j = 0; j < 8; j++) {
            float4 kv = *(const float4*)(kr + j * 4);
            d += q[j].x * kv.x + q[j].y * kv.y + q[j].z * kv.z + q[j].w * kv.w;
        }
        sc[k] = d * scale;
    }
    float mx = sc[0];
    #pragma unroll
    for (int k = 1; k < 5; k++) mx = fmaxf(mx, sc[k]);
    float ex[5], sum = 0.f;
    #pragma unroll
    for (int k = 0; k < 5; k++) { ex[k] = __expf(sc[k] - mx); sum += ex[k]; }
    float inv = 1.f / sum;
    #pragma unroll
    for (int k = 0; k < 5; k++) ex[k] *= inv;

    size_t base = ((size_t)b * Ssz + s0 + sl) * 256 + h * 32;
    const float* v0 = sV + (sl + 6 - 2 * dil) * ATT_STRIDE + colb;
    const int vstep = dil * ATT_STRIDE;
    uint32_t Hw[16];
    #pragma unroll
    for (int j = 0; j < 8; j++) {
        float4 o = make_float4(0.f, 0.f, 0.f, 0.f);
        #pragma unroll
        for (int k = 0; k < 5; k++) {
            float4 vv = *(const float4*)(v0 + k * vstep + j * 4);
            o.x += ex[k] * vv.x; o.y += ex[k] * vv.y;
            o.z += ex[k] * vv.z; o.w += ex[k] * vv.w;
        }
        __half2 h0 = __floats2half2_rn(o.x, o.y);
        __half2 h1 = __floats2half2_rn(o.z, o.w);
        Hw[2*j]   = *reinterpret_cast<uint32_t*>(&h0);
        Hw[2*j+1] = *reinterpret_cast<uint32_t*>(&h1);
    }
    #pragma unroll
    for (int u = 0; u < 4; u++) {
        uint4 vh = make_uint4(Hw[u*4], Hw[u*4+1], Hw[u*4+2], Hw[u*4+3]);
        *(uint4*)((char*)(ath + base) + u * 16) = vh;
    }

    if (scores != nullptr) {
        float* sp = scores + (((size_t)b * 8 + h) * Ssz + s0 + sl) * 5;
        #pragma unroll
        for (int k = 0; k < 5; k++) sp[k] = ex[k];
    }
}

// attention, QK == V (blocks 1 & 2 batched via blockIdx.z)
__global__ __launch_bounds__(256) void attn_same(
    const __half* __restrict__ qk0, const __half* __restrict__ qk1,
    __half* __restrict__ ath0, __half* __restrict__ ath1,
    float* __restrict__ qs)
{
    extern __shared__ float smf[];
    const int chain = blockIdx.z;
    const __half* QK = chain ? qk1 : qk0;
    const int b  = blockIdx.y;
    const int s0 = blockIdx.x * 32;
    const int tid = threadIdx.x;

    for (int idx = tid; idx < WIN * 64; idx += 256) {
        int w = idx >> 6, c4 = idx & 63;
        int s = s0 + w - 6;
        float4 vq = make_float4(0.f, 0.f, 0.f, 0.f);
        if (s >= 0 && s < Ssz)
            vq = h4_to_f4(((const uint2*)QK)[((size_t)b * Ssz + s) * 64 + c4]);
        *(float4*)(smf + w * ATT_STRIDE + (c4 >> 3) * 36 + (c4 & 7) * 4) = vq;
    }
    __syncthreads();

    attn_core(smf, smf, tid, b, s0, chain ? ath1 : ath0, chain ? qs : nullptr);
}

// attention, QK != V (block 3)
__global__ __launch_bounds__(256) void attn_two(
    const __half* __restrict__ QK, const __half* __restrict__ V,
    __half* __restrict__ ath)
{
    extern __shared__ float smf[];
    float* sQK = smf;
    float* sV  = smf + WIN * ATT_STRIDE;
    const int b  = blockIdx.y;
    const int s0 = blockIdx.x * 32;
    const int tid = threadIdx.x;

    for (int idx = tid; idx < WIN * 64; idx += 256) {
        int w = idx >> 6, c4 = idx & 63;
        int s = s0 + w - 6;
        float4 vq = make_float4(0.f, 0.f, 0.f, 0.f);
        float4 vv = vq;
        if (s >= 0 && s < Ssz) {
            size_t off = ((size_t)b * Ssz + s) * 64 + c4;
            vq = h4_to_f4(((const uint2*)QK)[off]);
            vv = h4_to_f4(((const uint2*)V)[off]);
        }
        int sc = w * ATT_STRIDE + (c4 >> 3) * 36 + (c4 & 7) * 4;
        *(float4*)(sQK + sc) = vq;
        *(float4*)(sV + sc)  = vv;
    }
    __syncthreads();

    attn_core(sQK, sV, tid, b, s0, ath, nullptr);
}

// ================= launch =================
extern "C" void kernel_launch(void* const* d_in, const int* in_sizes, int n_in,
                              void* d_out, int out_size)
{
    (void)in_sizes; (void)n_in; (void)out_size;
    const float* q_emb = (const float*)d_in[0];
    const float* s_emb = (const float*)d_in[1];
    const float* W_lin = (const float*)d_in[3];  // (3,2,128,128)
    const float* b_lin = (const float*)d_in[4];  // (3,2,128)
    const float* W_out = (const float*)d_in[5];  // (3,256,256)
    const float* b_out = (const float*)d_in[6];  // (3,256)
    const float* ln_g  = (const float*)d_in[7];  // (3,256)
    const float* ln_b  = (const float*)d_in[8];  // (3,256)

    float* outp = (float*)d_out;
    float* z  = outp;
    float* qs = outp + (size_t)BS * 256;

    float *p_hq, *p_hs;
    __half *p_qk0, *p_qk1, *p_v, *p_ath0, *p_ath1, *p_wlh, *p_woh;
    cudaGetSymbolAddress((void**)&p_qk0, g_qk0);
    cudaGetSymbolAddress((void**)&p_qk1, g_qk1);
    cudaGetSymbolAddress((void**)&p_v,   g_v);
    cudaGetSymbolAddress((void**)&p_hq,  g_hq);
    cudaGetSymbolAddress((void**)&p_hs,  g_hs);
    cudaGetSymbolAddress((void**)&p_ath0, g_ath0);
    cudaGetSymbolAddress((void**)&p_ath1, g_ath1);
    cudaGetSymbolAddress((void**)&p_wlh, g_wlh);
    cudaGetSymbolAddress((void**)&p_woh, g_woh);

    const int smemP  = (int)PR_SMEM;
    const int smemO  = (int)OLS_SMEM;
    const int smemA1 = ATT1_SMEM;
    const int smemA2 = ATT2_SMEM;
    cudaFuncSetAttribute(proj_mma,  cudaFuncAttributeMaxDynamicSharedMemorySize, smemP);
    cudaFuncSetAttribute(outln_mma, cudaFuncAttributeMaxDynamicSharedMemorySize, smemO);
    cudaFuncSetAttribute(attn_same, cudaFuncAttributeMaxDynamicSharedMemorySize, smemA1);
    cudaFuncSetAttribute(attn_two,  cudaFuncAttributeMaxDynamicSharedMemorySize, smemA2);

    split_w<<<768, 256>>>(W_lin, W_out, p_wlh, p_woh);

    // ---- blocks 1 & 2, batched ----
    proj_mma<<<dim3(BS/128, 2, 2), 512, smemP>>>(
        q_emb, s_emb, p_wlh, 32768, b_lin, 256, p_qk0, p_qk1);
    attn_same<<<dim3(Ssz/32, Bsz, 2), 256, smemA1>>>(
        p_qk0, p_qk1, p_ath0, p_ath1, qs);
    outln_mma<<<dim3(BS/128, 2), 512, smemO>>>(
        p_ath0, p_ath1, p_woh, 65536,
        b_out, q_emb, s_emb, ln_g, ln_b, 256, p_hq, p_hs);

    // ---- block 3 ----
    proj_mma<<<dim3(BS/128, 2, 2), 512, smemP>>>(
        p_hq, p_hs, p_wlh + 65536, 0, b_lin + 512, 0, p_qk0, p_v);
    attn_two<<<dim3(Ssz/32, Bsz), 256, smemA2>>>(p_qk0, p_v, p_ath0);
    outln_mma<<<dim3(BS/128, 1), 512, smemO>>>(
        p_ath0, p_ath0, p_woh + 131072, 0,
        b_out + 512, p_hq, p_hq, ln_g + 512, ln_b + 512, 0, z, z);
}

// round 10
// speedup vs baseline: 4.2855x; 1.0290x over previous
#include <cuda_runtime.h>
#include <cuda_fp16.h>
#include <cstdint>

#define Bsz 32
#define Ssz 2048
#define BS (Bsz*Ssz)   // 65536 rows
#define WIN 44         // attention smem window rows (32 + 2*6 halo)

// ---------------- scratch (device globals; no allocation) ----------------
__device__ __half g_qk0[(size_t)BS*256];
__device__ __half g_qk1[(size_t)BS*256];
__device__ __half g_v  [(size_t)BS*256];
__device__ __half g_hq [(size_t)BS*256];
__device__ __half g_hs [(size_t)BS*256];
__device__ __half g_ath0[(size_t)BS*256];
__device__ __half g_ath1[(size_t)BS*256];
__device__ __half g_wlh[3*2*128*128];
__device__ __half g_woh[3*256*256];

// ================= helpers =================
__device__ __forceinline__ uint32_t smem_u32(const void* p) {
    uint32_t a;
    asm("{ .reg .u64 t; cvta.to.shared.u64 t, %1; cvt.u32.u64 %0, t; }"
        : "=r"(a) : "l"(p));
    return a;
}
__device__ __forceinline__ void ldsm4(uint32_t r[4], uint32_t addr) {
    asm volatile("ldmatrix.sync.aligned.m8n8.x4.shared.b16 {%0,%1,%2,%3}, [%4];"
                 : "=r"(r[0]), "=r"(r[1]), "=r"(r[2]), "=r"(r[3]) : "r"(addr));
}
__device__ __forceinline__ void mma_f16(float4& c, const uint32_t a[4],
                                        uint32_t b0, uint32_t b1) {
    asm volatile(
        "mma.sync.aligned.m16n8k16.row.col.f32.f16.f16.f32 "
        "{%0,%1,%2,%3}, {%4,%5,%6,%7}, {%8,%9}, {%0,%1,%2,%3};"
        : "+f"(c.x), "+f"(c.y), "+f"(c.z), "+f"(c.w)
        : "r"(a[0]), "r"(a[1]), "r"(a[2]), "r"(a[3]), "r"(b0), "r"(b1));
}
__device__ __forceinline__ void cp16(uint32_t dst, const void* src) {
    asm volatile("cp.async.cg.shared.global [%0], [%1], 16;"
                 :: "r"(dst), "l"(src) : "memory");
}

// Fill a 128-row x 64-col chunk into fp16 smem, row stride 72 halves.
__device__ __forceinline__ void fill_hi(const float* __restrict__ src, int stride,
                                        uint32_t* __restrict__ hi, int tid) {
    #pragma unroll
    for (int it = 0; it < 8; it++) {
        int idx = tid + it * 512;
        int row = idx >> 5, c2 = idx & 31;
        float2 v = *(const float2*)(src + (size_t)row * stride + c2 * 2);
        __half2 h = __floats2half2_rn(v.x, v.y);
        hi[row * 36 + c2] = *reinterpret_cast<uint32_t*>(&h);
    }
}
__device__ __forceinline__ void fill_hi(const __half* __restrict__ src, int stride,
                                        uint32_t* __restrict__ hi, int tid) {
    #pragma unroll
    for (int it = 0; it < 8; it++) {
        int idx = tid + it * 512;
        int row = idx >> 5, c2 = idx & 31;
        hi[row * 36 + c2] = *(const uint32_t*)(src + (size_t)row * stride + c2 * 2);
    }
}
__device__ __forceinline__ float2 ld2f(const float* p) { return *(const float2*)p; }
__device__ __forceinline__ float2 ld2f(const __half* p) {
    uint32_t r = *(const uint32_t*)p;
    __half2 h = *reinterpret_cast<__half2*>(&r);
    return make_float2(__low2float(h), __high2float(h));
}
__device__ __forceinline__ void st2f(float* p, float2 v) { *(float2*)p = v; }
__device__ __forceinline__ void st2f(__half* p, float2 v) {
    __half2 h = __floats2half2_rn(v.x, v.y);
    *(uint32_t*)p = *reinterpret_cast<uint32_t*>(&h);
}

// ================= weight fp16 prep =================
__global__ void split_w(const float* __restrict__ Wl, const float* __restrict__ Wo,
                        __half* __restrict__ wlh, __half* __restrict__ woh)
{
    int i = blockIdx.x * 256 + threadIdx.x;
    if (i < 3*2*128*128) wlh[i] = __float2half_rn(Wl[i]);
    if (i < 3*256*256)   woh[i] = __float2half_rn(Wo[i]);
}

// ================= projection GEMM (fp16 out, batched 2 chains) =================
#define PR_BIAS 67584u
#define PR_SMEM 68096u

template<typename TIN>
__global__ __launch_bounds__(512) void proj_mma(
    const TIN* __restrict__ x0, const TIN* __restrict__ x1,
    const __half* __restrict__ whi, int wstep,
    const float* __restrict__ bias, int bstep,
    __half* __restrict__ out0, __half* __restrict__ out1)
{
    extern __shared__ __align__(16) char sm[];
    uint32_t* Ahi = (uint32_t*)(sm);
    char* Bhi = sm + 18432;
    float* sbias  = (float*)(sm + PR_BIAS);
    float* stg    = (float*)sm;   // overlaps operands post-GEMM

    const int chain = blockIdx.z;
    const TIN* x = chain ? x1 : x0;
    __half* out = chain ? out1 : out0;
    const int branch = blockIdx.y;
    const int r0 = blockIdx.x * 128;
    const int tid = threadIdx.x, lane = tid & 31, wid = tid >> 5;
    const int m0 = (wid >> 2) * 32, n0 = (wid & 3) * 32;

    const float* bp = bias + chain * bstep + branch * 128;
    if (tid < 128) sbias[tid] = bp[tid];

    const uint32_t sA = smem_u32(Ahi), sB = smem_u32(Bhi);
    const int a_row = lane & 15, a_kh = (lane >> 4) << 3;
    const int b_n = (lane & 7) + ((lane >> 4) << 3);
    const int b_kh = ((lane >> 3) & 1) << 3;

    float4 acc[2][4];
    #pragma unroll
    for (int i = 0; i < 2; i++)
        #pragma unroll
        for (int j = 0; j < 4; j++) acc[i][j] = make_float4(0.f, 0.f, 0.f, 0.f);

    const TIN* xp = x + (size_t)r0 * 256 + branch * 128;
    const __half* whb = whi + (size_t)chain * wstep + (size_t)branch * 128 * 128;

    uint32_t aAddr[2], bAddr[2];
    aAddr[0] = sA + ((m0 + a_row) * 72 + a_kh) * 2;
    aAddr[1] = sA + ((m0 + 16 + a_row) * 72 + a_kh) * 2;
    bAddr[0] = sB + ((n0 + b_n) * 72 + b_kh) * 2;
    bAddr[1] = sB + ((n0 + 16 + b_n) * 72 + b_kh) * 2;

    for (int kc = 0; kc < 128; kc += 64) {
        fill_hi(xp + kc, 256, Ahi, tid);
        #pragma unroll
        for (int it = 0; it < 2; it++) {
            int idx = tid + it * 512;
            int row = idx >> 3, u = idx & 7;
            *(uint4*)(Bhi + row * 144 + u * 16) =
                *(const uint4*)(whb + row * 128 + kc + u * 8);
        }
        __syncthreads();
        #pragma unroll
        for (int ks = 0; ks < 4; ks++) {
            uint32_t ah[2][4], bh[2][4];
            #pragma unroll
            for (int mt = 0; mt < 2; mt++) ldsm4(ah[mt], aAddr[mt] + ks * 32);
            #pragma unroll
            for (int bt = 0; bt < 2; bt++) ldsm4(bh[bt], bAddr[bt] + ks * 32);
            #pragma unroll
            for (int mt = 0; mt < 2; mt++)
                #pragma unroll
                for (int bt = 0; bt < 2; bt++)
                    #pragma unroll
                    for (int sub = 0; sub < 2; sub++)
                        mma_f16(acc[mt][bt * 2 + sub], ah[mt],
                                bh[bt][sub*2], bh[bt][sub*2+1]);
        }
        __syncthreads();
    }

    #pragma unroll
    for (int mt = 0; mt < 2; mt++) {
        int rb = m0 + mt * 16 + (lane >> 2);
        #pragma unroll
        for (int nt = 0; nt < 4; nt++) {
            int j = n0 + nt * 8 + (lane & 3) * 2;
            int p0 = ((j & 31) << 2) + (j >> 5);
            int p1 = (((j + 1) & 31) << 2) + ((j + 1) >> 5);
            float4 a = acc[mt][nt];
            stg[rb * 132 + p0]       = a.x + sbias[j];
            stg[rb * 132 + p1]       = a.y + sbias[j + 1];
            stg[(rb + 8) * 132 + p0] = a.z + sbias[j];
            stg[(rb + 8) * 132 + p1] = a.w + sbias[j + 1];
        }
    }
    __syncthreads();
    #pragma unroll
    for (int it = 0; it < 8; it++) {
        int idx = tid + it * 512;
        int row = idx >> 5, q = idx & 31;
        float4 v = *(const float4*)(stg + row * 132 + q * 4);
        __half2 h0 = __floats2half2_rn(v.x, v.y);
        __half2 h1 = __floats2half2_rn(v.z, v.w);
        uint2 u = make_uint2(*reinterpret_cast<uint32_t*>(&h0),
                             *reinterpret_cast<uint32_t*>(&h1));
        *(uint2*)(out + (size_t)(r0 + row) * 256 + branch * 128 + q * 4) = u;
    }
}

// ================= out-proj + bias + residual + LayerNorm =================
#define OLS_STAGE 55296u
#define OLS_SUM   110592u
#define OLS_SQ    112640u
#define OLS_SMEM  114688u

template<typename TX, typename TO>
__global__ __launch_bounds__(512) void outln_mma(
    const __half* __restrict__ A0h, const __half* __restrict__ A1h,
    const __half* __restrict__ Whi, int wstep,
    const float* __restrict__ bo, const TX* __restrict__ xr0,
    const TX* __restrict__ xr1,
    const float* __restrict__ g, const float* __restrict__ bb, int pstep,
    TO* __restrict__ out0, TO* __restrict__ out1)
{
    extern __shared__ __align__(16) char sm[];
    const int chain = blockIdx.y;
    const __half* Ahi = chain ? A1h : A0h;
    const __half* Wp  = Whi + (size_t)chain * wstep;
    const TX* xres = chain ? xr1 : xr0;
    const float* bop = bo + chain * pstep;
    const float* gp  = g  + chain * pstep;
    const float* bbp = bb + chain * pstep;
    TO* out = chain ? out1 : out0;

    const int r0 = blockIdx.x * 128;
    const int tid = threadIdx.x, lane = tid & 31, wid = tid >> 5;
    const int m0 = (wid >> 2) * 32, n0 = (wid & 3) * 64;
    const uint32_t sb = smem_u32(sm);

    auto load_chunk = [&](int kc) {
        uint32_t st = sb + (uint32_t)(kc & 1) * OLS_STAGE;
        const __half* ah = Ahi + (size_t)r0 * 256 + kc * 64;
        const __half* wh = Wp + kc * 64;
        #pragma unroll
        for (int it = 0; it < 2; it++) {
            int idx = tid + it * 512;
            int row = idx >> 3, u = idx & 7;
            cp16(st + row * 144 + u * 16, ah + (size_t)row * 256 + u * 8);
        }
        #pragma unroll
        for (int it = 0; it < 4; it++) {
            int idx = tid + it * 512;
            int row = idx >> 3, u = idx & 7;
            cp16(st + 18432u + row * 144 + u * 16, wh + (size_t)row * 256 + u * 8);
        }
        asm volatile("cp.async.commit_group;" ::: "memory");
    };

    const int a_row = lane & 15, a_kh = (lane >> 4) << 3;
    const int b_n = (lane & 7) + ((lane >> 4) << 3);
    const int b_kh = ((lane >> 3) & 1) << 3;
    const uint32_t aOff = ((m0 + a_row) * 72 + a_kh) * 2;
    const uint32_t bOff = 18432u + ((n0 + b_n) * 72 + b_kh) * 2;

    float4 acc[2][8];
    #pragma unroll
    for (int i = 0; i < 2; i++)
        #pragma unroll
        for (int j = 0; j < 8; j++) acc[i][j] = make_float4(0.f, 0.f, 0.f, 0.f);

    load_chunk(0);
    #pragma unroll 1
    for (int kc = 0; kc < 4; kc++) {
        if (kc < 3) {
            load_chunk(kc + 1);
            asm volatile("cp.async.wait_group 1;" ::: "memory");
        } else {
            asm volatile("cp.async.wait_group 0;" ::: "memory");
        }
        __syncthreads();
        uint32_t st = sb + (uint32_t)(kc & 1) * OLS_STAGE;
        uint32_t aB = st + aOff, bB = st + bOff;
        #pragma unroll
        for (int ks = 0; ks < 4; ks++) {
            uint32_t ah[2][4];
            ldsm4(ah[0], aB + ks * 32);
            ldsm4(ah[1], aB + 2304 + ks * 32);
            #pragma unroll
            for (int nb = 0; nb < 4; nb++) {
                uint32_t bh[4];
                ldsm4(bh, bB + nb * 2304 + ks * 32);
                #pragma unroll
                for (int mt = 0; mt < 2; mt++)
                    #pragma unroll
                    for (int sub = 0; sub < 2; sub++)
                        mma_f16(acc[mt][nb * 2 + sub], ah[mt],
                                bh[sub*2], bh[sub*2+1]);
            }
        }
        __syncthreads();
    }

    float sums[2][2] = {{0.f,0.f},{0.f,0.f}}, sqs[2][2] = {{0.f,0.f},{0.f,0.f}};
    #pragma unroll
    for (int mt = 0; mt < 2; mt++) {
        int rl = r0 + m0 + mt * 16 + (lane >> 2);
        #pragma unroll
        for (int nt = 0; nt < 8; nt++) {
            int c = n0 + nt * 8 + (lane & 3) * 2;
            float2 bo2 = *(const float2*)(bop + c);
            float2 xl = ld2f(xres + (size_t)rl * 256 + c);
            float2 xh = ld2f(xres + (size_t)(rl + 8) * 256 + c);
            float4& a = acc[mt][nt];
            a.x += bo2.x + xl.x; a.y += bo2.y + xl.y;
            a.z += bo2.x + xh.x; a.w += bo2.y + xh.y;
            sums[mt][0] += a.x + a.y; sqs[mt][0] += a.x*a.x + a.y*a.y;
            sums[mt][1] += a.z + a.w; sqs[mt][1] += a.z*a.z + a.w*a.w;
        }
    }
    #pragma unroll
    for (int mt = 0; mt < 2; mt++)
        #pragma unroll
        for (int hf = 0; hf < 2; hf++) {
            sums[mt][hf] += __shfl_xor_sync(0xffffffffu, sums[mt][hf], 1);
            sums[mt][hf] += __shfl_xor_sync(0xffffffffu, sums[mt][hf], 2);
            sqs[mt][hf]  += __shfl_xor_sync(0xffffffffu, sqs[mt][hf], 1);
            sqs[mt][hf]  += __shfl_xor_sync(0xffffffffu, sqs[mt][hf], 2);
        }
    float* ssum = (float*)(sm + OLS_SUM);
    float* ssq  = (float*)(sm + OLS_SQ);
    if ((lane & 3) == 0) {
        #pragma unroll
        for (int mt = 0; mt < 2; mt++)
            #pragma unroll
            for (int hf = 0; hf < 2; hf++) {
                int row = m0 + mt * 16 + hf * 8 + (lane >> 2);
                ssum[(wid & 3) * 128 + row] = sums[mt][hf];
                ssq [(wid & 3) * 128 + row] = sqs[mt][hf];
            }
    }
    __syncthreads();
    float mu[2][2], rs[2][2];
    #pragma unroll
    for (int mt = 0; mt < 2; mt++)
        #pragma unroll
        for (int hf = 0; hf < 2; hf++) {
            int row = m0 + mt * 16 + hf * 8 + (lane >> 2);
            float s = ssum[row] + ssum[128 + row] + ssum[256 + row] + ssum[384 + row];
            float q = ssq[row] + ssq[128 + row] + ssq[256 + row] + ssq[384 + row];
            float m = s * (1.f / 256.f);
            mu[mt][hf] = m;
            rs[mt][hf] = rsqrtf(q * (1.f / 256.f) - m * m + 1e-5f);
        }
    #pragma unroll
    for (int mt = 0; mt < 2; mt++) {
        int rl = r0 + m0 + mt * 16 + (lane >> 2);
        #pragma unroll
        for (int nt = 0; nt < 8; nt++) {
            int c = n0 + nt * 8 + (lane & 3) * 2;
            float2 g2 = *(const float2*)(gp + c);
            float2 b2 = *(const float2*)(bbp + c);
            float4 a = acc[mt][nt];
            float2 o1, o2;
            o1.x = (a.x - mu[mt][0]) * rs[mt][0] * g2.x + b2.x;
            o1.y = (a.y - mu[mt][0]) * rs[mt][0] * g2.y + b2.y;
            o2.x = (a.z - mu[mt][1]) * rs[mt][1] * g2.x + b2.x;
            o2.y = (a.w - mu[mt][1]) * rs[mt][1] * g2.y + b2.y;
            st2f(out + (size_t)rl * 256 + c, o1);
            st2f(out + (size_t)(rl + 8) * 256 + c, o2);
        }
    }
}

// ================= attention common (fp16 input, fp32 smem/math) =================
#define ATT_STRIDE 288
#define ATT1_SMEM (WIN * ATT_STRIDE * 4)       // 50688 (QK==V)
#define ATT2_SMEM (2 * WIN * ATT_STRIDE * 4)   // 101376

__device__ __forceinline__ float4 h4_to_f4(uint2 raw) {
    __half2 h0 = *reinterpret_cast<__half2*>(&raw.x);
    __half2 h1 = *reinterpret_cast<__half2*>(&raw.y);
    return make_float4(__low2float(h0), __high2float(h0),
                       __low2float(h1), __high2float(h1));
}

__device__ __forceinline__ void attn_core(
    const float* sQK, const float* sV, int tid, int b, int s0,
    __half* __restrict__ ath, float* __restrict__ scores)
{
    const int sl = tid >> 3, h = tid & 7;
    const int dil = (h < 4) ? 3 : 1;
    const float scale = 0.1767766952966369f;  // 32^-0.5
    const int colb = h * 36;

    float4 q[8];
    {
        const float* qr = sQK + (sl + 6) * ATT_STRIDE + colb;
        #pragma unroll
        for (int j = 0; j < 8; j++) q[j] = *(const float4*)(qr + j * 4);
    }

    float sc[5];
    #pragma unroll
    for (int k = 0; k < 5; k++) {
        const float* kr = sQK + (sl + 6 + (k - 2) * dil) * ATT_STRIDE + colb;
        float d = 0.f;
        #pragma unroll
        for (int j = 0; j < 8; j++) {
            float4 kv = *(const float4*)(kr + j * 4);
            d += q[j].x * kv.x + q[j].y * kv.y + q[j].z * kv.z + q[j].w * kv.w;
        }
        sc[k] = d * scale;
    }
    float mx = sc[0];
    #pragma unroll
    for (int k = 1; k < 5; k++) mx = fmaxf(mx, sc[k]);
    float ex[5], sum = 0.f;
    #pragma unroll
    for (int k = 0; k < 5; k++) { ex[k] = __expf(sc[k] - mx); sum += ex[k]; }
    float inv = 1.f / sum;
    #pragma unroll
    for (int k = 0; k < 5; k++) ex[k] *= inv;

    size_t base = ((size_t)b * Ssz + s0 + sl) * 256 + h * 32;
    const float* v0 = sV + (sl + 6 - 2 * dil) * ATT_STRIDE + colb;
    const int vstep = dil * ATT_STRIDE;
    uint32_t Hw[16];
    #pragma unroll
    for (int j = 0; j < 8; j++) {
        float4 o = make_float4(0.f, 0.f, 0.f, 0.f);
        #pragma unroll
        for (int k = 0; k < 5; k++) {
            float4 vv = *(const float4*)(v0 + k * vstep + j * 4);
            o.x += ex[k] * vv.x; o.y += ex[k] * vv.y;
            o.z += ex[k] * vv.z; o.w += ex[k] * vv.w;
        }
        __half2 h0 = __floats2half2_rn(o.x, o.y);
        __half2 h1 = __floats2half2_rn(o.z, o.w);
        Hw[2*j]   = *reinterpret_cast<uint32_t*>(&h0);
        Hw[2*j+1] = *reinterpret_cast<uint32_t*>(&h1);
    }
    #pragma unroll
    for (int u = 0; u < 4; u++) {
        uint4 vh = make_uint4(Hw[u*4], Hw[u*4+1], Hw[u*4+2], Hw[u*4+3]);
        *(uint4*)((char*)(ath + base) + u * 16) = vh;
    }

    if (scores != nullptr) {
        float* sp = scores + (((size_t)b * 8 + h) * Ssz + s0 + sl) * 5;
        #pragma unroll
        for (int k = 0; k < 5; k++) sp[k] = ex[k];
    }
}

// attention, QK == V (blocks 1 & 2 batched via blockIdx.z)
__global__ __launch_bounds__(256) void attn_same(
    const __half* __restrict__ qk0, const __half* __restrict__ qk1,
    __half* __restrict__ ath0, __half* __restrict__ ath1,
    float* __restrict__ qs)
{
    extern __shared__ float smf[];
    const int chain = blockIdx.z;
    const __half* QK = chain ? qk1 : qk0;
    const int b  = blockIdx.y;
    const int s0 = blockIdx.x * 32;
    const int tid = threadIdx.x;

    for (int idx = tid; idx < WIN * 64; idx += 256) {
        int w = idx >> 6, c4 = idx & 63;
        int s = s0 + w - 6;
        float4 vq = make_float4(0.f, 0.f, 0.f, 0.f);
        if (s >= 0 && s < Ssz)
            vq = h4_to_f4(((const uint2*)QK)[((size_t)b * Ssz + s) * 64 + c4]);
        *(float4*)(smf + w * ATT_STRIDE + (c4 >> 3) * 36 + (c4 & 7) * 4) = vq;
    }
    __syncthreads();

    attn_core(smf, smf, tid, b, s0, chain ? ath1 : ath0, chain ? qs : nullptr);
}

// attention, QK != V (block 3)
__global__ __launch_bounds__(256) void attn_two(
    const __half* __restrict__ QK, const __half* __restrict__ V,
    __half* __restrict__ ath)
{
    extern __shared__ float smf[];
    float* sQK = smf;
    float* sV  = smf + WIN * ATT_STRIDE;
    const int b  = blockIdx.y;
    const int s0 = blockIdx.x * 32;
    const int tid = threadIdx.x;

    for (int idx = tid; idx < WIN * 64; idx += 256) {
        int w = idx >> 6, c4 = idx & 63;
        int s = s0 + w - 6;
        float4 vq = make_float4(0.f, 0.f, 0.f, 0.f);
        float4 vv = vq;
        if (s >= 0 && s < Ssz) {
            size_t off = ((size_t)b * Ssz + s) * 64 + c4;
            vq = h4_to_f4(((const uint2*)QK)[off]);
            vv = h4_to_f4(((const uint2*)V)[off]);
        }
        int sc = w * ATT_STRIDE + (c4 >> 3) * 36 + (c4 & 7) * 4;
        *(float4*)(sQK + sc) = vq;
        *(float4*)(sV + sc)  = vv;
    }
    __syncthreads();

    attn_core(sQK, sV, tid, b, s0, ath, nullptr);
}

// ================= launch =================
extern "C" void kernel_launch(void* const* d_in, const int* in_sizes, int n_in,
                              void* d_out, int out_size)
{
    (void)in_sizes; (void)n_in; (void)out_size;
    const float* q_emb = (const float*)d_in[0];
    const float* s_emb = (const float*)d_in[1];
    const float* W_lin = (const float*)d_in[3];  // (3,2,128,128)
    const float* b_lin = (const float*)d_in[4];  // (3,2,128)
    const float* W_out = (const float*)d_in[5];  // (3,256,256)
    const float* b_out = (const float*)d_in[6];  // (3,256)
    const float* ln_g  = (const float*)d_in[7];  // (3,256)
    const float* ln_b  = (const float*)d_in[8];  // (3,256)

    float* outp = (float*)d_out;
    float* z  = outp;
    float* qs = outp + (size_t)BS * 256;

    __half *p_qk0, *p_qk1, *p_v, *p_hq, *p_hs, *p_ath0, *p_ath1, *p_wlh, *p_woh;
    cudaGetSymbolAddress((void**)&p_qk0, g_qk0);
    cudaGetSymbolAddress((void**)&p_qk1, g_qk1);
    cudaGetSymbolAddress((void**)&p_v,   g_v);
    cudaGetSymbolAddress((void**)&p_hq,  g_hq);
    cudaGetSymbolAddress((void**)&p_hs,  g_hs);
    cudaGetSymbolAddress((void**)&p_ath0, g_ath0);
    cudaGetSymbolAddress((void**)&p_ath1, g_ath1);
    cudaGetSymbolAddress((void**)&p_wlh, g_wlh);
    cudaGetSymbolAddress((void**)&p_woh, g_woh);

    const int smemP  = (int)PR_SMEM;
    const int smemO  = (int)OLS_SMEM;
    const int smemA1 = ATT1_SMEM;
    const int smemA2 = ATT2_SMEM;
    cudaFuncSetAttribute(proj_mma<float>,  cudaFuncAttributeMaxDynamicSharedMemorySize, smemP);
    cudaFuncSetAttribute(proj_mma<__half>, cudaFuncAttributeMaxDynamicSharedMemorySize, smemP);
    cudaFuncSetAttribute((const void*)outln_mma<float, __half>,
                         cudaFuncAttributeMaxDynamicSharedMemorySize, smemO);
    cudaFuncSetAttribute((const void*)outln_mma<__half, float>,
                         cudaFuncAttributeMaxDynamicSharedMemorySize, smemO);
    cudaFuncSetAttribute(attn_same, cudaFuncAttributeMaxDynamicSharedMemorySize, smemA1);
    cudaFuncSetAttribute(attn_two,  cudaFuncAttributeMaxDynamicSharedMemorySize, smemA2);

    split_w<<<768, 256>>>(W_lin, W_out, p_wlh, p_woh);

    // ---- blocks 1 & 2, batched ----
    proj_mma<float><<<dim3(BS/128, 2, 2), 512, smemP>>>(
        q_emb, s_emb, p_wlh, 32768, b_lin, 256, p_qk0, p_qk1);
    attn_same<<<dim3(Ssz/32, Bsz, 2), 256, smemA1>>>(
        p_qk0, p_qk1, p_ath0, p_ath1, qs);
    outln_mma<float, __half><<<dim3(BS/128, 2), 512, smemO>>>(
        p_ath0, p_ath1, p_woh, 65536,
        b_out, q_emb, s_emb, ln_g, ln_b, 256, p_hq, p_hs);

    // ---- block 3 ----
    proj_mma<__half><<<dim3(BS/128, 2, 2), 512, smemP>>>(
        p_hq, p_hs, p_wlh + 65536, 0, b_lin + 512, 0, p_qk0, p_v);
    attn_two<<<dim3(Ssz/32, Bsz), 256, smemA2>>>(p_qk0, p_v, p_ath0);
    outln_mma<__half, float><<<dim3(BS/128, 1), 512, smemO>>>(
        p_ath0, p_ath0, p_woh + 131072, 0,
        b_out + 512, p_hq, p_hq, ln_g + 512, ln_b + 512, 0, z, z);
}

// round 11
// speedup vs baseline: 4.4386x; 1.0357x over previous
#include <cuda_runtime.h>
#include <cuda_fp16.h>
#include <cstdint>

#define Bsz 32
#define Ssz 2048
#define BS (Bsz*Ssz)   // 65536 rows
#define WIN 44         // attention smem window rows (32 + 2*6 halo)

// ---------------- scratch (device globals; no allocation) ----------------
__device__ __half g_qk0[(size_t)BS*256];
__device__ __half g_qk1[(size_t)BS*256];
__device__ __half g_v  [(size_t)BS*256];
__device__ __half g_hq [(size_t)BS*256];
__device__ __half g_hs [(size_t)BS*256];
__device__ __half g_ath0[(size_t)BS*256];
__device__ __half g_ath1[(size_t)BS*256];
__device__ __half g_wlh[3*2*128*128];
__device__ __half g_woh[3*256*256];

// ================= helpers =================
__device__ __forceinline__ uint32_t smem_u32(const void* p) {
    uint32_t a;
    asm("{ .reg .u64 t; cvta.to.shared.u64 t, %1; cvt.u32.u64 %0, t; }"
        : "=r"(a) : "l"(p));
    return a;
}
__device__ __forceinline__ void ldsm4(uint32_t r[4], uint32_t addr) {
    asm volatile("ldmatrix.sync.aligned.m8n8.x4.shared.b16 {%0,%1,%2,%3}, [%4];"
                 : "=r"(r[0]), "=r"(r[1]), "=r"(r[2]), "=r"(r[3]) : "r"(addr));
}
__device__ __forceinline__ void mma_f16(float4& c, const uint32_t a[4],
                                        uint32_t b0, uint32_t b1) {
    asm volatile(
        "mma.sync.aligned.m16n8k16.row.col.f32.f16.f16.f32 "
        "{%0,%1,%2,%3}, {%4,%5,%6,%7}, {%8,%9}, {%0,%1,%2,%3};"
        : "+f"(c.x), "+f"(c.y), "+f"(c.z), "+f"(c.w)
        : "r"(a[0]), "r"(a[1]), "r"(a[2]), "r"(a[3]), "r"(b0), "r"(b1));
}
__device__ __forceinline__ void cp16(uint32_t dst, const void* src) {
    asm volatile("cp.async.cg.shared.global [%0], [%1], 16;"
                 :: "r"(dst), "l"(src) : "memory");
}

// Fill a 64-row x 64-col chunk into fp16 smem (row stride 72 halves), 256 threads.
__device__ __forceinline__ void fill_hi64(const float* __restrict__ src, int stride,
                                          uint32_t* __restrict__ hi, int tid) {
    #pragma unroll
    for (int it = 0; it < 8; it++) {
        int idx = tid + it * 256;
        int row = idx >> 5, c2 = idx & 31;
        float2 v = *(const float2*)(src + (size_t)row * stride + c2 * 2);
        __half2 h = __floats2half2_rn(v.x, v.y);
        hi[row * 36 + c2] = *reinterpret_cast<uint32_t*>(&h);
    }
}
__device__ __forceinline__ void fill_hi64(const __half* __restrict__ src, int stride,
                                          uint32_t* __restrict__ hi, int tid) {
    #pragma unroll
    for (int it = 0; it < 8; it++) {
        int idx = tid + it * 256;
        int row = idx >> 5, c2 = idx & 31;
        hi[row * 36 + c2] = *(const uint32_t*)(src + (size_t)row * stride + c2 * 2);
    }
}
__device__ __forceinline__ float2 ld2f(const float* p) { return *(const float2*)p; }
__device__ __forceinline__ float2 ld2f(const __half* p) {
    uint32_t r = *(const uint32_t*)p;
    __half2 h = *reinterpret_cast<__half2*>(&r);
    return make_float2(__low2float(h), __high2float(h));
}
__device__ __forceinline__ void st2f(float* p, float2 v) { *(float2*)p = v; }
__device__ __forceinline__ void st2f(__half* p, float2 v) {
    __half2 h = __floats2half2_rn(v.x, v.y);
    *(uint32_t*)p = *reinterpret_cast<uint32_t*>(&h);
}

// ================= weight fp16 prep =================
__global__ void split_w(const float* __restrict__ Wl, const float* __restrict__ Wo,
                        __half* __restrict__ wlh, __half* __restrict__ woh)
{
    int i = blockIdx.x * 256 + threadIdx.x;
    if (i < 3*2*128*128) wlh[i] = __float2half_rn(Wl[i]);
    if (i < 3*256*256)   woh[i] = __float2half_rn(Wo[i]);
}

// ================= projection GEMM (64-row tile, 256 thr, 2 CTA/SM) =================
// tile 64 rows x 128 cols; warps: m0=(wid>>2)*32 (2 groups), n0=(wid&3)*32.
#define PR_BIAS 33792u
#define PR_SMEM 34304u

template<typename TIN>
__global__ __launch_bounds__(256) void proj_mma(
    const TIN* __restrict__ x0, const TIN* __restrict__ x1,
    const __half* __restrict__ whi, int wstep,
    const float* __restrict__ bias, int bstep,
    __half* __restrict__ out0, __half* __restrict__ out1)
{
    extern __shared__ __align__(16) char sm[];
    uint32_t* Ahi = (uint32_t*)(sm);          // 64 x 72 halves = 9216 B
    char* Bhi = sm + 9216;                    // 128 x 72 halves = 18432 B
    float* sbias  = (float*)(sm + PR_BIAS);
    float* stg    = (float*)sm;               // 64 x 132 fp32 = 33792 B (overlap)

    const int chain = blockIdx.z;
    const TIN* x = chain ? x1 : x0;
    __half* out = chain ? out1 : out0;
    const int branch = blockIdx.y;
    const int r0 = blockIdx.x * 64;
    const int tid = threadIdx.x, lane = tid & 31, wid = tid >> 5;
    const int m0 = (wid >> 2) * 32, n0 = (wid & 3) * 32;

    const float* bp = bias + chain * bstep + branch * 128;
    if (tid < 128) sbias[tid] = bp[tid];

    const uint32_t sA = smem_u32(Ahi), sB = smem_u32(Bhi);
    const int a_row = lane & 15, a_kh = (lane >> 4) << 3;
    const int b_n = (lane & 7) + ((lane >> 4) << 3);
    const int b_kh = ((lane >> 3) & 1) << 3;

    float4 acc[2][4];
    #pragma unroll
    for (int i = 0; i < 2; i++)
        #pragma unroll
        for (int j = 0; j < 4; j++) acc[i][j] = make_float4(0.f, 0.f, 0.f, 0.f);

    const TIN* xp = x + (size_t)r0 * 256 + branch * 128;
    const __half* whb = whi + (size_t)chain * wstep + (size_t)branch * 128 * 128;

    uint32_t aAddr[2], bAddr[2];
    aAddr[0] = sA + ((m0 + a_row) * 72 + a_kh) * 2;
    aAddr[1] = sA + ((m0 + 16 + a_row) * 72 + a_kh) * 2;
    bAddr[0] = sB + ((n0 + b_n) * 72 + b_kh) * 2;
    bAddr[1] = sB + ((n0 + 16 + b_n) * 72 + b_kh) * 2;

    for (int kc = 0; kc < 128; kc += 64) {
        fill_hi64(xp + kc, 256, Ahi, tid);
        #pragma unroll
        for (int it = 0; it < 4; it++) {
            int idx = tid + it * 256;
            int row = idx >> 3, u = idx & 7;
            *(uint4*)(Bhi + row * 144 + u * 16) =
                *(const uint4*)(whb + row * 128 + kc + u * 8);
        }
        __syncthreads();
        #pragma unroll
        for (int ks = 0; ks < 4; ks++) {
            uint32_t ah[2][4], bh[2][4];
            #pragma unroll
            for (int mt = 0; mt < 2; mt++) ldsm4(ah[mt], aAddr[mt] + ks * 32);
            #pragma unroll
            for (int bt = 0; bt < 2; bt++) ldsm4(bh[bt], bAddr[bt] + ks * 32);
            #pragma unroll
            for (int mt = 0; mt < 2; mt++)
                #pragma unroll
                for (int bt = 0; bt < 2; bt++)
                    #pragma unroll
                    for (int sub = 0; sub < 2; sub++)
                        mma_f16(acc[mt][bt * 2 + sub], ah[mt],
                                bh[bt][sub*2], bh[bt][sub*2+1]);
        }
        __syncthreads();
    }

    #pragma unroll
    for (int mt = 0; mt < 2; mt++) {
        int rb = m0 + mt * 16 + (lane >> 2);
        #pragma unroll
        for (int nt = 0; nt < 4; nt++) {
            int j = n0 + nt * 8 + (lane & 3) * 2;
            int p0 = ((j & 31) << 2) + (j >> 5);
            int p1 = (((j + 1) & 31) << 2) + ((j + 1) >> 5);
            float4 a = acc[mt][nt];
            stg[rb * 132 + p0]       = a.x + sbias[j];
            stg[rb * 132 + p1]       = a.y + sbias[j + 1];
            stg[(rb + 8) * 132 + p0] = a.z + sbias[j];
            stg[(rb + 8) * 132 + p1] = a.w + sbias[j + 1];
        }
    }
    __syncthreads();
    #pragma unroll
    for (int it = 0; it < 8; it++) {
        int idx = tid + it * 256;
        int row = idx >> 5, q = idx & 31;
        float4 v = *(const float4*)(stg + row * 132 + q * 4);
        __half2 h0 = __floats2half2_rn(v.x, v.y);
        __half2 h1 = __floats2half2_rn(v.z, v.w);
        uint2 u = make_uint2(*reinterpret_cast<uint32_t*>(&h0),
                             *reinterpret_cast<uint32_t*>(&h1));
        *(uint2*)(out + (size_t)(r0 + row) * 256 + branch * 128 + q * 4) = u;
    }
}

// ================= out-proj + bias + residual + LN (64-row tile, 256 thr) =================
// stage: A 64x72h (9216 B) + W 256x72h (36864 B) = 46080 B; two stages.
#define OLS_STAGE 46080u
#define OLS_SUM   92160u
#define OLS_SQ    93184u
#define OLS_SMEM  94208u

template<typename TX, typename TO>
__global__ __launch_bounds__(256) void outln_mma(
    const __half* __restrict__ A0h, const __half* __restrict__ A1h,
    const __half* __restrict__ Whi, int wstep,
    const float* __restrict__ bo, const TX* __restrict__ xr0,
    const TX* __restrict__ xr1,
    const float* __restrict__ g, const float* __restrict__ bb, int pstep,
    TO* __restrict__ out0, TO* __restrict__ out1)
{
    extern __shared__ __align__(16) char sm[];
    const int chain = blockIdx.y;
    const __half* Ahi = chain ? A1h : A0h;
    const __half* Wp  = Whi + (size_t)chain * wstep;
    const TX* xres = chain ? xr1 : xr0;
    const float* bop = bo + chain * pstep;
    const float* gp  = g  + chain * pstep;
    const float* bbp = bb + chain * pstep;
    TO* out = chain ? out1 : out0;

    const int r0 = blockIdx.x * 64;
    const int tid = threadIdx.x, lane = tid & 31, wid = tid >> 5;
    const int m0 = (wid >> 2) * 32, n0 = (wid & 3) * 64;
    const uint32_t sb = smem_u32(sm);

    auto load_chunk = [&](int kc) {
        uint32_t st = sb + (uint32_t)(kc & 1) * OLS_STAGE;
        const __half* ah = Ahi + (size_t)r0 * 256 + kc * 64;
        const __half* wh = Wp + kc * 64;
        #pragma unroll
        for (int it = 0; it < 2; it++) {
            int idx = tid + it * 256;
            int row = idx >> 3, u = idx & 7;
            cp16(st + row * 144 + u * 16, ah + (size_t)row * 256 + u * 8);
        }
        #pragma unroll
        for (int it = 0; it < 8; it++) {
            int idx = tid + it * 256;
            int row = idx >> 3, u = idx & 7;
            cp16(st + 9216u + row * 144 + u * 16, wh + (size_t)row * 256 + u * 8);
        }
        asm volatile("cp.async.commit_group;" ::: "memory");
    };

    const int a_row = lane & 15, a_kh = (lane >> 4) << 3;
    const int b_n = (lane & 7) + ((lane >> 4) << 3);
    const int b_kh = ((lane >> 3) & 1) << 3;
    const uint32_t aOff = ((m0 + a_row) * 72 + a_kh) * 2;
    const uint32_t bOff = 9216u + ((n0 + b_n) * 72 + b_kh) * 2;

    float4 acc[2][8];
    #pragma unroll
    for (int i = 0; i < 2; i++)
        #pragma unroll
        for (int j = 0; j < 8; j++) acc[i][j] = make_float4(0.f, 0.f, 0.f, 0.f);

    load_chunk(0);
    #pragma unroll 1
    for (int kc = 0; kc < 4; kc++) {
        if (kc < 3) {
            load_chunk(kc + 1);
            asm volatile("cp.async.wait_group 1;" ::: "memory");
        } else {
            asm volatile("cp.async.wait_group 0;" ::: "memory");
        }
        __syncthreads();
        uint32_t st = sb + (uint32_t)(kc & 1) * OLS_STAGE;
        uint32_t aB = st + aOff, bB = st + bOff;
        #pragma unroll
        for (int ks = 0; ks < 4; ks++) {
            uint32_t ah[2][4];
            ldsm4(ah[0], aB + ks * 32);
            ldsm4(ah[1], aB + 2304 + ks * 32);
            #pragma unroll
            for (int nb = 0; nb < 4; nb++) {
                uint32_t bh[4];
                ldsm4(bh, bB + nb * 2304 + ks * 32);
                #pragma unroll
                for (int mt = 0; mt < 2; mt++)
                    #pragma unroll
                    for (int sub = 0; sub < 2; sub++)
                        mma_f16(acc[mt][nb * 2 + sub], ah[mt],
                                bh[sub*2], bh[sub*2+1]);
            }
        }
        __syncthreads();
    }

    float sums[2][2] = {{0.f,0.f},{0.f,0.f}}, sqs[2][2] = {{0.f,0.f},{0.f,0.f}};
    #pragma unroll
    for (int mt = 0; mt < 2; mt++) {
        int rl = r0 + m0 + mt * 16 + (lane >> 2);
        #pragma unroll
        for (int nt = 0; nt < 8; nt++) {
            int c = n0 + nt * 8 + (lane & 3) * 2;
            float2 bo2 = *(const float2*)(bop + c);
            float2 xl = ld2f(xres + (size_t)rl * 256 + c);
            float2 xh = ld2f(xres + (size_t)(rl + 8) * 256 + c);
            float4& a = acc[mt][nt];
            a.x += bo2.x + xl.x; a.y += bo2.y + xl.y;
            a.z += bo2.x + xh.x; a.w += bo2.y + xh.y;
            sums[mt][0] += a.x + a.y; sqs[mt][0] += a.x*a.x + a.y*a.y;
            sums[mt][1] += a.z + a.w; sqs[mt][1] += a.z*a.z + a.w*a.w;
        }
    }
    #pragma unroll
    for (int mt = 0; mt < 2; mt++)
        #pragma unroll
        for (int hf = 0; hf < 2; hf++) {
            sums[mt][hf] += __shfl_xor_sync(0xffffffffu, sums[mt][hf], 1);
            sums[mt][hf] += __shfl_xor_sync(0xffffffffu, sums[mt][hf], 2);
            sqs[mt][hf]  += __shfl_xor_sync(0xffffffffu, sqs[mt][hf], 1);
            sqs[mt][hf]  += __shfl_xor_sync(0xffffffffu, sqs[mt][hf], 2);
        }
    float* ssum = (float*)(sm + OLS_SUM);
    float* ssq  = (float*)(sm + OLS_SQ);
    if ((lane & 3) == 0) {
        #pragma unroll
        for (int mt = 0; mt < 2; mt++)
            #pragma unroll
            for (int hf = 0; hf < 2; hf++) {
                int row = m0 + mt * 16 + hf * 8 + (lane >> 2);
                ssum[(wid & 3) * 64 + row] = sums[mt][hf];
                ssq [(wid & 3) * 64 + row] = sqs[mt][hf];
            }
    }
    __syncthreads();
    float mu[2][2], rs[2][2];
    #pragma unroll
    for (int mt = 0; mt < 2; mt++)
        #pragma unroll
        for (int hf = 0; hf < 2; hf++) {
            int row = m0 + mt * 16 + hf * 8 + (lane >> 2);
            float s = ssum[row] + ssum[64 + row] + ssum[128 + row] + ssum[192 + row];
            float q = ssq[row] + ssq[64 + row] + ssq[128 + row] + ssq[192 + row];
            float m = s * (1.f / 256.f);
            mu[mt][hf] = m;
            rs[mt][hf] = rsqrtf(q * (1.f / 256.f) - m * m + 1e-5f);
        }
    #pragma unroll
    for (int mt = 0; mt < 2; mt++) {
        int rl = r0 + m0 + mt * 16 + (lane >> 2);
        #pragma unroll
        for (int nt = 0; nt < 8; nt++) {
            int c = n0 + nt * 8 + (lane & 3) * 2;
            float2 g2 = *(const float2*)(gp + c);
            float2 b2 = *(const float2*)(bbp + c);
            float4 a = acc[mt][nt];
            float2 o1, o2;
            o1.x = (a.x - mu[mt][0]) * rs[mt][0] * g2.x + b2.x;
            o1.y = (a.y - mu[mt][0]) * rs[mt][0] * g2.y + b2.y;
            o2.x = (a.z - mu[mt][1]) * rs[mt][1] * g2.x + b2.x;
            o2.y = (a.w - mu[mt][1]) * rs[mt][1] * g2.y + b2.y;
            st2f(out + (size_t)rl * 256 + c, o1);
            st2f(out + (size_t)(rl + 8) * 256 + c, o2);
        }
    }
}

// ================= attention common (fp16 input, fp32 smem/math) =================
#define ATT_STRIDE 288
#define ATT1_SMEM (WIN * ATT_STRIDE * 4)       // 50688 (QK==V)
#define ATT2_SMEM (2 * WIN * ATT_STRIDE * 4)   // 101376

__device__ __forceinline__ float4 h4_to_f4(uint2 raw) {
    __half2 h0 = *reinterpret_cast<__half2*>(&raw.x);
    __half2 h1 = *reinterpret_cast<__half2*>(&raw.y);
    return make_float4(__low2float(h0), __high2float(h0),
                       __low2float(h1), __high2float(h1));
}

__device__ __forceinline__ void attn_core(
    const float* sQK, const float* sV, int tid, int b, int s0,
    __half* __restrict__ ath, float* __restrict__ scores)
{
    const int sl = tid >> 3, h = tid & 7;
    const int dil = (h < 4) ? 3 : 1;
    const float scale = 0.1767766952966369f;  // 32^-0.5
    const int colb = h * 36;

    float4 q[8];
    {
        const float* qr = sQK + (sl + 6) * ATT_STRIDE + colb;
        #pragma unroll
        for (int j = 0; j < 8; j++) q[j] = *(const float4*)(qr + j * 4);
    }

    float sc[5];
    #pragma unroll
    for (int k = 0; k < 5; k++) {
        const float* kr = sQK + (sl + 6 + (k - 2) * dil) * ATT_STRIDE + colb;
        float d = 0.f;
        #pragma unroll
        for (int j = 0; j < 8; j++) {
            float4 kv = *(const float4*)(kr + j * 4);
            d += q[j].x * kv.x + q[j].y * kv.y + q[j].z * kv.z + q[j].w * kv.w;
        }
        sc[k] = d * scale;
    }
    float mx = sc[0];
    #pragma unroll
    for (int k = 1; k < 5; k++) mx = fmaxf(mx, sc[k]);
    float ex[5], sum = 0.f;
    #pragma unroll
    for (int k = 0; k < 5; k++) { ex[k] = __expf(sc[k] - mx); sum += ex[k]; }
    float inv = 1.f / sum;
    #pragma unroll
    for (int k = 0; k < 5; k++) ex[k] *= inv;

    size_t base = ((size_t)b * Ssz + s0 + sl) * 256 + h * 32;
    const float* v0 = sV + (sl + 6 - 2 * dil) * ATT_STRIDE + colb;
    const int vstep = dil * ATT_STRIDE;
    uint32_t Hw[16];
    #pragma unroll
    for (int j = 0; j < 8; j++) {
        float4 o = make_float4(0.f, 0.f, 0.f, 0.f);
        #pragma unroll
        for (int k = 0; k < 5; k++) {
            float4 vv = *(const float4*)(v0 + k * vstep + j * 4);
            o.x += ex[k] * vv.x; o.y += ex[k] * vv.y;
            o.z += ex[k] * vv.z; o.w += ex[k] * vv.w;
        }
        __half2 h0 = __floats2half2_rn(o.x, o.y);
        __half2 h1 = __floats2half2_rn(o.z, o.w);
        Hw[2*j]   = *reinterpret_cast<uint32_t*>(&h0);
        Hw[2*j+1] = *reinterpret_cast<uint32_t*>(&h1);
    }
    #pragma unroll
    for (int u = 0; u < 4; u++) {
        uint4 vh = make_uint4(Hw[u*4], Hw[u*4+1], Hw[u*4+2], Hw[u*4+3]);
        *(uint4*)((char*)(ath + base) + u * 16) = vh;
    }

    if (scores != nullptr) {
        float* sp = scores + (((size_t)b * 8 + h) * Ssz + s0 + sl) * 5;
        #pragma unroll
        for (int k = 0; k < 5; k++) sp[k] = ex[k];
    }
}

// attention, QK == V (blocks 1 & 2 batched via blockIdx.z)
__global__ __launch_bounds__(256) void attn_same(
    const __half* __restrict__ qk0, const __half* __restrict__ qk1,
    __half* __restrict__ ath0, __half* __restrict__ ath1,
    float* __restrict__ qs)
{
    extern __shared__ float smf[];
    const int chain = blockIdx.z;
    const __half* QK = chain ? qk1 : qk0;
    const int b  = blockIdx.y;
    const int s0 = blockIdx.x * 32;
    const int tid = threadIdx.x;

    for (int idx = tid; idx < WIN * 64; idx += 256) {
        int w = idx >> 6, c4 = idx & 63;
        int s = s0 + w - 6;
        float4 vq = make_float4(0.f, 0.f, 0.f, 0.f);
        if (s >= 0 && s < Ssz)
            vq = h4_to_f4(((const uint2*)QK)[((size_t)b * Ssz + s) * 64 + c4]);
        *(float4*)(smf + w * ATT_STRIDE + (c4 >> 3) * 36 + (c4 & 7) * 4) = vq;
    }
    __syncthreads();

    attn_core(smf, smf, tid, b, s0, chain ? ath1 : ath0, chain ? qs : nullptr);
}

// attention, QK != V (block 3)
__global__ __launch_bounds__(256) void attn_two(
    const __half* __restrict__ QK, const __half* __restrict__ V,
    __half* __restrict__ ath)
{
    extern __shared__ float smf[];
    float* sQK = smf;
    float* sV  = smf + WIN * ATT_STRIDE;
    const int b  = blockIdx.y;
    const int s0 = blockIdx.x * 32;
    const int tid = threadIdx.x;

    for (int idx = tid; idx < WIN * 64; idx += 256) {
        int w = idx >> 6, c4 = idx & 63;
        int s = s0 + w - 6;
        float4 vq = make_float4(0.f, 0.f, 0.f, 0.f);
        float4 vv = vq;
        if (s >= 0 && s < Ssz) {
            size_t off = ((size_t)b * Ssz + s) * 64 + c4;
            vq = h4_to_f4(((const uint2*)QK)[off]);
            vv = h4_to_f4(((const uint2*)V)[off]);
        }
        int sc = w * ATT_STRIDE + (c4 >> 3) * 36 + (c4 & 7) * 4;
        *(float4*)(sQK + sc) = vq;
        *(float4*)(sV + sc)  = vv;
    }
    __syncthreads();

    attn_core(sQK, sV, tid, b, s0, ath, nullptr);
}

// ================= launch =================
extern "C" void kernel_launch(void* const* d_in, const int* in_sizes, int n_in,
                              void* d_out, int out_size)
{
    (void)in_sizes; (void)n_in; (void)out_size;
    const float* q_emb = (const float*)d_in[0];
    const float* s_emb = (const float*)d_in[1];
    const float* W_lin = (const float*)d_in[3];  // (3,2,128,128)
    const float* b_lin = (const float*)d_in[4];  // (3,2,128)
    const float* W_out = (const float*)d_in[5];  // (3,256,256)
    const float* b_out = (const float*)d_in[6];  // (3,256)
    const float* ln_g  = (const float*)d_in[7];  // (3,256)
    const float* ln_b  = (const float*)d_in[8];  // (3,256)

    float* outp = (float*)d_out;
    float* z  = outp;
    float* qs = outp + (size_t)BS * 256;

    __half *p_qk0, *p_qk1, *p_v, *p_hq, *p_hs, *p_ath0, *p_ath1, *p_wlh, *p_woh;
    cudaGetSymbolAddress((void**)&p_qk0, g_qk0);
    cudaGetSymbolAddress((void**)&p_qk1, g_qk1);
    cudaGetSymbolAddress((void**)&p_v,   g_v);
    cudaGetSymbolAddress((void**)&p_hq,  g_hq);
    cudaGetSymbolAddress((void**)&p_hs,  g_hs);
    cudaGetSymbolAddress((void**)&p_ath0, g_ath0);
    cudaGetSymbolAddress((void**)&p_ath1, g_ath1);
    cudaGetSymbolAddress((void**)&p_wlh, g_wlh);
    cudaGetSymbolAddress((void**)&p_woh, g_woh);

    const int smemP  = (int)PR_SMEM;    // 34304
    const int smemO  = (int)OLS_SMEM;   // 94208
    const int smemA1 = ATT1_SMEM;
    const int smemA2 = ATT2_SMEM;
    cudaFuncSetAttribute(proj_mma<float>,  cudaFuncAttributeMaxDynamicSharedMemorySize, smemP);
    cudaFuncSetAttribute(proj_mma<__half>, cudaFuncAttributeMaxDynamicSharedMemorySize, smemP);
    cudaFuncSetAttribute((const void*)outln_mma<float, __half>,
                         cudaFuncAttributeMaxDynamicSharedMemorySize, smemO);
    cudaFuncSetAttribute((const void*)outln_mma<__half, float>,
                         cudaFuncAttributeMaxDynamicSharedMemorySize, smemO);
    cudaFuncSetAttribute(attn_same, cudaFuncAttributeMaxDynamicSharedMemorySize, smemA1);
    cudaFuncSetAttribute(attn_two,  cudaFuncAttributeMaxDynamicSharedMemorySize, smemA2);

    split_w<<<768, 256>>>(W_lin, W_out, p_wlh, p_woh);

    // ---- blocks 1 & 2, batched ----
    proj_mma<float><<<dim3(BS/64, 2, 2), 256, smemP>>>(
        q_emb, s_emb, p_wlh, 32768, b_lin, 256, p_qk0, p_qk1);
    attn_same<<<dim3(Ssz/32, Bsz, 2), 256, smemA1>>>(
        p_qk0, p_qk1, p_ath0, p_ath1, qs);
    outln_mma<float, __half><<<dim3(BS/64, 2), 256, smemO>>>(
        p_ath0, p_ath1, p_woh, 65536,
        b_out, q_emb, s_emb, ln_g, ln_b, 256, p_hq, p_hs);

    // ---- block 3 ----
    proj_mma<__half><<<dim3(BS/64, 2, 2), 256, smemP>>>(
        p_hq, p_hs, p_wlh + 65536, 0, b_lin + 512, 0, p_qk0, p_v);
    attn_two<<<dim3(Ssz/32, Bsz), 256, smemA2>>>(p_qk0, p_v, p_ath0);
    outln_mma<__half, float><<<dim3(BS/64, 1), 256, smemO>>>(
        p_ath0, p_ath0, p_woh + 131072, 0,
        b_out + 512, p_hq, p_hq, ln_g + 512, ln_b + 512, 0, z, z);
}